// round 10
// baseline (speedup 1.0000x reference)
#include <cuda_runtime.h>
#include <cuda_fp16.h>
#include <cstdint>
#include <math.h>

// ---------------------------------------------------------------------------
// SwinV2 block: B=32, H=W=56, C=384, HEADS=12, WIN=7, SHIFT=3
// ---------------------------------------------------------------------------
#define Bb      32
#define Hh      56
#define Wwid    56
#define Cc      384
#define HEADS   12
#define HD      32
#define WIN     7
#define SHIFT   3
#define Nn49    49
#define NW      64
#define NWIN    (Bb*NW)       // 2048
#define TOK     (NWIN*Nn49)   // 100352
#define HIDDEN  768

// scratch (static device globals)
__device__ __half g_a      [(size_t)TOK * Cc];
__device__ __half g_qkv    [(size_t)TOK * 3 * Cc];
__device__ __half g_o      [(size_t)TOK * Cc];
__device__ float  g_x2     [(size_t)TOK * Cc];      // x + attn residual (spatial)
__device__ __half g_xm     [(size_t)TOK * Cc];
__device__ __half g_hidden [(size_t)TOK * HIDDEN];
__device__ float  g_bias   [(size_t)NW * HEADS * Nn49 * Nn49];
// fp16 weights
__device__ __half g_wqkv [3*Cc*Cc];
__device__ __half g_wproj[Cc*Cc];
__device__ __half g_wm1  [HIDDEN*Cc];
__device__ __half g_wm2  [Cc*HIDDEN];

#define SZ_QKV (3*Cc*Cc)
#define SZ_PRJ (Cc*Cc)
#define SZ_M1  (HIDDEN*Cc)
#define SZ_M2  (Cc*HIDDEN)
#define SZ_ALL (SZ_QKV+SZ_PRJ+SZ_M1+SZ_M2)

// ---------------------------------------------------------------------------
__device__ __forceinline__ uint32_t smem_u32(const void* p) {
    return (uint32_t)__cvta_generic_to_shared(p);
}
__device__ __forceinline__ void cp_async16(uint32_t dst, const void* src) {
    asm volatile("cp.async.cg.shared.global [%0], [%1], 16;" :: "r"(dst), "l"(src));
}

#define LDSM4(r0,r1,r2,r3,addr) \
    asm volatile("ldmatrix.sync.aligned.m8n8.x4.shared.b16 {%0,%1,%2,%3}, [%4];" \
        : "=r"(r0),"=r"(r1),"=r"(r2),"=r"(r3) : "r"(addr))

#define MMA16816(c, a, b) \
    asm volatile("mma.sync.aligned.m16n8k16.row.col.f32.f16.f16.f32 " \
        "{%0,%1,%2,%3},{%4,%5,%6,%7},{%8,%9},{%0,%1,%2,%3};" \
        : "+f"(c[0]),"+f"(c[1]),"+f"(c[2]),"+f"(c[3]) \
        : "r"(a[0]),"r"(a[1]),"r"(a[2]),"r"(a[3]),"r"(b[0]),"r"(b[1]))

// ---------------------------------------------------------------------------
// merged weight conversion fp32 -> fp16 (single launch)
// ---------------------------------------------------------------------------
__global__ void __launch_bounds__(256) f2h_all(
    const float* __restrict__ w_qkv, const float* __restrict__ w_prj,
    const float* __restrict__ w_m1,  const float* __restrict__ w_m2)
{
    int i = blockIdx.x * 256 + threadIdx.x;
    if (i < SZ_QKV) {
        g_wqkv[i] = __float2half(w_qkv[i]);
    } else if (i < SZ_QKV + SZ_PRJ) {
        g_wproj[i - SZ_QKV] = __float2half(w_prj[i - SZ_QKV]);
    } else if (i < SZ_QKV + SZ_PRJ + SZ_M1) {
        g_wm1[i - SZ_QKV - SZ_PRJ] = __float2half(w_m1[i - SZ_QKV - SZ_PRJ]);
    } else if (i < SZ_ALL) {
        g_wm2[i - SZ_QKV - SZ_PRJ - SZ_M1] = __float2half(w_m2[i - SZ_QKV - SZ_PRJ - SZ_M1]);
    }
}

// ---------------------------------------------------------------------------
// fused CPB-MLP + rpb + mask bias table: one block per (wm, h)
// bias[wm][h][i][j] = 16*sigmoid(cpb(di)) + mask
// ---------------------------------------------------------------------------
__device__ __forceinline__ float relcoord(int d) {
    float v = 8.0f * (float)d / 6.0f;
    return copysignf(log2f(fabsf(v) + 1.0f) * (1.0f / 3.0f), v);
}

__global__ void __launch_bounds__(256) bias_kernel(
    const float* __restrict__ mask,
    const float* __restrict__ w1, const float* __restrict__ b1,
    const float* __restrict__ w2)
{
    int wm = blockIdx.x, h = blockIdx.y;
    __shared__ float tabh[169];

    // 1) compute this head's 169-entry CPB column
    if (threadIdx.x < 169) {
        int p  = threadIdx.x;
        float r0 = relcoord(p / 13 - 6);
        float r1 = relcoord(p % 13 - 6);
        const float* w2h = w2 + h*512;
        float acc = 0.f;
        for (int j = 0; j < 512; j++) {
            float hv = fmaxf(r0 * w1[j*2] + r1 * w1[j*2+1] + b1[j], 0.f);
            acc += hv * w2h[j];
        }
        tabh[p] = acc;
    }
    __syncthreads();

    // 2) write the (49x49) bias tile
    float* dst = g_bias + ((size_t)wm*HEADS + h) * (Nn49*Nn49);
    const float* msk = mask + (size_t)wm * (Nn49*Nn49);
    for (int e = threadIdx.x; e < Nn49*Nn49; e += 256) {
        int i = e / Nn49, j = e % Nn49;
        int di = (i/WIN - j/WIN + 6)*13 + (i%WIN - j%WIN + 6);
        dst[e] = 16.f / (1.f + __expf(-tabh[di])) + msk[e];
    }
}

// ---------------------------------------------------------------------------
// LN1 + cyclic shift + window partition -> g_a (fp16)
// ---------------------------------------------------------------------------
__global__ void __launch_bounds__(128) ln1_kernel(
    const float* __restrict__ x, const float* __restrict__ g,
    const float* __restrict__ bb)
{
    int t   = blockIdx.x;
    int win = t / Nn49, n = t % Nn49;
    int b   = win >> 6, wi = win & 63;
    int wy  = wi >> 3,  wx = wi & 7;
    int py  = n / WIN,  px = n % WIN;
    int hh  = (wy*WIN + py + SHIFT) % Hh;
    int ww  = (wx*WIN + px + SHIFT) % Wwid;
    const float* row = x + (((size_t)b*Hh + hh)*Wwid + ww) * Cc;

    int tid = threadIdx.x;
    float4 v = make_float4(0.f, 0.f, 0.f, 0.f);
    if (tid < 96) v = ((const float4*)row)[tid];
    float s  = v.x + v.y + v.z + v.w;
    float s2 = v.x*v.x + v.y*v.y + v.z*v.z + v.w*v.w;
#pragma unroll
    for (int off = 16; off; off >>= 1) {
        s  += __shfl_xor_sync(0xffffffffu, s,  off);
        s2 += __shfl_xor_sync(0xffffffffu, s2, off);
    }
    __shared__ float rs[4], rs2[4];
    if ((tid & 31) == 0) { rs[tid>>5] = s; rs2[tid>>5] = s2; }
    __syncthreads();
    s  = rs[0]  + rs[1]  + rs[2]  + rs[3];
    s2 = rs2[0] + rs2[1] + rs2[2] + rs2[3];
    float mu  = s * (1.f/384.f);
    float var = s2 * (1.f/384.f) - mu*mu;
    float inv = rsqrtf(var + 1e-5f);
    if (tid < 96) {
        float4 gv = ((const float4*)g)[tid];
        float4 bv = ((const float4*)bb)[tid];
        __half2 h0 = __floats2half2_rn((v.x - mu)*inv*gv.x + bv.x,
                                       (v.y - mu)*inv*gv.y + bv.y);
        __half2 h1 = __floats2half2_rn((v.z - mu)*inv*gv.z + bv.z,
                                       (v.w - mu)*inv*gv.w + bv.w);
        __half2* dst = (__half2*)(g_a + (size_t)t * Cc + tid*4);
        dst[0] = h0; dst[1] = h1;
    }
}

// ---------------------------------------------------------------------------
// fp16 HMMA GEMM: BM=128, BN=128, BK=32, 3-stage cp.async, 1 barrier/iter,
// 8 warps (2x4), warp tile 64x32.
// EPI: 0 fp16+bias (smem-staged coalesced store)
//      1 fp16+bias+GELU (smem-staged)
//      3 fp32+bias+resid (row-direct, MLP2 -> d_out)
//      4 fp32+bias + x-residual with window->spatial scatter (proj -> g_x2)
// ---------------------------------------------------------------------------
#define STAGES    3
#define TS_STAGE  (128*40)
#define GEMM_SMEM (STAGES*2*TS_STAGE*2)          // 61440 bytes
#define STG_STRIDE 136

template<int EPI>
__global__ void __launch_bounds__(256, 2) hgemm(
    const __half* __restrict__ A, const __half* __restrict__ Wt,
    const float* __restrict__ bias, const float* __restrict__ resid,
    void* __restrict__ Cptr, int M, int Nd, int K)
{
    extern __shared__ __half dyns[];
    __half* Asm = dyns;
    __half* Bsm = dyns + STAGES*TS_STAGE;

    const int tid  = threadIdx.x;
    const int bm   = blockIdx.y * 128;
    const int bn   = blockIdx.x * 128;
    const int wid  = tid >> 5, lane = tid & 31;
    const int wm   = (wid & 1) * 64;
    const int wn   = (wid >> 1) * 32;

    float acc[4][4][4];
#pragma unroll
    for (int mi = 0; mi < 4; mi++)
#pragma unroll
        for (int ni = 0; ni < 4; ni++)
#pragma unroll
            for (int q = 0; q < 4; q++) acc[mi][ni][q] = 0.f;

    const int lr = tid >> 2;
    const int lc = (tid & 3) * 8;
    const int nk = K >> 5;

    auto load_stage = [&](int slot, int kt) {
        __half* As = Asm + slot*TS_STAGE;
        __half* Bs = Bsm + slot*TS_STAGE;
        int k0 = kt << 5;
#pragma unroll
        for (int r = 0; r < 2; r++) {
            int row = lr + 64*r;
            cp_async16(smem_u32(&As[row*40 + lc]), A  + (size_t)(bm+row)*K + k0 + lc);
            cp_async16(smem_u32(&Bs[row*40 + lc]), Wt + (size_t)(bn+row)*K + k0 + lc);
        }
    };

#pragma unroll
    for (int s = 0; s < STAGES-1; s++) {
        if (s < nk) load_stage(s, s);
        asm volatile("cp.async.commit_group;");
    }

    for (int kt = 0; kt < nk; kt++) {
        asm volatile("cp.async.wait_group %0;" :: "n"(STAGES-2));
        __syncthreads();

        int pre = kt + STAGES - 1;
        if (pre < nk) load_stage(pre % STAGES, pre);
        asm volatile("cp.async.commit_group;");

        const __half* As = Asm + (kt % STAGES)*TS_STAGE;
        const __half* Bs = Bsm + (kt % STAGES)*TS_STAGE;

#pragma unroll
        for (int kk = 0; kk < 2; kk++) {
            uint32_t a[4][4], b[4][2];
#pragma unroll
            for (int mi = 0; mi < 4; mi++) {
                int row = wm + mi*16 + (lane & 15);
                int col = kk*16 + ((lane >> 4) << 3);
                LDSM4(a[mi][0], a[mi][1], a[mi][2], a[mi][3],
                      smem_u32(&As[row*40 + col]));
            }
#pragma unroll
            for (int bi = 0; bi < 2; bi++) {
                int n   = wn + bi*16 + ((lane >> 4) << 3) + (lane & 7);
                int col = kk*16 + ((lane >> 3) & 1) * 8;
                uint32_t t0, t1, t2, t3;
                LDSM4(t0, t1, t2, t3, smem_u32(&Bs[n*40 + col]));
                b[bi*2+0][0] = t0; b[bi*2+0][1] = t1;
                b[bi*2+1][0] = t2; b[bi*2+1][1] = t3;
            }
#pragma unroll
            for (int mi = 0; mi < 4; mi++)
#pragma unroll
                for (int ni = 0; ni < 4; ni++)
                    MMA16816(acc[mi][ni], a[mi], b[ni]);
        }
    }

    const int er = lane >> 2, ec = (lane & 3) * 2;

    if (EPI == 0 || EPI == 1) {
        __syncthreads();
        __half* stg = Asm;
#pragma unroll
        for (int mi = 0; mi < 4; mi++) {
#pragma unroll
            for (int ni = 0; ni < 4; ni++) {
                int col = wn + ni*8 + ec;
                float b0 = bias[bn + col], b1 = bias[bn + col + 1];
#pragma unroll
                for (int hh = 0; hh < 2; hh++) {
                    int row = wm + mi*16 + er + hh*8;
                    float v0 = acc[mi][ni][hh*2+0] + b0;
                    float v1 = acc[mi][ni][hh*2+1] + b1;
                    if (EPI == 1) {
                        v0 = 0.5f * v0 * (1.0f + erff(v0 * 0.70710678118654752f));
                        v1 = 0.5f * v1 * (1.0f + erff(v1 * 0.70710678118654752f));
                    }
                    *(__half2*)&stg[row*STG_STRIDE + col] = __floats2half2_rn(v0, v1);
                }
            }
        }
        __syncthreads();
#pragma unroll
        for (int i = 0; i < 8; i++) {
            int idx = tid + i*256;
            int row = idx >> 4;
            int u   = idx & 15;
            uint4 v = *(const uint4*)&stg[row*STG_STRIDE + u*8];
            *(uint4*)((__half*)Cptr + (size_t)(bm + row) * Nd + bn + u*8) = v;
        }
    } else if (EPI == 4) {
        // proj: out[spatial] = acc + bias + x[spatial]  (window -> spatial scatter)
#pragma unroll
        for (int mi = 0; mi < 4; mi++) {
#pragma unroll
            for (int hh = 0; hh < 2; hh++) {
                int rp  = bm + wm + mi*16 + er + hh*8;   // window-token row
                int win = rp / Nn49, n = rp % Nn49;
                int b   = win >> 6,  wi = win & 63;
                int sh  = (wi >> 3)*WIN + n/WIN;
                int sw  = (wi & 7)*WIN + n%WIN;
                int hs  = sh + SHIFT; if (hs >= Hh)   hs -= Hh;
                int ws  = sw + SHIFT; if (ws >= Wwid) ws -= Wwid;
                size_t srow = ((size_t)b*Hh + hs)*Wwid + ws;
#pragma unroll
                for (int ni = 0; ni < 4; ni++) {
                    int col = bn + wn + ni*8 + ec;
                    const float* xr = resid + srow * Nd + col;
                    float2 f;
                    f.x = acc[mi][ni][hh*2+0] + bias[col] + xr[0];
                    f.y = acc[mi][ni][hh*2+1] + bias[col+1] + xr[1];
                    *(float2*)((float*)Cptr + srow * Nd + col) = f;
                }
            }
        }
    } else {
        // EPI 3: fp32 + bias + row-direct residual
#pragma unroll
        for (int mi = 0; mi < 4; mi++) {
#pragma unroll
            for (int ni = 0; ni < 4; ni++) {
                int col = bn + wn + ni*8 + ec;
                float b0 = bias[col], b1 = bias[col+1];
#pragma unroll
                for (int hh = 0; hh < 2; hh++) {
                    size_t row = (size_t)(bm + wm + mi*16 + er + hh*8);
                    const float* rr = resid + row * Nd + col;
                    float2 f;
                    f.x = acc[mi][ni][hh*2+0] + b0 + rr[0];
                    f.y = acc[mi][ni][hh*2+1] + b1 + rr[1];
                    *(float2*)((float*)Cptr + row * Nd + col) = f;
                }
            }
        }
    }
}

// ---------------------------------------------------------------------------
// Tensor-core window attention (R4, proven)
// ---------------------------------------------------------------------------
__global__ void __launch_bounds__(128) attn_kernel(const float* __restrict__ lscale)
{
    const int win = blockIdx.x;
    const int h   = blockIdx.y;
    const int wm  = win & 63;
    const int tid = threadIdx.x;
    const int warp = tid >> 5, lane = tid & 31;

    __shared__ __half qs[64*40];
    __shared__ __half ks[64*40];
    __shared__ __half vt[32*72];
    __shared__ __half ps[64*72];

    {
        uint4 z = make_uint4(0,0,0,0);
        uint4* q4 = (uint4*)qs; uint4* k4 = (uint4*)ks;
        for (int i = tid; i < 320; i += 128) { q4[i] = z; k4[i] = z; }
        uint4* v4 = (uint4*)vt;
        for (int i = tid; i < 288; i += 128) v4[i] = z;
        uint4* p4 = (uint4*)ps;
        for (int i = tid; i < 576; i += 128) p4[i] = z;
    }
    __syncthreads();

    const __half* base = g_qkv + (size_t)(win*Nn49) * (3*Cc) + h*HD;
    for (int idx = tid; idx < Nn49*4; idx += 128) {
        int row = idx >> 2;
        int c   = (idx & 3) * 8;
        const __half* rb = base + (size_t)row * (3*Cc) + c;
        uint4 qv = *(const uint4*)(rb);
        uint4 kv = *(const uint4*)(rb + Cc);
        uint4 vv = *(const uint4*)(rb + 2*Cc);
        *(uint4*)(qs + row*40 + c) = qv;
        *(uint4*)(ks + row*40 + c) = kv;
        __half hb[8]; *(uint4*)hb = vv;
#pragma unroll
        for (int m = 0; m < 8; m++) vt[(c+m)*72 + row] = hb[m];
    }
    __syncthreads();

    {
        float scale_h = __expf(fminf(lscale[h], 4.6051701859880914f));
        int r = -1; bool isq = false;
        if (tid < Nn49) { r = tid; isq = true; }
        else if (tid >= 64 && tid < 64 + Nn49) { r = tid - 64; }
        if (r >= 0) {
            __half* row = (isq ? qs : ks) + r*40;
            float ss = 0.f;
#pragma unroll
            for (int d = 0; d < HD; d += 2) {
                float2 f = __half22float2(*(__half2*)(row + d));
                ss += f.x*f.x + f.y*f.y;
            }
            float inv = 1.0f / fmaxf(sqrtf(ss), 1e-12f);
            if (isq) inv *= scale_h;
#pragma unroll
            for (int d = 0; d < HD; d += 2) {
                __half2* p = (__half2*)(row + d);
                float2 f = __half22float2(*p);
                *p = __floats2half2_rn(f.x*inv, f.y*inv);
            }
        }
    }
    __syncthreads();

    float s[7][4];
#pragma unroll
    for (int t = 0; t < 7; t++)
#pragma unroll
        for (int c = 0; c < 4; c++) s[t][c] = 0.f;

#pragma unroll
    for (int kk = 0; kk < 2; kk++) {
        uint32_t a[4];
        {
            int row = warp*16 + (lane & 15);
            int col = kk*16 + ((lane >> 4) << 3);
            LDSM4(a[0], a[1], a[2], a[3], smem_u32(qs + row*40 + col));
        }
        uint32_t b[8][2];
#pragma unroll
        for (int bi = 0; bi < 4; bi++) {
            int n   = bi*16 + ((lane >> 4) << 3) + (lane & 7);
            int col = kk*16 + ((lane >> 3) & 1) * 8;
            uint32_t t0, t1, t2, t3;
            LDSM4(t0, t1, t2, t3, smem_u32(ks + n*40 + col));
            b[bi*2+0][0] = t0; b[bi*2+0][1] = t1;
            b[bi*2+1][0] = t2; b[bi*2+1][1] = t3;
        }
#pragma unroll
        for (int t = 0; t < 7; t++)
            MMA16816(s[t], a, b[t]);
    }

    {
        const float* bias = g_bias + ((size_t)wm*HEADS + h) * (Nn49*Nn49);
        int r0 = lane >> 2;
        int i0 = warp*16 + r0;
        int i1 = i0 + 8;
        int jb = (lane & 3) * 2;
#pragma unroll
        for (int t = 0; t < 7; t++) {
#pragma unroll
            for (int c = 0; c < 4; c++) {
                int i = (c >= 2) ? i1 : i0;
                int j = t*8 + jb + (c & 1);
                s[t][c] = (i < Nn49 && j < Nn49) ? s[t][c] + bias[i*Nn49 + j]
                                                 : -1e30f;
            }
        }
        float mx0 = -1e30f, mx1 = -1e30f;
#pragma unroll
        for (int t = 0; t < 7; t++) {
            mx0 = fmaxf(mx0, fmaxf(s[t][0], s[t][1]));
            mx1 = fmaxf(mx1, fmaxf(s[t][2], s[t][3]));
        }
#pragma unroll
        for (int off = 1; off <= 2; off <<= 1) {
            mx0 = fmaxf(mx0, __shfl_xor_sync(0xffffffffu, mx0, off));
            mx1 = fmaxf(mx1, __shfl_xor_sync(0xffffffffu, mx1, off));
        }
        float sm0 = 0.f, sm1 = 0.f;
#pragma unroll
        for (int t = 0; t < 7; t++) {
            s[t][0] = __expf(s[t][0] - mx0); sm0 += s[t][0];
            s[t][1] = __expf(s[t][1] - mx0); sm0 += s[t][1];
            s[t][2] = __expf(s[t][2] - mx1); sm1 += s[t][2];
            s[t][3] = __expf(s[t][3] - mx1); sm1 += s[t][3];
        }
#pragma unroll
        for (int off = 1; off <= 2; off <<= 1) {
            sm0 += __shfl_xor_sync(0xffffffffu, sm0, off);
            sm1 += __shfl_xor_sync(0xffffffffu, sm1, off);
        }
        float inv0 = 1.0f / sm0, inv1 = 1.0f / sm1;
#pragma unroll
        for (int t = 0; t < 7; t++) {
            int j0 = t*8 + jb;
            *(__half2*)(ps + (i0 & 63)*72 + j0) = __floats2half2_rn(s[t][0]*inv0, s[t][1]*inv0);
            *(__half2*)(ps + (i1 & 63)*72 + j0) = __floats2half2_rn(s[t][2]*inv1, s[t][3]*inv1);
        }
    }
    __syncwarp();

    float o[4][4];
#pragma unroll
    for (int t = 0; t < 4; t++)
#pragma unroll
        for (int c = 0; c < 4; c++) o[t][c] = 0.f;

#pragma unroll
    for (int kk = 0; kk < 4; kk++) {
        uint32_t a[4];
        {
            int row = warp*16 + (lane & 15);
            int col = kk*16 + ((lane >> 4) << 3);
            LDSM4(a[0], a[1], a[2], a[3], smem_u32(ps + row*72 + col));
        }
        uint32_t b[4][2];
#pragma unroll
        for (int bi = 0; bi < 2; bi++) {
            int n   = bi*16 + ((lane >> 4) << 3) + (lane & 7);
            int col = kk*16 + ((lane >> 3) & 1) * 8;
            uint32_t t0, t1, t2, t3;
            LDSM4(t0, t1, t2, t3, smem_u32(vt + n*72 + col));
            b[bi*2+0][0] = t0; b[bi*2+0][1] = t1;
            b[bi*2+1][0] = t2; b[bi*2+1][1] = t3;
        }
#pragma unroll
        for (int t = 0; t < 4; t++)
            MMA16816(o[t], a, b[t]);
    }

    {
        int r0 = lane >> 2;
        int i0 = warp*16 + r0;
        int i1 = i0 + 8;
        int d0 = (lane & 3) * 2;
#pragma unroll
        for (int t = 0; t < 4; t++) {
            int d = t*8 + d0;
            if (i0 < Nn49)
                *(__half2*)(g_o + (size_t)(win*Nn49 + i0)*Cc + h*HD + d) =
                    __floats2half2_rn(o[t][0], o[t][1]);
            if (i1 < Nn49)
                *(__half2*)(g_o + (size_t)(win*Nn49 + i1)*Cc + h*HD + d) =
                    __floats2half2_rn(o[t][2], o[t][3]);
        }
    }
}

// ---------------------------------------------------------------------------
// LN2 on g_x2 (spatial, already contains x + attn-residual) -> g_xm (fp16)
// ---------------------------------------------------------------------------
__global__ void __launch_bounds__(128) ln2_kernel(
    const float* __restrict__ g, const float* __restrict__ bb)
{
    int s_tok = blockIdx.x;
    const float* row = g_x2 + (size_t)s_tok * Cc;

    int tid = threadIdx.x;
    float4 v = make_float4(0.f, 0.f, 0.f, 0.f);
    if (tid < 96) v = ((const float4*)row)[tid];
    float s  = v.x + v.y + v.z + v.w;
    float s2 = v.x*v.x + v.y*v.y + v.z*v.z + v.w*v.w;
#pragma unroll
    for (int off = 16; off; off >>= 1) {
        s  += __shfl_xor_sync(0xffffffffu, s,  off);
        s2 += __shfl_xor_sync(0xffffffffu, s2, off);
    }
    __shared__ float rs[4], rs2[4];
    if ((tid & 31) == 0) { rs[tid>>5] = s; rs2[tid>>5] = s2; }
    __syncthreads();
    s  = rs[0]  + rs[1]  + rs[2]  + rs[3];
    s2 = rs2[0] + rs2[1] + rs2[2] + rs2[3];
    float mu  = s * (1.f/384.f);
    float var = s2 * (1.f/384.f) - mu*mu;
    float inv = rsqrtf(var + 1e-5f);
    if (tid < 96) {
        float4 gv = ((const float4*)g)[tid];
        float4 bv = ((const float4*)bb)[tid];
        __half2 h0 = __floats2half2_rn((v.x - mu)*inv*gv.x + bv.x,
                                       (v.y - mu)*inv*gv.y + bv.y);
        __half2 h1 = __floats2half2_rn((v.z - mu)*inv*gv.z + bv.z,
                                       (v.w - mu)*inv*gv.w + bv.w);
        __half2* dst = (__half2*)(g_xm + (size_t)s_tok * Cc + tid*4);
        dst[0] = h0; dst[1] = h1;
    }
}

// ---------------------------------------------------------------------------
extern "C" void kernel_launch(void* const* d_in, const int* in_sizes, int n_in,
                              void* d_out, int out_size)
{
    const float* x       = (const float*)d_in[0];
    const float* mask    = (const float*)d_in[1];
    const float* n1g     = (const float*)d_in[2];
    const float* n1b     = (const float*)d_in[3];
    const float* qkv_w   = (const float*)d_in[4];
    const float* qkv_b   = (const float*)d_in[5];
    const float* proj_w  = (const float*)d_in[6];
    const float* proj_b  = (const float*)d_in[7];
    const float* cpb_w1  = (const float*)d_in[8];
    const float* cpb_b1  = (const float*)d_in[9];
    const float* cpb_w2  = (const float*)d_in[10];
    const float* lscale  = (const float*)d_in[11];
    const float* n2g     = (const float*)d_in[12];
    const float* n2b     = (const float*)d_in[13];
    const float* mlp_w1  = (const float*)d_in[14];
    const float* mlp_b1  = (const float*)d_in[15];
    const float* mlp_w2  = (const float*)d_in[16];
    const float* mlp_b2  = (const float*)d_in[17];
    float* out = (float*)d_out;

    __half *a=nullptr, *qkv=nullptr, *o=nullptr, *xm=nullptr, *hidden=nullptr;
    __half *wqkv=nullptr, *wproj=nullptr, *wm1=nullptr, *wm2=nullptr;
    float *x2=nullptr;
    cudaGetSymbolAddress((void**)&a,       g_a);
    cudaGetSymbolAddress((void**)&qkv,     g_qkv);
    cudaGetSymbolAddress((void**)&o,       g_o);
    cudaGetSymbolAddress((void**)&x2,      g_x2);
    cudaGetSymbolAddress((void**)&xm,      g_xm);
    cudaGetSymbolAddress((void**)&hidden,  g_hidden);
    cudaGetSymbolAddress((void**)&wqkv,    g_wqkv);
    cudaGetSymbolAddress((void**)&wproj,   g_wproj);
    cudaGetSymbolAddress((void**)&wm1,     g_wm1);
    cudaGetSymbolAddress((void**)&wm2,     g_wm2);

    cudaFuncSetAttribute(hgemm<0>, cudaFuncAttributeMaxDynamicSharedMemorySize, GEMM_SMEM);
    cudaFuncSetAttribute(hgemm<1>, cudaFuncAttributeMaxDynamicSharedMemorySize, GEMM_SMEM);
    cudaFuncSetAttribute(hgemm<3>, cudaFuncAttributeMaxDynamicSharedMemorySize, GEMM_SMEM);
    cudaFuncSetAttribute(hgemm<4>, cudaFuncAttributeMaxDynamicSharedMemorySize, GEMM_SMEM);

    // 1: merged weight conversion fp32 -> fp16
    f2h_all<<<(SZ_ALL + 255)/256, 256>>>(qkv_w, proj_w, mlp_w1, mlp_w2);
    // 2: LN1 + shift + window partition
    ln1_kernel<<<TOK, 128>>>(x, n1g, n1b);
    // 3: QKV GEMM -> fp16
    hgemm<0><<<dim3(9, TOK/128), 256, GEMM_SMEM>>>(a, wqkv, qkv_b, nullptr, qkv, TOK, 3*Cc, Cc);
    // 4: fused CPB + rpb + mask bias table
    bias_kernel<<<dim3(NW, HEADS), 256>>>(mask, cpb_w1, cpb_b1, cpb_w2);
    // 5: tensor-core window attention
    attn_kernel<<<dim3(NWIN, HEADS), 128>>>(lscale);
    // 6: proj GEMM + x residual + spatial scatter -> g_x2 (fp32)
    hgemm<4><<<dim3(3, TOK/128), 256, GEMM_SMEM>>>(o, wproj, proj_b, x, x2, TOK, Cc, Cc);
    // 7: LN2 (plain) -> g_xm (fp16)
    ln2_kernel<<<TOK, 128>>>(n2g, n2b);
    // 8: MLP1 + GELU -> fp16
    hgemm<1><<<dim3(6, TOK/128), 256, GEMM_SMEM>>>(xm, wm1, mlp_b1, nullptr, hidden, TOK, HIDDEN, Cc);
    // 9: MLP2 + x2 residual -> d_out (fp32)
    hgemm<3><<<dim3(3, TOK/128), 256, GEMM_SMEM>>>(hidden, wm2, mlp_b2, x2, out, TOK, Cc, HIDDEN);
}

// round 11
// speedup vs baseline: 1.0317x; 1.0317x over previous
#include <cuda_runtime.h>
#include <cuda_fp16.h>
#include <cstdint>
#include <math.h>

// ---------------------------------------------------------------------------
// SwinV2 block: B=32, H=W=56, C=384, HEADS=12, WIN=7, SHIFT=3
// ---------------------------------------------------------------------------
#define Bb      32
#define Hh      56
#define Wwid    56
#define Cc      384
#define HEADS   12
#define HD      32
#define WIN     7
#define SHIFT   3
#define Nn49    49
#define NW      64
#define NWIN    (Bb*NW)       // 2048
#define TOK     (NWIN*Nn49)   // 100352
#define HIDDEN  768

// scratch (static device globals)
__device__ __half g_a      [(size_t)TOK * Cc];
__device__ __half g_qkv    [(size_t)TOK * 3 * Cc];
__device__ __half g_o      [(size_t)TOK * Cc];
__device__ float  g_x2     [(size_t)TOK * Cc];      // x + attn residual (spatial)
__device__ __half g_xm     [(size_t)TOK * Cc];
__device__ __half g_hidden [(size_t)TOK * HIDDEN];
__device__ float  g_tab    [169 * HEADS];
__device__ float  g_bias   [(size_t)NW * HEADS * Nn49 * Nn49];
// fp16 weights
__device__ __half g_wqkv [3*Cc*Cc];
__device__ __half g_wproj[Cc*Cc];
__device__ __half g_wm1  [HIDDEN*Cc];
__device__ __half g_wm2  [Cc*HIDDEN];

#define SZ_QKV (3*Cc*Cc)
#define SZ_PRJ (Cc*Cc)
#define SZ_M1  (HIDDEN*Cc)
#define SZ_M2  (Cc*HIDDEN)
#define SZ_ALL (SZ_QKV+SZ_PRJ+SZ_M1+SZ_M2)

// ---------------------------------------------------------------------------
__device__ __forceinline__ uint32_t smem_u32(const void* p) {
    return (uint32_t)__cvta_generic_to_shared(p);
}
__device__ __forceinline__ void cp_async16(uint32_t dst, const void* src) {
    asm volatile("cp.async.cg.shared.global [%0], [%1], 16;" :: "r"(dst), "l"(src));
}

#define LDSM4(r0,r1,r2,r3,addr) \
    asm volatile("ldmatrix.sync.aligned.m8n8.x4.shared.b16 {%0,%1,%2,%3}, [%4];" \
        : "=r"(r0),"=r"(r1),"=r"(r2),"=r"(r3) : "r"(addr))

#define MMA16816(c, a, b) \
    asm volatile("mma.sync.aligned.m16n8k16.row.col.f32.f16.f16.f32 " \
        "{%0,%1,%2,%3},{%4,%5,%6,%7},{%8,%9},{%0,%1,%2,%3};" \
        : "+f"(c[0]),"+f"(c[1]),"+f"(c[2]),"+f"(c[3]) \
        : "r"(a[0]),"r"(a[1]),"r"(a[2]),"r"(a[3]),"r"(b[0]),"r"(b[1]))

// ---------------------------------------------------------------------------
// merged weight conversion fp32 -> fp16 (single launch)
// ---------------------------------------------------------------------------
__global__ void __launch_bounds__(256) f2h_all(
    const float* __restrict__ w_qkv, const float* __restrict__ w_prj,
    const float* __restrict__ w_m1,  const float* __restrict__ w_m2)
{
    int i = blockIdx.x * 256 + threadIdx.x;
    if (i < SZ_QKV) {
        g_wqkv[i] = __float2half(w_qkv[i]);
    } else if (i < SZ_QKV + SZ_PRJ) {
        g_wproj[i - SZ_QKV] = __float2half(w_prj[i - SZ_QKV]);
    } else if (i < SZ_QKV + SZ_PRJ + SZ_M1) {
        g_wm1[i - SZ_QKV - SZ_PRJ] = __float2half(w_m1[i - SZ_QKV - SZ_PRJ]);
    } else if (i < SZ_ALL) {
        g_wm2[i - SZ_QKV - SZ_PRJ - SZ_M1] = __float2half(w_m2[i - SZ_QKV - SZ_PRJ - SZ_M1]);
    }
}

// ---------------------------------------------------------------------------
// CPB table (parallel-over-512 reduction; one block per rel-coord p)
// ---------------------------------------------------------------------------
__device__ __forceinline__ float relcoord(int d) {
    float v = 8.0f * (float)d / 6.0f;
    return copysignf(log2f(fabsf(v) + 1.0f) * (1.0f / 3.0f), v);
}

__global__ void __launch_bounds__(256) cpb_kernel(
    const float* __restrict__ w1, const float* __restrict__ b1,
    const float* __restrict__ w2)
{
    int p  = blockIdx.x;
    float r0 = relcoord(p / 13 - 6);
    float r1 = relcoord(p % 13 - 6);
    float acc[HEADS];
#pragma unroll
    for (int h = 0; h < HEADS; h++) acc[h] = 0.f;
    for (int j = threadIdx.x; j < 512; j += 256) {
        float hv = fmaxf(r0 * w1[j*2] + r1 * w1[j*2+1] + b1[j], 0.f);
#pragma unroll
        for (int h = 0; h < HEADS; h++) acc[h] += hv * w2[h*512 + j];
    }
    __shared__ float red[256];
    for (int h = 0; h < HEADS; h++) {
        red[threadIdx.x] = acc[h];
        __syncthreads();
        for (int s = 128; s > 0; s >>= 1) {
            if (threadIdx.x < s) red[threadIdx.x] += red[threadIdx.x + s];
            __syncthreads();
        }
        if (threadIdx.x == 0) g_tab[p*HEADS + h] = red[0];
        __syncthreads();
    }
}

// ---------------------------------------------------------------------------
// bias table: bias[wm][h][i][j] = 16*sigmoid(tab) + mask
// ---------------------------------------------------------------------------
__global__ void __launch_bounds__(256) bias_kernel(const float* __restrict__ mask)
{
    int wm = blockIdx.x, h = blockIdx.y;
    float* dst = g_bias + ((size_t)wm*HEADS + h) * (Nn49*Nn49);
    const float* msk = mask + (size_t)wm * (Nn49*Nn49);
    for (int e = threadIdx.x; e < Nn49*Nn49; e += 256) {
        int i = e / Nn49, j = e % Nn49;
        int di = (i/WIN - j/WIN + 6)*13 + (i%WIN - j%WIN + 6);
        float t = g_tab[di*HEADS + h];
        dst[e] = 16.f / (1.f + __expf(-t)) + msk[e];
    }
}

// ---------------------------------------------------------------------------
// LN1 + cyclic shift + window partition -> g_a (fp16)
// ---------------------------------------------------------------------------
__global__ void __launch_bounds__(128) ln1_kernel(
    const float* __restrict__ x, const float* __restrict__ g,
    const float* __restrict__ bb)
{
    int t   = blockIdx.x;
    int win = t / Nn49, n = t % Nn49;
    int b   = win >> 6, wi = win & 63;
    int wy  = wi >> 3,  wx = wi & 7;
    int py  = n / WIN,  px = n % WIN;
    int hh  = (wy*WIN + py + SHIFT) % Hh;
    int ww  = (wx*WIN + px + SHIFT) % Wwid;
    const float* row = x + (((size_t)b*Hh + hh)*Wwid + ww) * Cc;

    int tid = threadIdx.x;
    float4 v = make_float4(0.f, 0.f, 0.f, 0.f);
    if (tid < 96) v = ((const float4*)row)[tid];
    float s  = v.x + v.y + v.z + v.w;
    float s2 = v.x*v.x + v.y*v.y + v.z*v.z + v.w*v.w;
#pragma unroll
    for (int off = 16; off; off >>= 1) {
        s  += __shfl_xor_sync(0xffffffffu, s,  off);
        s2 += __shfl_xor_sync(0xffffffffu, s2, off);
    }
    __shared__ float rs[4], rs2[4];
    if ((tid & 31) == 0) { rs[tid>>5] = s; rs2[tid>>5] = s2; }
    __syncthreads();
    s  = rs[0]  + rs[1]  + rs[2]  + rs[3];
    s2 = rs2[0] + rs2[1] + rs2[2] + rs2[3];
    float mu  = s * (1.f/384.f);
    float var = s2 * (1.f/384.f) - mu*mu;
    float inv = rsqrtf(var + 1e-5f);
    if (tid < 96) {
        float4 gv = ((const float4*)g)[tid];
        float4 bv = ((const float4*)bb)[tid];
        __half2 h0 = __floats2half2_rn((v.x - mu)*inv*gv.x + bv.x,
                                       (v.y - mu)*inv*gv.y + bv.y);
        __half2 h1 = __floats2half2_rn((v.z - mu)*inv*gv.z + bv.z,
                                       (v.w - mu)*inv*gv.w + bv.w);
        __half2* dst = (__half2*)(g_a + (size_t)t * Cc + tid*4);
        dst[0] = h0; dst[1] = h1;
    }
}

// ---------------------------------------------------------------------------
// fp16 HMMA GEMM: BM=128, BN=128, BK=32, 3-stage cp.async, 1 barrier/iter,
// 8 warps (2x4), warp tile 64x32.
// EPI: 0 fp16+bias (smem-staged coalesced store)
//      1 fp16+bias+GELU (smem-staged)
//      3 fp32+bias+resid (row-direct, MLP2 -> d_out)
//      4 fp32+bias + x-residual with window->spatial scatter (proj -> g_x2)
// ---------------------------------------------------------------------------
#define STAGES    3
#define TS_STAGE  (128*40)
#define GEMM_SMEM (STAGES*2*TS_STAGE*2)          // 61440 bytes
#define STG_STRIDE 136

template<int EPI>
__global__ void __launch_bounds__(256, 2) hgemm(
    const __half* __restrict__ A, const __half* __restrict__ Wt,
    const float* __restrict__ bias, const float* __restrict__ resid,
    void* __restrict__ Cptr, int M, int Nd, int K)
{
    extern __shared__ __half dyns[];
    __half* Asm = dyns;
    __half* Bsm = dyns + STAGES*TS_STAGE;

    const int tid  = threadIdx.x;
    const int bm   = blockIdx.y * 128;
    const int bn   = blockIdx.x * 128;
    const int wid  = tid >> 5, lane = tid & 31;
    const int wm   = (wid & 1) * 64;
    const int wn   = (wid >> 1) * 32;

    float acc[4][4][4];
#pragma unroll
    for (int mi = 0; mi < 4; mi++)
#pragma unroll
        for (int ni = 0; ni < 4; ni++)
#pragma unroll
            for (int q = 0; q < 4; q++) acc[mi][ni][q] = 0.f;

    const int lr = tid >> 2;
    const int lc = (tid & 3) * 8;
    const int nk = K >> 5;

    auto load_stage = [&](int slot, int kt) {
        __half* As = Asm + slot*TS_STAGE;
        __half* Bs = Bsm + slot*TS_STAGE;
        int k0 = kt << 5;
#pragma unroll
        for (int r = 0; r < 2; r++) {
            int row = lr + 64*r;
            cp_async16(smem_u32(&As[row*40 + lc]), A  + (size_t)(bm+row)*K + k0 + lc);
            cp_async16(smem_u32(&Bs[row*40 + lc]), Wt + (size_t)(bn+row)*K + k0 + lc);
        }
    };

#pragma unroll
    for (int s = 0; s < STAGES-1; s++) {
        if (s < nk) load_stage(s, s);
        asm volatile("cp.async.commit_group;");
    }

    for (int kt = 0; kt < nk; kt++) {
        asm volatile("cp.async.wait_group %0;" :: "n"(STAGES-2));
        __syncthreads();

        int pre = kt + STAGES - 1;
        if (pre < nk) load_stage(pre % STAGES, pre);
        asm volatile("cp.async.commit_group;");

        const __half* As = Asm + (kt % STAGES)*TS_STAGE;
        const __half* Bs = Bsm + (kt % STAGES)*TS_STAGE;

#pragma unroll
        for (int kk = 0; kk < 2; kk++) {
            uint32_t a[4][4], b[4][2];
#pragma unroll
            for (int mi = 0; mi < 4; mi++) {
                int row = wm + mi*16 + (lane & 15);
                int col = kk*16 + ((lane >> 4) << 3);
                LDSM4(a[mi][0], a[mi][1], a[mi][2], a[mi][3],
                      smem_u32(&As[row*40 + col]));
            }
#pragma unroll
            for (int bi = 0; bi < 2; bi++) {
                int n   = wn + bi*16 + ((lane >> 4) << 3) + (lane & 7);
                int col = kk*16 + ((lane >> 3) & 1) * 8;
                uint32_t t0, t1, t2, t3;
                LDSM4(t0, t1, t2, t3, smem_u32(&Bs[n*40 + col]));
                b[bi*2+0][0] = t0; b[bi*2+0][1] = t1;
                b[bi*2+1][0] = t2; b[bi*2+1][1] = t3;
            }
#pragma unroll
            for (int mi = 0; mi < 4; mi++)
#pragma unroll
                for (int ni = 0; ni < 4; ni++)
                    MMA16816(acc[mi][ni], a[mi], b[ni]);
        }
    }

    const int er = lane >> 2, ec = (lane & 3) * 2;

    if (EPI == 0 || EPI == 1) {
        __syncthreads();
        __half* stg = Asm;
#pragma unroll
        for (int mi = 0; mi < 4; mi++) {
#pragma unroll
            for (int ni = 0; ni < 4; ni++) {
                int col = wn + ni*8 + ec;
                float b0 = bias[bn + col], b1 = bias[bn + col + 1];
#pragma unroll
                for (int hh = 0; hh < 2; hh++) {
                    int row = wm + mi*16 + er + hh*8;
                    float v0 = acc[mi][ni][hh*2+0] + b0;
                    float v1 = acc[mi][ni][hh*2+1] + b1;
                    if (EPI == 1) {
                        v0 = 0.5f * v0 * (1.0f + erff(v0 * 0.70710678118654752f));
                        v1 = 0.5f * v1 * (1.0f + erff(v1 * 0.70710678118654752f));
                    }
                    *(__half2*)&stg[row*STG_STRIDE + col] = __floats2half2_rn(v0, v1);
                }
            }
        }
        __syncthreads();
#pragma unroll
        for (int i = 0; i < 8; i++) {
            int idx = tid + i*256;
            int row = idx >> 4;
            int u   = idx & 15;
            uint4 v = *(const uint4*)&stg[row*STG_STRIDE + u*8];
            *(uint4*)((__half*)Cptr + (size_t)(bm + row) * Nd + bn + u*8) = v;
        }
    } else if (EPI == 4) {
        // proj: out[spatial] = acc + bias + x[spatial]  (window -> spatial scatter)
#pragma unroll
        for (int mi = 0; mi < 4; mi++) {
#pragma unroll
            for (int hh = 0; hh < 2; hh++) {
                int rp  = bm + wm + mi*16 + er + hh*8;   // window-token row
                int win = rp / Nn49, n = rp % Nn49;
                int b   = win >> 6,  wi = win & 63;
                int sh  = (wi >> 3)*WIN + n/WIN;
                int sw  = (wi & 7)*WIN + n%WIN;
                int hs  = sh + SHIFT; if (hs >= Hh)   hs -= Hh;
                int ws  = sw + SHIFT; if (ws >= Wwid) ws -= Wwid;
                size_t srow = ((size_t)b*Hh + hs)*Wwid + ws;
#pragma unroll
                for (int ni = 0; ni < 4; ni++) {
                    int col = bn + wn + ni*8 + ec;
                    const float* xr = resid + srow * Nd + col;
                    float2 f;
                    f.x = acc[mi][ni][hh*2+0] + bias[col] + xr[0];
                    f.y = acc[mi][ni][hh*2+1] + bias[col+1] + xr[1];
                    *(float2*)((float*)Cptr + srow * Nd + col) = f;
                }
            }
        }
    } else {
        // EPI 3: fp32 + bias + row-direct residual
#pragma unroll
        for (int mi = 0; mi < 4; mi++) {
#pragma unroll
            for (int ni = 0; ni < 4; ni++) {
                int col = bn + wn + ni*8 + ec;
                float b0 = bias[col], b1 = bias[col+1];
#pragma unroll
                for (int hh = 0; hh < 2; hh++) {
                    size_t row = (size_t)(bm + wm + mi*16 + er + hh*8);
                    const float* rr = resid + row * Nd + col;
                    float2 f;
                    f.x = acc[mi][ni][hh*2+0] + b0 + rr[0];
                    f.y = acc[mi][ni][hh*2+1] + b1 + rr[1];
                    *(float2*)((float*)Cptr + row * Nd + col) = f;
                }
            }
        }
    }
}

// ---------------------------------------------------------------------------
// Tensor-core window attention (R4, proven)
// ---------------------------------------------------------------------------
__global__ void __launch_bounds__(128) attn_kernel(const float* __restrict__ lscale)
{
    const int win = blockIdx.x;
    const int h   = blockIdx.y;
    const int wm  = win & 63;
    const int tid = threadIdx.x;
    const int warp = tid >> 5, lane = tid & 31;

    __shared__ __half qs[64*40];
    __shared__ __half ks[64*40];
    __shared__ __half vt[32*72];
    __shared__ __half ps[64*72];

    {
        uint4 z = make_uint4(0,0,0,0);
        uint4* q4 = (uint4*)qs; uint4* k4 = (uint4*)ks;
        for (int i = tid; i < 320; i += 128) { q4[i] = z; k4[i] = z; }
        uint4* v4 = (uint4*)vt;
        for (int i = tid; i < 288; i += 128) v4[i] = z;
        uint4* p4 = (uint4*)ps;
        for (int i = tid; i < 576; i += 128) p4[i] = z;
    }
    __syncthreads();

    const __half* base = g_qkv + (size_t)(win*Nn49) * (3*Cc) + h*HD;
    for (int idx = tid; idx < Nn49*4; idx += 128) {
        int row = idx >> 2;
        int c   = (idx & 3) * 8;
        const __half* rb = base + (size_t)row * (3*Cc) + c;
        uint4 qv = *(const uint4*)(rb);
        uint4 kv = *(const uint4*)(rb + Cc);
        uint4 vv = *(const uint4*)(rb + 2*Cc);
        *(uint4*)(qs + row*40 + c) = qv;
        *(uint4*)(ks + row*40 + c) = kv;
        __half hb[8]; *(uint4*)hb = vv;
#pragma unroll
        for (int m = 0; m < 8; m++) vt[(c+m)*72 + row] = hb[m];
    }
    __syncthreads();

    {
        float scale_h = __expf(fminf(lscale[h], 4.6051701859880914f));
        int r = -1; bool isq = false;
        if (tid < Nn49) { r = tid; isq = true; }
        else if (tid >= 64 && tid < 64 + Nn49) { r = tid - 64; }
        if (r >= 0) {
            __half* row = (isq ? qs : ks) + r*40;
            float ss = 0.f;
#pragma unroll
            for (int d = 0; d < HD; d += 2) {
                float2 f = __half22float2(*(__half2*)(row + d));
                ss += f.x*f.x + f.y*f.y;
            }
            float inv = 1.0f / fmaxf(sqrtf(ss), 1e-12f);
            if (isq) inv *= scale_h;
#pragma unroll
            for (int d = 0; d < HD; d += 2) {
                __half2* p = (__half2*)(row + d);
                float2 f = __half22float2(*p);
                *p = __floats2half2_rn(f.x*inv, f.y*inv);
            }
        }
    }
    __syncthreads();

    float s[7][4];
#pragma unroll
    for (int t = 0; t < 7; t++)
#pragma unroll
        for (int c = 0; c < 4; c++) s[t][c] = 0.f;

#pragma unroll
    for (int kk = 0; kk < 2; kk++) {
        uint32_t a[4];
        {
            int row = warp*16 + (lane & 15);
            int col = kk*16 + ((lane >> 4) << 3);
            LDSM4(a[0], a[1], a[2], a[3], smem_u32(qs + row*40 + col));
        }
        uint32_t b[8][2];
#pragma unroll
        for (int bi = 0; bi < 4; bi++) {
            int n   = bi*16 + ((lane >> 4) << 3) + (lane & 7);
            int col = kk*16 + ((lane >> 3) & 1) * 8;
            uint32_t t0, t1, t2, t3;
            LDSM4(t0, t1, t2, t3, smem_u32(ks + n*40 + col));
            b[bi*2+0][0] = t0; b[bi*2+0][1] = t1;
            b[bi*2+1][0] = t2; b[bi*2+1][1] = t3;
        }
#pragma unroll
        for (int t = 0; t < 7; t++)
            MMA16816(s[t], a, b[t]);
    }

    {
        const float* bias = g_bias + ((size_t)wm*HEADS + h) * (Nn49*Nn49);
        int r0 = lane >> 2;
        int i0 = warp*16 + r0;
        int i1 = i0 + 8;
        int jb = (lane & 3) * 2;
#pragma unroll
        for (int t = 0; t < 7; t++) {
#pragma unroll
            for (int c = 0; c < 4; c++) {
                int i = (c >= 2) ? i1 : i0;
                int j = t*8 + jb + (c & 1);
                s[t][c] = (i < Nn49 && j < Nn49) ? s[t][c] + bias[i*Nn49 + j]
                                                 : -1e30f;
            }
        }
        float mx0 = -1e30f, mx1 = -1e30f;
#pragma unroll
        for (int t = 0; t < 7; t++) {
            mx0 = fmaxf(mx0, fmaxf(s[t][0], s[t][1]));
            mx1 = fmaxf(mx1, fmaxf(s[t][2], s[t][3]));
        }
#pragma unroll
        for (int off = 1; off <= 2; off <<= 1) {
            mx0 = fmaxf(mx0, __shfl_xor_sync(0xffffffffu, mx0, off));
            mx1 = fmaxf(mx1, __shfl_xor_sync(0xffffffffu, mx1, off));
        }
        float sm0 = 0.f, sm1 = 0.f;
#pragma unroll
        for (int t = 0; t < 7; t++) {
            s[t][0] = __expf(s[t][0] - mx0); sm0 += s[t][0];
            s[t][1] = __expf(s[t][1] - mx0); sm0 += s[t][1];
            s[t][2] = __expf(s[t][2] - mx1); sm1 += s[t][2];
            s[t][3] = __expf(s[t][3] - mx1); sm1 += s[t][3];
        }
#pragma unroll
        for (int off = 1; off <= 2; off <<= 1) {
            sm0 += __shfl_xor_sync(0xffffffffu, sm0, off);
            sm1 += __shfl_xor_sync(0xffffffffu, sm1, off);
        }
        float inv0 = 1.0f / sm0, inv1 = 1.0f / sm1;
#pragma unroll
        for (int t = 0; t < 7; t++) {
            int j0 = t*8 + jb;
            *(__half2*)(ps + (i0 & 63)*72 + j0) = __floats2half2_rn(s[t][0]*inv0, s[t][1]*inv0);
            *(__half2*)(ps + (i1 & 63)*72 + j0) = __floats2half2_rn(s[t][2]*inv1, s[t][3]*inv1);
        }
    }
    __syncwarp();

    float o[4][4];
#pragma unroll
    for (int t = 0; t < 4; t++)
#pragma unroll
        for (int c = 0; c < 4; c++) o[t][c] = 0.f;

#pragma unroll
    for (int kk = 0; kk < 4; kk++) {
        uint32_t a[4];
        {
            int row = warp*16 + (lane & 15);
            int col = kk*16 + ((lane >> 4) << 3);
            LDSM4(a[0], a[1], a[2], a[3], smem_u32(ps + row*72 + col));
        }
        uint32_t b[4][2];
#pragma unroll
        for (int bi = 0; bi < 2; bi++) {
            int n   = bi*16 + ((lane >> 4) << 3) + (lane & 7);
            int col = kk*16 + ((lane >> 3) & 1) * 8;
            uint32_t t0, t1, t2, t3;
            LDSM4(t0, t1, t2, t3, smem_u32(vt + n*72 + col));
            b[bi*2+0][0] = t0; b[bi*2+0][1] = t1;
            b[bi*2+1][0] = t2; b[bi*2+1][1] = t3;
        }
#pragma unroll
        for (int t = 0; t < 4; t++)
            MMA16816(o[t], a, b[t]);
    }

    {
        int r0 = lane >> 2;
        int i0 = warp*16 + r0;
        int i1 = i0 + 8;
        int d0 = (lane & 3) * 2;
#pragma unroll
        for (int t = 0; t < 4; t++) {
            int d = t*8 + d0;
            if (i0 < Nn49)
                *(__half2*)(g_o + (size_t)(win*Nn49 + i0)*Cc + h*HD + d) =
                    __floats2half2_rn(o[t][0], o[t][1]);
            if (i1 < Nn49)
                *(__half2*)(g_o + (size_t)(win*Nn49 + i1)*Cc + h*HD + d) =
                    __floats2half2_rn(o[t][2], o[t][3]);
        }
    }
}

// ---------------------------------------------------------------------------
// LN2 on g_x2 (spatial, already contains x + attn-residual) -> g_xm (fp16)
// ---------------------------------------------------------------------------
__global__ void __launch_bounds__(128) ln2_kernel(
    const float* __restrict__ g, const float* __restrict__ bb)
{
    int s_tok = blockIdx.x;
    const float* row = g_x2 + (size_t)s_tok * Cc;

    int tid = threadIdx.x;
    float4 v = make_float4(0.f, 0.f, 0.f, 0.f);
    if (tid < 96) v = ((const float4*)row)[tid];
    float s  = v.x + v.y + v.z + v.w;
    float s2 = v.x*v.x + v.y*v.y + v.z*v.z + v.w*v.w;
#pragma unroll
    for (int off = 16; off; off >>= 1) {
        s  += __shfl_xor_sync(0xffffffffu, s,  off);
        s2 += __shfl_xor_sync(0xffffffffu, s2, off);
    }
    __shared__ float rs[4], rs2[4];
    if ((tid & 31) == 0) { rs[tid>>5] = s; rs2[tid>>5] = s2; }
    __syncthreads();
    s  = rs[0]  + rs[1]  + rs[2]  + rs[3];
    s2 = rs2[0] + rs2[1] + rs2[2] + rs2[3];
    float mu  = s * (1.f/384.f);
    float var = s2 * (1.f/384.f) - mu*mu;
    float inv = rsqrtf(var + 1e-5f);
    if (tid < 96) {
        float4 gv = ((const float4*)g)[tid];
        float4 bv = ((const float4*)bb)[tid];
        __half2 h0 = __floats2half2_rn((v.x - mu)*inv*gv.x + bv.x,
                                       (v.y - mu)*inv*gv.y + bv.y);
        __half2 h1 = __floats2half2_rn((v.z - mu)*inv*gv.z + bv.z,
                                       (v.w - mu)*inv*gv.w + bv.w);
        __half2* dst = (__half2*)(g_xm + (size_t)s_tok * Cc + tid*4);
        dst[0] = h0; dst[1] = h1;
    }
}

// ---------------------------------------------------------------------------
extern "C" void kernel_launch(void* const* d_in, const int* in_sizes, int n_in,
                              void* d_out, int out_size)
{
    const float* x       = (const float*)d_in[0];
    const float* mask    = (const float*)d_in[1];
    const float* n1g     = (const float*)d_in[2];
    const float* n1b     = (const float*)d_in[3];
    const float* qkv_w   = (const float*)d_in[4];
    const float* qkv_b   = (const float*)d_in[5];
    const float* proj_w  = (const float*)d_in[6];
    const float* proj_b  = (const float*)d_in[7];
    const float* cpb_w1  = (const float*)d_in[8];
    const float* cpb_b1  = (const float*)d_in[9];
    const float* cpb_w2  = (const float*)d_in[10];
    const float* lscale  = (const float*)d_in[11];
    const float* n2g     = (const float*)d_in[12];
    const float* n2b     = (const float*)d_in[13];
    const float* mlp_w1  = (const float*)d_in[14];
    const float* mlp_b1  = (const float*)d_in[15];
    const float* mlp_w2  = (const float*)d_in[16];
    const float* mlp_b2  = (const float*)d_in[17];
    float* out = (float*)d_out;

    __half *a=nullptr, *qkv=nullptr, *o=nullptr, *xm=nullptr, *hidden=nullptr;
    __half *wqkv=nullptr, *wproj=nullptr, *wm1=nullptr, *wm2=nullptr;
    float *x2=nullptr;
    cudaGetSymbolAddress((void**)&a,       g_a);
    cudaGetSymbolAddress((void**)&qkv,     g_qkv);
    cudaGetSymbolAddress((void**)&o,       g_o);
    cudaGetSymbolAddress((void**)&x2,      g_x2);
    cudaGetSymbolAddress((void**)&xm,      g_xm);
    cudaGetSymbolAddress((void**)&hidden,  g_hidden);
    cudaGetSymbolAddress((void**)&wqkv,    g_wqkv);
    cudaGetSymbolAddress((void**)&wproj,   g_wproj);
    cudaGetSymbolAddress((void**)&wm1,     g_wm1);
    cudaGetSymbolAddress((void**)&wm2,     g_wm2);

    cudaFuncSetAttribute(hgemm<0>, cudaFuncAttributeMaxDynamicSharedMemorySize, GEMM_SMEM);
    cudaFuncSetAttribute(hgemm<1>, cudaFuncAttributeMaxDynamicSharedMemorySize, GEMM_SMEM);
    cudaFuncSetAttribute(hgemm<3>, cudaFuncAttributeMaxDynamicSharedMemorySize, GEMM_SMEM);
    cudaFuncSetAttribute(hgemm<4>, cudaFuncAttributeMaxDynamicSharedMemorySize, GEMM_SMEM);

    // 1: merged weight conversion fp32 -> fp16
    f2h_all<<<(SZ_ALL + 255)/256, 256>>>(qkv_w, proj_w, mlp_w1, mlp_w2);
    // 2: LN1 + shift + window partition
    ln1_kernel<<<TOK, 128>>>(x, n1g, n1b);
    // 3: QKV GEMM -> fp16
    hgemm<0><<<dim3(9, TOK/128), 256, GEMM_SMEM>>>(a, wqkv, qkv_b, nullptr, qkv, TOK, 3*Cc, Cc);
    // 4: CPB table (parallel reduction)
    cpb_kernel<<<169, 256>>>(cpb_w1, cpb_b1, cpb_w2);
    // 5: rpb + mask bias table
    bias_kernel<<<dim3(NW, HEADS), 256>>>(mask);
    // 6: tensor-core window attention
    attn_kernel<<<dim3(NWIN, HEADS), 128>>>(lscale);
    // 7: proj GEMM + x residual + spatial scatter -> g_x2 (fp32)
    hgemm<4><<<dim3(3, TOK/128), 256, GEMM_SMEM>>>(o, wproj, proj_b, x, x2, TOK, Cc, Cc);
    // 8: LN2 (plain) -> g_xm (fp16)
    ln2_kernel<<<TOK, 128>>>(n2g, n2b);
    // 9: MLP1 + GELU -> fp16
    hgemm<1><<<dim3(6, TOK/128), 256, GEMM_SMEM>>>(xm, wm1, mlp_b1, nullptr, hidden, TOK, HIDDEN, Cc);
    // 10: MLP2 + x2 residual -> d_out (fp32)
    hgemm<3><<<dim3(3, TOK/128), 256, GEMM_SMEM>>>(hidden, wm2, mlp_b2, x2, out, TOK, Cc, HIDDEN);
}

// round 12
// speedup vs baseline: 1.0710x; 1.0381x over previous
#include <cuda_runtime.h>
#include <cuda_fp16.h>
#include <cstdint>
#include <math.h>

// ---------------------------------------------------------------------------
// SwinV2 block: B=32, H=W=56, C=384, HEADS=12, WIN=7, SHIFT=3
// ---------------------------------------------------------------------------
#define Bb      32
#define Hh      56
#define Wwid    56
#define Cc      384
#define HEADS   12
#define HD      32
#define WIN     7
#define SHIFT   3
#define Nn49    49
#define NW      64
#define NWIN    (Bb*NW)       // 2048
#define TOK     (NWIN*Nn49)   // 100352
#define HIDDEN  768

// scratch (static device globals)
__device__ __half g_a      [(size_t)TOK * Cc];
__device__ __half g_qkv    [(size_t)TOK * 3 * Cc];
__device__ __half g_o      [(size_t)TOK * Cc];
__device__ float  g_x2     [(size_t)TOK * Cc];      // x + attn residual (spatial)
__device__ __half g_xm     [(size_t)TOK * Cc];
__device__ __half g_hidden [(size_t)TOK * HIDDEN];
__device__ float  g_tab    [169 * HEADS];
__device__ float  g_bias   [(size_t)NW * HEADS * Nn49 * Nn49];
// fp16 weights
__device__ __half g_wqkv [3*Cc*Cc];
__device__ __half g_wproj[Cc*Cc];
__device__ __half g_wm1  [HIDDEN*Cc];
__device__ __half g_wm2  [Cc*HIDDEN];

#define SZ_QKV (3*Cc*Cc)
#define SZ_PRJ (Cc*Cc)
#define SZ_M1  (HIDDEN*Cc)
#define SZ_M2  (Cc*HIDDEN)
#define SZ_ALL (SZ_QKV+SZ_PRJ+SZ_M1+SZ_M2)

// ---------------------------------------------------------------------------
__device__ __forceinline__ uint32_t smem_u32(const void* p) {
    return (uint32_t)__cvta_generic_to_shared(p);
}
__device__ __forceinline__ void cp_async16(uint32_t dst, const void* src) {
    asm volatile("cp.async.cg.shared.global [%0], [%1], 16;" :: "r"(dst), "l"(src));
}

#define LDSM4(r0,r1,r2,r3,addr) \
    asm volatile("ldmatrix.sync.aligned.m8n8.x4.shared.b16 {%0,%1,%2,%3}, [%4];" \
        : "=r"(r0),"=r"(r1),"=r"(r2),"=r"(r3) : "r"(addr))

#define MMA16816(c, a, b) \
    asm volatile("mma.sync.aligned.m16n8k16.row.col.f32.f16.f16.f32 " \
        "{%0,%1,%2,%3},{%4,%5,%6,%7},{%8,%9},{%0,%1,%2,%3};" \
        : "+f"(c[0]),"+f"(c[1]),"+f"(c[2]),"+f"(c[3]) \
        : "r"(a[0]),"r"(a[1]),"r"(a[2]),"r"(a[3]),"r"(b[0]),"r"(b[1]))

// ---------------------------------------------------------------------------
// merged weight conversion fp32 -> fp16 (single launch)
// ---------------------------------------------------------------------------
__global__ void __launch_bounds__(256) f2h_all(
    const float* __restrict__ w_qkv, const float* __restrict__ w_prj,
    const float* __restrict__ w_m1,  const float* __restrict__ w_m2)
{
    int i = blockIdx.x * 256 + threadIdx.x;
    if (i < SZ_QKV) {
        g_wqkv[i] = __float2half(w_qkv[i]);
    } else if (i < SZ_QKV + SZ_PRJ) {
        g_wproj[i - SZ_QKV] = __float2half(w_prj[i - SZ_QKV]);
    } else if (i < SZ_QKV + SZ_PRJ + SZ_M1) {
        g_wm1[i - SZ_QKV - SZ_PRJ] = __float2half(w_m1[i - SZ_QKV - SZ_PRJ]);
    } else if (i < SZ_ALL) {
        g_wm2[i - SZ_QKV - SZ_PRJ - SZ_M1] = __float2half(w_m2[i - SZ_QKV - SZ_PRJ - SZ_M1]);
    }
}

// ---------------------------------------------------------------------------
// CPB table (parallel-over-512 reduction; one block per rel-coord p)
// ---------------------------------------------------------------------------
__device__ __forceinline__ float relcoord(int d) {
    float v = 8.0f * (float)d / 6.0f;
    return copysignf(log2f(fabsf(v) + 1.0f) * (1.0f / 3.0f), v);
}

__global__ void __launch_bounds__(256) cpb_kernel(
    const float* __restrict__ w1, const float* __restrict__ b1,
    const float* __restrict__ w2)
{
    int p  = blockIdx.x;
    float r0 = relcoord(p / 13 - 6);
    float r1 = relcoord(p % 13 - 6);
    float acc[HEADS];
#pragma unroll
    for (int h = 0; h < HEADS; h++) acc[h] = 0.f;
    for (int j = threadIdx.x; j < 512; j += 256) {
        float hv = fmaxf(r0 * w1[j*2] + r1 * w1[j*2+1] + b1[j], 0.f);
#pragma unroll
        for (int h = 0; h < HEADS; h++) acc[h] += hv * w2[h*512 + j];
    }
    __shared__ float red[256];
    for (int h = 0; h < HEADS; h++) {
        red[threadIdx.x] = acc[h];
        __syncthreads();
        for (int s = 128; s > 0; s >>= 1) {
            if (threadIdx.x < s) red[threadIdx.x] += red[threadIdx.x + s];
            __syncthreads();
        }
        if (threadIdx.x == 0) g_tab[p*HEADS + h] = red[0];
        __syncthreads();
    }
}

// ---------------------------------------------------------------------------
// bias table: bias[wm][h][i][j] = 16*sigmoid(tab) + mask
// ---------------------------------------------------------------------------
__global__ void __launch_bounds__(256) bias_kernel(const float* __restrict__ mask)
{
    int wm = blockIdx.x, h = blockIdx.y;
    float* dst = g_bias + ((size_t)wm*HEADS + h) * (Nn49*Nn49);
    const float* msk = mask + (size_t)wm * (Nn49*Nn49);
    for (int e = threadIdx.x; e < Nn49*Nn49; e += 256) {
        int i = e / Nn49, j = e % Nn49;
        int di = (i/WIN - j/WIN + 6)*13 + (i%WIN - j%WIN + 6);
        float t = g_tab[di*HEADS + h];
        dst[e] = 16.f / (1.f + __expf(-t)) + msk[e];
    }
}

// ---------------------------------------------------------------------------
// LN1 + cyclic shift + window partition -> g_a (fp16). WARP-PER-TOKEN.
// 256 threads = 8 warps = 8 tokens per block. Shuffle-only reduction.
// ---------------------------------------------------------------------------
__global__ void __launch_bounds__(256) ln1_kernel(
    const float* __restrict__ x, const float* __restrict__ g,
    const float* __restrict__ bb)
{
    const int warp = threadIdx.x >> 5, lane = threadIdx.x & 31;
    const int t   = blockIdx.x * 8 + warp;
    const int win = t / Nn49, n = t % Nn49;
    const int b   = win >> 6, wi = win & 63;
    const int hh  = ((wi >> 3)*WIN + n/WIN + SHIFT) % Hh;
    const int ww  = ((wi & 7)*WIN + n%WIN + SHIFT) % Wwid;
    const float4* row = (const float4*)(x + (((size_t)b*Hh + hh)*Wwid + ww) * Cc);

    float4 v[3];
#pragma unroll
    for (int i = 0; i < 3; i++) v[i] = row[lane + 32*i];

    float s = 0.f, s2 = 0.f;
#pragma unroll
    for (int i = 0; i < 3; i++) {
        s  += v[i].x + v[i].y + v[i].z + v[i].w;
        s2 += v[i].x*v[i].x + v[i].y*v[i].y + v[i].z*v[i].z + v[i].w*v[i].w;
    }
#pragma unroll
    for (int off = 16; off; off >>= 1) {
        s  += __shfl_xor_sync(0xffffffffu, s,  off);
        s2 += __shfl_xor_sync(0xffffffffu, s2, off);
    }
    float mu  = s * (1.f/384.f);
    float var = s2 * (1.f/384.f) - mu*mu;
    float inv = rsqrtf(var + 1e-5f);

    uint2* dst = (uint2*)(g_a + (size_t)t * Cc);
    const float4* gg = (const float4*)g;
    const float4* bv4 = (const float4*)bb;
#pragma unroll
    for (int i = 0; i < 3; i++) {
        float4 gv = gg[lane + 32*i];
        float4 bv = bv4[lane + 32*i];
        __half2 h0 = __floats2half2_rn((v[i].x - mu)*inv*gv.x + bv.x,
                                       (v[i].y - mu)*inv*gv.y + bv.y);
        __half2 h1 = __floats2half2_rn((v[i].z - mu)*inv*gv.z + bv.z,
                                       (v[i].w - mu)*inv*gv.w + bv.w);
        uint2 u; u.x = *(uint32_t*)&h0; u.y = *(uint32_t*)&h1;
        dst[lane + 32*i] = u;
    }
}

// ---------------------------------------------------------------------------
// fp16 HMMA GEMM: BM=128, BN=128, BK=32, 3-stage cp.async, 1 barrier/iter,
// 8 warps (2x4), warp tile 64x32.
// EPI: 0 fp16+bias (smem-staged coalesced store)
//      1 fp16+bias+GELU (smem-staged)
//      3 fp32+bias+resid (row-direct, MLP2 -> d_out)
//      4 fp32+bias + x-residual with window->spatial scatter (proj -> g_x2)
// ---------------------------------------------------------------------------
#define STAGES    3
#define TS_STAGE  (128*40)
#define GEMM_SMEM (STAGES*2*TS_STAGE*2)          // 61440 bytes
#define STG_STRIDE 136

template<int EPI>
__global__ void __launch_bounds__(256, 2) hgemm(
    const __half* __restrict__ A, const __half* __restrict__ Wt,
    const float* __restrict__ bias, const float* __restrict__ resid,
    void* __restrict__ Cptr, int M, int Nd, int K)
{
    extern __shared__ __half dyns[];
    __half* Asm = dyns;
    __half* Bsm = dyns + STAGES*TS_STAGE;

    const int tid  = threadIdx.x;
    const int bm   = blockIdx.y * 128;
    const int bn   = blockIdx.x * 128;
    const int wid  = tid >> 5, lane = tid & 31;
    const int wm   = (wid & 1) * 64;
    const int wn   = (wid >> 1) * 32;

    float acc[4][4][4];
#pragma unroll
    for (int mi = 0; mi < 4; mi++)
#pragma unroll
        for (int ni = 0; ni < 4; ni++)
#pragma unroll
            for (int q = 0; q < 4; q++) acc[mi][ni][q] = 0.f;

    const int lr = tid >> 2;
    const int lc = (tid & 3) * 8;
    const int nk = K >> 5;

    auto load_stage = [&](int slot, int kt) {
        __half* As = Asm + slot*TS_STAGE;
        __half* Bs = Bsm + slot*TS_STAGE;
        int k0 = kt << 5;
#pragma unroll
        for (int r = 0; r < 2; r++) {
            int row = lr + 64*r;
            cp_async16(smem_u32(&As[row*40 + lc]), A  + (size_t)(bm+row)*K + k0 + lc);
            cp_async16(smem_u32(&Bs[row*40 + lc]), Wt + (size_t)(bn+row)*K + k0 + lc);
        }
    };

#pragma unroll
    for (int s = 0; s < STAGES-1; s++) {
        if (s < nk) load_stage(s, s);
        asm volatile("cp.async.commit_group;");
    }

    for (int kt = 0; kt < nk; kt++) {
        asm volatile("cp.async.wait_group %0;" :: "n"(STAGES-2));
        __syncthreads();

        int pre = kt + STAGES - 1;
        if (pre < nk) load_stage(pre % STAGES, pre);
        asm volatile("cp.async.commit_group;");

        const __half* As = Asm + (kt % STAGES)*TS_STAGE;
        const __half* Bs = Bsm + (kt % STAGES)*TS_STAGE;

#pragma unroll
        for (int kk = 0; kk < 2; kk++) {
            uint32_t a[4][4], b[4][2];
#pragma unroll
            for (int mi = 0; mi < 4; mi++) {
                int row = wm + mi*16 + (lane & 15);
                int col = kk*16 + ((lane >> 4) << 3);
                LDSM4(a[mi][0], a[mi][1], a[mi][2], a[mi][3],
                      smem_u32(&As[row*40 + col]));
            }
#pragma unroll
            for (int bi = 0; bi < 2; bi++) {
                int n   = wn + bi*16 + ((lane >> 4) << 3) + (lane & 7);
                int col = kk*16 + ((lane >> 3) & 1) * 8;
                uint32_t t0, t1, t2, t3;
                LDSM4(t0, t1, t2, t3, smem_u32(&Bs[n*40 + col]));
                b[bi*2+0][0] = t0; b[bi*2+0][1] = t1;
                b[bi*2+1][0] = t2; b[bi*2+1][1] = t3;
            }
#pragma unroll
            for (int mi = 0; mi < 4; mi++)
#pragma unroll
                for (int ni = 0; ni < 4; ni++)
                    MMA16816(acc[mi][ni], a[mi], b[ni]);
        }
    }

    const int er = lane >> 2, ec = (lane & 3) * 2;

    if (EPI == 0 || EPI == 1) {
        __syncthreads();
        __half* stg = Asm;
#pragma unroll
        for (int mi = 0; mi < 4; mi++) {
#pragma unroll
            for (int ni = 0; ni < 4; ni++) {
                int col = wn + ni*8 + ec;
                float b0 = bias[bn + col], b1 = bias[bn + col + 1];
#pragma unroll
                for (int hh = 0; hh < 2; hh++) {
                    int row = wm + mi*16 + er + hh*8;
                    float v0 = acc[mi][ni][hh*2+0] + b0;
                    float v1 = acc[mi][ni][hh*2+1] + b1;
                    if (EPI == 1) {
                        v0 = 0.5f * v0 * (1.0f + erff(v0 * 0.70710678118654752f));
                        v1 = 0.5f * v1 * (1.0f + erff(v1 * 0.70710678118654752f));
                    }
                    *(__half2*)&stg[row*STG_STRIDE + col] = __floats2half2_rn(v0, v1);
                }
            }
        }
        __syncthreads();
#pragma unroll
        for (int i = 0; i < 8; i++) {
            int idx = tid + i*256;
            int row = idx >> 4;
            int u   = idx & 15;
            uint4 v = *(const uint4*)&stg[row*STG_STRIDE + u*8];
            *(uint4*)((__half*)Cptr + (size_t)(bm + row) * Nd + bn + u*8) = v;
        }
    } else if (EPI == 4) {
        // proj: out[spatial] = acc + bias + x[spatial]  (window -> spatial scatter)
#pragma unroll
        for (int mi = 0; mi < 4; mi++) {
#pragma unroll
            for (int hh = 0; hh < 2; hh++) {
                int rp  = bm + wm + mi*16 + er + hh*8;
                int win = rp / Nn49, n = rp % Nn49;
                int b   = win >> 6,  wi = win & 63;
                int sh  = (wi >> 3)*WIN + n/WIN;
                int sw  = (wi & 7)*WIN + n%WIN;
                int hs  = sh + SHIFT; if (hs >= Hh)   hs -= Hh;
                int ws  = sw + SHIFT; if (ws >= Wwid) ws -= Wwid;
                size_t srow = ((size_t)b*Hh + hs)*Wwid + ws;
#pragma unroll
                for (int ni = 0; ni < 4; ni++) {
                    int col = bn + wn + ni*8 + ec;
                    const float* xr = resid + srow * Nd + col;
                    float2 f;
                    f.x = acc[mi][ni][hh*2+0] + bias[col] + xr[0];
                    f.y = acc[mi][ni][hh*2+1] + bias[col+1] + xr[1];
                    *(float2*)((float*)Cptr + srow * Nd + col) = f;
                }
            }
        }
    } else {
        // EPI 3: fp32 + bias + row-direct residual
#pragma unroll
        for (int mi = 0; mi < 4; mi++) {
#pragma unroll
            for (int ni = 0; ni < 4; ni++) {
                int col = bn + wn + ni*8 + ec;
                float b0 = bias[col], b1 = bias[col+1];
#pragma unroll
                for (int hh = 0; hh < 2; hh++) {
                    size_t row = (size_t)(bm + wm + mi*16 + er + hh*8);
                    const float* rr = resid + row * Nd + col;
                    float2 f;
                    f.x = acc[mi][ni][hh*2+0] + b0 + rr[0];
                    f.y = acc[mi][ni][hh*2+1] + b1 + rr[1];
                    *(float2*)((float*)Cptr + row * Nd + col) = f;
                }
            }
        }
    }
}

// ---------------------------------------------------------------------------
// Tensor-core window attention. Zero-fill reduced to vt+ps only (qs/ks garbage
// rows/cols are replaced, not accumulated, in the softmax epilogue).
// ---------------------------------------------------------------------------
__global__ void __launch_bounds__(128) attn_kernel(const float* __restrict__ lscale)
{
    const int win = blockIdx.x;
    const int h   = blockIdx.y;
    const int wm  = win & 63;
    const int tid = threadIdx.x;
    const int warp = tid >> 5, lane = tid & 31;

    __shared__ __half qs[64*40];
    __shared__ __half ks[64*40];
    __shared__ __half vt[32*72];
    __shared__ __half ps[64*72];

    {
        uint4 z = make_uint4(0,0,0,0);
        uint4* v4 = (uint4*)vt;   // 288 uint4
        uint4* p4 = (uint4*)ps;   // 576 uint4
        for (int i = tid; i < 576; i += 128) {
            p4[i] = z;
            if (i < 288) v4[i] = z;
        }
    }
    __syncthreads();

    const __half* base = g_qkv + (size_t)(win*Nn49) * (3*Cc) + h*HD;
    for (int idx = tid; idx < Nn49*4; idx += 128) {
        int row = idx >> 2;
        int c   = (idx & 3) * 8;
        const __half* rb = base + (size_t)row * (3*Cc) + c;
        uint4 qv = *(const uint4*)(rb);
        uint4 kv = *(const uint4*)(rb + Cc);
        uint4 vv = *(const uint4*)(rb + 2*Cc);
        *(uint4*)(qs + row*40 + c) = qv;
        *(uint4*)(ks + row*40 + c) = kv;
        __half hb[8]; *(uint4*)hb = vv;
#pragma unroll
        for (int m = 0; m < 8; m++) vt[(c+m)*72 + row] = hb[m];
    }
    __syncthreads();

    {
        float scale_h = __expf(fminf(lscale[h], 4.6051701859880914f));
        int r = -1; bool isq = false;
        if (tid < Nn49) { r = tid; isq = true; }
        else if (tid >= 64 && tid < 64 + Nn49) { r = tid - 64; }
        if (r >= 0) {
            __half* row = (isq ? qs : ks) + r*40;
            float ss = 0.f;
#pragma unroll
            for (int d = 0; d < HD; d += 2) {
                float2 f = __half22float2(*(__half2*)(row + d));
                ss += f.x*f.x + f.y*f.y;
            }
            float inv = 1.0f / fmaxf(sqrtf(ss), 1e-12f);
            if (isq) inv *= scale_h;
#pragma unroll
            for (int d = 0; d < HD; d += 2) {
                __half2* p = (__half2*)(row + d);
                float2 f = __half22float2(*p);
                *p = __floats2half2_rn(f.x*inv, f.y*inv);
            }
        }
    }
    __syncthreads();

    float s[7][4];
#pragma unroll
    for (int t = 0; t < 7; t++)
#pragma unroll
        for (int c = 0; c < 4; c++) s[t][c] = 0.f;

#pragma unroll
    for (int kk = 0; kk < 2; kk++) {
        uint32_t a[4];
        {
            int row = warp*16 + (lane & 15);
            int col = kk*16 + ((lane >> 4) << 3);
            LDSM4(a[0], a[1], a[2], a[3], smem_u32(qs + row*40 + col));
        }
        uint32_t b[8][2];
#pragma unroll
        for (int bi = 0; bi < 4; bi++) {
            int n   = bi*16 + ((lane >> 4) << 3) + (lane & 7);
            int col = kk*16 + ((lane >> 3) & 1) * 8;
            uint32_t t0, t1, t2, t3;
            LDSM4(t0, t1, t2, t3, smem_u32(ks + n*40 + col));
            b[bi*2+0][0] = t0; b[bi*2+0][1] = t1;
            b[bi*2+1][0] = t2; b[bi*2+1][1] = t3;
        }
#pragma unroll
        for (int t = 0; t < 7; t++)
            MMA16816(s[t], a, b[t]);
    }

    {
        const float* bias = g_bias + ((size_t)wm*HEADS + h) * (Nn49*Nn49);
        int r0 = lane >> 2;
        int i0 = warp*16 + r0;
        int i1 = i0 + 8;
        int jb = (lane & 3) * 2;
#pragma unroll
        for (int t = 0; t < 7; t++) {
#pragma unroll
            for (int c = 0; c < 4; c++) {
                int i = (c >= 2) ? i1 : i0;
                int j = t*8 + jb + (c & 1);
                s[t][c] = (i < Nn49 && j < Nn49) ? s[t][c] + bias[i*Nn49 + j]
                                                 : -1e30f;
            }
        }
        float mx0 = -1e30f, mx1 = -1e30f;
#pragma unroll
        for (int t = 0; t < 7; t++) {
            mx0 = fmaxf(mx0, fmaxf(s[t][0], s[t][1]));
            mx1 = fmaxf(mx1, fmaxf(s[t][2], s[t][3]));
        }
#pragma unroll
        for (int off = 1; off <= 2; off <<= 1) {
            mx0 = fmaxf(mx0, __shfl_xor_sync(0xffffffffu, mx0, off));
            mx1 = fmaxf(mx1, __shfl_xor_sync(0xffffffffu, mx1, off));
        }
        float sm0 = 0.f, sm1 = 0.f;
#pragma unroll
        for (int t = 0; t < 7; t++) {
            s[t][0] = __expf(s[t][0] - mx0); sm0 += s[t][0];
            s[t][1] = __expf(s[t][1] - mx0); sm0 += s[t][1];
            s[t][2] = __expf(s[t][2] - mx1); sm1 += s[t][2];
            s[t][3] = __expf(s[t][3] - mx1); sm1 += s[t][3];
        }
#pragma unroll
        for (int off = 1; off <= 2; off <<= 1) {
            sm0 += __shfl_xor_sync(0xffffffffu, sm0, off);
            sm1 += __shfl_xor_sync(0xffffffffu, sm1, off);
        }
        float inv0 = 1.0f / sm0, inv1 = 1.0f / sm1;
#pragma unroll
        for (int t = 0; t < 7; t++) {
            int j0 = t*8 + jb;
            *(__half2*)(ps + (i0 & 63)*72 + j0) = __floats2half2_rn(s[t][0]*inv0, s[t][1]*inv0);
            *(__half2*)(ps + (i1 & 63)*72 + j0) = __floats2half2_rn(s[t][2]*inv1, s[t][3]*inv1);
        }
    }
    __syncwarp();

    float o[4][4];
#pragma unroll
    for (int t = 0; t < 4; t++)
#pragma unroll
        for (int c = 0; c < 4; c++) o[t][c] = 0.f;

#pragma unroll
    for (int kk = 0; kk < 4; kk++) {
        uint32_t a[4];
        {
            int row = warp*16 + (lane & 15);
            int col = kk*16 + ((lane >> 4) << 3);
            LDSM4(a[0], a[1], a[2], a[3], smem_u32(ps + row*72 + col));
        }
        uint32_t b[4][2];
#pragma unroll
        for (int bi = 0; bi < 2; bi++) {
            int n   = bi*16 + ((lane >> 4) << 3) + (lane & 7);
            int col = kk*16 + ((lane >> 3) & 1) * 8;
            uint32_t t0, t1, t2, t3;
            LDSM4(t0, t1, t2, t3, smem_u32(vt + n*72 + col));
            b[bi*2+0][0] = t0; b[bi*2+0][1] = t1;
            b[bi*2+1][0] = t2; b[bi*2+1][1] = t3;
        }
#pragma unroll
        for (int t = 0; t < 4; t++)
            MMA16816(o[t], a, b[t]);
    }

    {
        int r0 = lane >> 2;
        int i0 = warp*16 + r0;
        int i1 = i0 + 8;
        int d0 = (lane & 3) * 2;
#pragma unroll
        for (int t = 0; t < 4; t++) {
            int d = t*8 + d0;
            if (i0 < Nn49)
                *(__half2*)(g_o + (size_t)(win*Nn49 + i0)*Cc + h*HD + d) =
                    __floats2half2_rn(o[t][0], o[t][1]);
            if (i1 < Nn49)
                *(__half2*)(g_o + (size_t)(win*Nn49 + i1)*Cc + h*HD + d) =
                    __floats2half2_rn(o[t][2], o[t][3]);
        }
    }
}

// ---------------------------------------------------------------------------
// LN2 on g_x2 -> g_xm (fp16). WARP-PER-TOKEN, 8 tokens/block.
// ---------------------------------------------------------------------------
__global__ void __launch_bounds__(256) ln2_kernel(
    const float* __restrict__ g, const float* __restrict__ bb)
{
    const int warp = threadIdx.x >> 5, lane = threadIdx.x & 31;
    const int t = blockIdx.x * 8 + warp;
    const float4* row = (const float4*)(g_x2 + (size_t)t * Cc);

    float4 v[3];
#pragma unroll
    for (int i = 0; i < 3; i++) v[i] = row[lane + 32*i];

    float s = 0.f, s2 = 0.f;
#pragma unroll
    for (int i = 0; i < 3; i++) {
        s  += v[i].x + v[i].y + v[i].z + v[i].w;
        s2 += v[i].x*v[i].x + v[i].y*v[i].y + v[i].z*v[i].z + v[i].w*v[i].w;
    }
#pragma unroll
    for (int off = 16; off; off >>= 1) {
        s  += __shfl_xor_sync(0xffffffffu, s,  off);
        s2 += __shfl_xor_sync(0xffffffffu, s2, off);
    }
    float mu  = s * (1.f/384.f);
    float var = s2 * (1.f/384.f) - mu*mu;
    float inv = rsqrtf(var + 1e-5f);

    uint2* dst = (uint2*)(g_xm + (size_t)t * Cc);
    const float4* gg = (const float4*)g;
    const float4* bv4 = (const float4*)bb;
#pragma unroll
    for (int i = 0; i < 3; i++) {
        float4 gv = gg[lane + 32*i];
        float4 bv = bv4[lane + 32*i];
        __half2 h0 = __floats2half2_rn((v[i].x - mu)*inv*gv.x + bv.x,
                                       (v[i].y - mu)*inv*gv.y + bv.y);
        __half2 h1 = __floats2half2_rn((v[i].z - mu)*inv*gv.z + bv.z,
                                       (v[i].w - mu)*inv*gv.w + bv.w);
        uint2 u; u.x = *(uint32_t*)&h0; u.y = *(uint32_t*)&h1;
        dst[lane + 32*i] = u;
    }
}

// ---------------------------------------------------------------------------
extern "C" void kernel_launch(void* const* d_in, const int* in_sizes, int n_in,
                              void* d_out, int out_size)
{
    const float* x       = (const float*)d_in[0];
    const float* mask    = (const float*)d_in[1];
    const float* n1g     = (const float*)d_in[2];
    const float* n1b     = (const float*)d_in[3];
    const float* qkv_w   = (const float*)d_in[4];
    const float* qkv_b   = (const float*)d_in[5];
    const float* proj_w  = (const float*)d_in[6];
    const float* proj_b  = (const float*)d_in[7];
    const float* cpb_w1  = (const float*)d_in[8];
    const float* cpb_b1  = (const float*)d_in[9];
    const float* cpb_w2  = (const float*)d_in[10];
    const float* lscale  = (const float*)d_in[11];
    const float* n2g     = (const float*)d_in[12];
    const float* n2b     = (const float*)d_in[13];
    const float* mlp_w1  = (const float*)d_in[14];
    const float* mlp_b1  = (const float*)d_in[15];
    const float* mlp_w2  = (const float*)d_in[16];
    const float* mlp_b2  = (const float*)d_in[17];
    float* out = (float*)d_out;

    __half *a=nullptr, *qkv=nullptr, *o=nullptr, *xm=nullptr, *hidden=nullptr;
    __half *wqkv=nullptr, *wproj=nullptr, *wm1=nullptr, *wm2=nullptr;
    float *x2=nullptr;
    cudaGetSymbolAddress((void**)&a,       g_a);
    cudaGetSymbolAddress((void**)&qkv,     g_qkv);
    cudaGetSymbolAddress((void**)&o,       g_o);
    cudaGetSymbolAddress((void**)&x2,      g_x2);
    cudaGetSymbolAddress((void**)&xm,      g_xm);
    cudaGetSymbolAddress((void**)&hidden,  g_hidden);
    cudaGetSymbolAddress((void**)&wqkv,    g_wqkv);
    cudaGetSymbolAddress((void**)&wproj,   g_wproj);
    cudaGetSymbolAddress((void**)&wm1,     g_wm1);
    cudaGetSymbolAddress((void**)&wm2,     g_wm2);

    cudaFuncSetAttribute(hgemm<0>, cudaFuncAttributeMaxDynamicSharedMemorySize, GEMM_SMEM);
    cudaFuncSetAttribute(hgemm<1>, cudaFuncAttributeMaxDynamicSharedMemorySize, GEMM_SMEM);
    cudaFuncSetAttribute(hgemm<3>, cudaFuncAttributeMaxDynamicSharedMemorySize, GEMM_SMEM);
    cudaFuncSetAttribute(hgemm<4>, cudaFuncAttributeMaxDynamicSharedMemorySize, GEMM_SMEM);

    // 1: merged weight conversion fp32 -> fp16
    f2h_all<<<(SZ_ALL + 255)/256, 256>>>(qkv_w, proj_w, mlp_w1, mlp_w2);
    // 2: LN1 + shift + window partition (warp-per-token)
    ln1_kernel<<<TOK/8, 256>>>(x, n1g, n1b);
    // 3: QKV GEMM -> fp16
    hgemm<0><<<dim3(9, TOK/128), 256, GEMM_SMEM>>>(a, wqkv, qkv_b, nullptr, qkv, TOK, 3*Cc, Cc);
    // 4: CPB table (parallel reduction)
    cpb_kernel<<<169, 256>>>(cpb_w1, cpb_b1, cpb_w2);
    // 5: rpb + mask bias table
    bias_kernel<<<dim3(NW, HEADS), 256>>>(mask);
    // 6: tensor-core window attention
    attn_kernel<<<dim3(NWIN, HEADS), 128>>>(lscale);
    // 7: proj GEMM + x residual + spatial scatter -> g_x2 (fp32)
    hgemm<4><<<dim3(3, TOK/128), 256, GEMM_SMEM>>>(o, wproj, proj_b, x, x2, TOK, Cc, Cc);
    // 8: LN2 (warp-per-token) -> g_xm (fp16)
    ln2_kernel<<<TOK/8, 256>>>(n2g, n2b);
    // 9: MLP1 + GELU -> fp16
    hgemm<1><<<dim3(6, TOK/128), 256, GEMM_SMEM>>>(xm, wm1, mlp_b1, nullptr, hidden, TOK, HIDDEN, Cc);
    // 10: MLP2 + x2 residual -> d_out (fp32)
    hgemm<3><<<dim3(3, TOK/128), 256, GEMM_SMEM>>>(hidden, wm2, mlp_b2, x2, out, TOK, Cc, HIDDEN);
}

// round 13
// speedup vs baseline: 1.1110x; 1.0374x over previous
#include <cuda_runtime.h>
#include <cuda_fp16.h>
#include <cstdint>
#include <math.h>

// ---------------------------------------------------------------------------
// SwinV2 block: B=32, H=W=56, C=384, HEADS=12, WIN=7, SHIFT=3
// ---------------------------------------------------------------------------
#define Bb      32
#define Hh      56
#define Wwid    56
#define Cc      384
#define HEADS   12
#define HD      32
#define WIN     7
#define SHIFT   3
#define Nn49    49
#define NW      64
#define NWIN    (Bb*NW)       // 2048
#define TOK     (NWIN*Nn49)   // 100352
#define HIDDEN  768

// scratch (static device globals)
__device__ __half g_a      [(size_t)TOK * Cc];
__device__ __half g_qkv    [(size_t)TOK * 3 * Cc];
__device__ __half g_o      [(size_t)TOK * Cc];
__device__ float  g_x2     [(size_t)TOK * Cc];      // x + attn residual (spatial)
__device__ __half g_xm     [(size_t)TOK * Cc];
__device__ __half g_hidden [(size_t)TOK * HIDDEN];
__device__ float  g_tab    [169 * HEADS];
__device__ float  g_bias   [(size_t)NW * HEADS * Nn49 * Nn49];
// fp16 weights
__device__ __half g_wqkv [3*Cc*Cc];
__device__ __half g_wproj[Cc*Cc];
__device__ __half g_wm1  [HIDDEN*Cc];
__device__ __half g_wm2  [Cc*HIDDEN];

#define SZ_QKV (3*Cc*Cc)
#define SZ_PRJ (Cc*Cc)
#define SZ_M1  (HIDDEN*Cc)
#define SZ_M2  (Cc*HIDDEN)
#define SZ_ALL (SZ_QKV+SZ_PRJ+SZ_M1+SZ_M2)
#define F2H_BLOCKS ((SZ_ALL + 255)/256)          // 4608
#define LN1_BLOCKS (TOK/8)                        // 12544

// ---------------------------------------------------------------------------
__device__ __forceinline__ uint32_t smem_u32(const void* p) {
    return (uint32_t)__cvta_generic_to_shared(p);
}
__device__ __forceinline__ void cp_async16(uint32_t dst, const void* src) {
    asm volatile("cp.async.cg.shared.global [%0], [%1], 16;" :: "r"(dst), "l"(src));
}

#define LDSM4(r0,r1,r2,r3,addr) \
    asm volatile("ldmatrix.sync.aligned.m8n8.x4.shared.b16 {%0,%1,%2,%3}, [%4];" \
        : "=r"(r0),"=r"(r1),"=r"(r2),"=r"(r3) : "r"(addr))

#define MMA16816(c, a, b) \
    asm volatile("mma.sync.aligned.m16n8k16.row.col.f32.f16.f16.f32 " \
        "{%0,%1,%2,%3},{%4,%5,%6,%7},{%8,%9},{%0,%1,%2,%3};" \
        : "+f"(c[0]),"+f"(c[1]),"+f"(c[2]),"+f"(c[3]) \
        : "r"(a[0]),"r"(a[1]),"r"(a[2]),"r"(a[3]),"r"(b[0]),"r"(b[1]))

__device__ __forceinline__ float gelu_tanh(float v) {
    float u = 0.7978845608028654f * (v + 0.044715f * v * v * v);
    float th;
    asm("tanh.approx.f32 %0, %1;" : "=f"(th) : "f"(u));
    return 0.5f * v * (1.0f + th);
}

// ---------------------------------------------------------------------------
// kernel 1: weight conversion fp32->fp16 + CPB table (extra blocks)
// ---------------------------------------------------------------------------
__device__ __forceinline__ float relcoord(int d) {
    float v = 8.0f * (float)d / 6.0f;
    return copysignf(log2f(fabsf(v) + 1.0f) * (1.0f / 3.0f), v);
}

__global__ void __launch_bounds__(256) f2h_cpb(
    const float* __restrict__ w_qkv, const float* __restrict__ w_prj,
    const float* __restrict__ w_m1,  const float* __restrict__ w_m2,
    const float* __restrict__ cw1, const float* __restrict__ cb1,
    const float* __restrict__ cw2)
{
    if (blockIdx.x < F2H_BLOCKS) {
        int i = blockIdx.x * 256 + threadIdx.x;
        if (i < SZ_QKV) {
            g_wqkv[i] = __float2half(w_qkv[i]);
        } else if (i < SZ_QKV + SZ_PRJ) {
            g_wproj[i - SZ_QKV] = __float2half(w_prj[i - SZ_QKV]);
        } else if (i < SZ_QKV + SZ_PRJ + SZ_M1) {
            g_wm1[i - SZ_QKV - SZ_PRJ] = __float2half(w_m1[i - SZ_QKV - SZ_PRJ]);
        } else if (i < SZ_ALL) {
            g_wm2[i - SZ_QKV - SZ_PRJ - SZ_M1] = __float2half(w_m2[i - SZ_QKV - SZ_PRJ - SZ_M1]);
        }
    } else {
        // CPB: one block per rel-coord p
        int p  = blockIdx.x - F2H_BLOCKS;
        float r0 = relcoord(p / 13 - 6);
        float r1 = relcoord(p % 13 - 6);
        float acc[HEADS];
#pragma unroll
        for (int h = 0; h < HEADS; h++) acc[h] = 0.f;
        for (int j = threadIdx.x; j < 512; j += 256) {
            float hv = fmaxf(r0 * cw1[j*2] + r1 * cw1[j*2+1] + cb1[j], 0.f);
#pragma unroll
            for (int h = 0; h < HEADS; h++) acc[h] += hv * cw2[h*512 + j];
        }
        __shared__ float red[256];
        for (int h = 0; h < HEADS; h++) {
            red[threadIdx.x] = acc[h];
            __syncthreads();
            for (int s = 128; s > 0; s >>= 1) {
                if (threadIdx.x < s) red[threadIdx.x] += red[threadIdx.x + s];
                __syncthreads();
            }
            if (threadIdx.x == 0) g_tab[p*HEADS + h] = red[0];
            __syncthreads();
        }
    }
}

// ---------------------------------------------------------------------------
// kernel 2: LN1 (warp-per-token) + bias table (extra blocks)
// ---------------------------------------------------------------------------
__global__ void __launch_bounds__(256) ln1_bias(
    const float* __restrict__ x, const float* __restrict__ g,
    const float* __restrict__ bb, const float* __restrict__ mask)
{
    if (blockIdx.x < LN1_BLOCKS) {
        const int warp = threadIdx.x >> 5, lane = threadIdx.x & 31;
        const int t   = blockIdx.x * 8 + warp;
        const int win = t / Nn49, n = t % Nn49;
        const int b   = win >> 6, wi = win & 63;
        const int hh  = ((wi >> 3)*WIN + n/WIN + SHIFT) % Hh;
        const int ww  = ((wi & 7)*WIN + n%WIN + SHIFT) % Wwid;
        const float4* row = (const float4*)(x + (((size_t)b*Hh + hh)*Wwid + ww) * Cc);

        float4 v[3];
#pragma unroll
        for (int i = 0; i < 3; i++) v[i] = row[lane + 32*i];

        float s = 0.f, s2 = 0.f;
#pragma unroll
        for (int i = 0; i < 3; i++) {
            s  += v[i].x + v[i].y + v[i].z + v[i].w;
            s2 += v[i].x*v[i].x + v[i].y*v[i].y + v[i].z*v[i].z + v[i].w*v[i].w;
        }
#pragma unroll
        for (int off = 16; off; off >>= 1) {
            s  += __shfl_xor_sync(0xffffffffu, s,  off);
            s2 += __shfl_xor_sync(0xffffffffu, s2, off);
        }
        float mu  = s * (1.f/384.f);
        float var = s2 * (1.f/384.f) - mu*mu;
        float inv = rsqrtf(var + 1e-5f);

        uint2* dst = (uint2*)(g_a + (size_t)t * Cc);
        const float4* gg = (const float4*)g;
        const float4* bv4 = (const float4*)bb;
#pragma unroll
        for (int i = 0; i < 3; i++) {
            float4 gv = gg[lane + 32*i];
            float4 bv = bv4[lane + 32*i];
            __half2 h0 = __floats2half2_rn((v[i].x - mu)*inv*gv.x + bv.x,
                                           (v[i].y - mu)*inv*gv.y + bv.y);
            __half2 h1 = __floats2half2_rn((v[i].z - mu)*inv*gv.z + bv.z,
                                           (v[i].w - mu)*inv*gv.w + bv.w);
            uint2 u; u.x = *(uint32_t*)&h0; u.y = *(uint32_t*)&h1;
            dst[lane + 32*i] = u;
        }
    } else {
        // bias tile: idx -> (wm, h). Requires g_tab (written by kernel 1).
        int idx = blockIdx.x - LN1_BLOCKS;
        int wm = idx & 63, h = idx >> 6;
        float* dst = g_bias + ((size_t)wm*HEADS + h) * (Nn49*Nn49);
        const float* msk = mask + (size_t)wm * (Nn49*Nn49);
        for (int e = threadIdx.x; e < Nn49*Nn49; e += 256) {
            int i = e / Nn49, j = e % Nn49;
            int di = (i/WIN - j/WIN + 6)*13 + (i%WIN - j%WIN + 6);
            float t = g_tab[di*HEADS + h];
            dst[e] = 16.f / (1.f + __expf(-t)) + msk[e];
        }
    }
}

// ---------------------------------------------------------------------------
// fp16 HMMA GEMM: BM=128, BN=128, BK=32, 3-stage cp.async, 1 barrier/iter,
// 8 warps (2x4), warp tile 64x32.
// EPI: 0 fp16+bias (smem-staged coalesced store)
//      1 fp16+bias+GELU(tanh) (smem-staged)
//      3 fp32+bias+resid (row-direct, MLP2 -> d_out)
//      4 fp32+bias + x-residual with window->spatial scatter (proj -> g_x2)
// ---------------------------------------------------------------------------
#define STAGES    3
#define TS_STAGE  (128*40)
#define GEMM_SMEM (STAGES*2*TS_STAGE*2)          // 61440 bytes
#define STG_STRIDE 136

template<int EPI>
__global__ void __launch_bounds__(256, 2) hgemm(
    const __half* __restrict__ A, const __half* __restrict__ Wt,
    const float* __restrict__ bias, const float* __restrict__ resid,
    void* __restrict__ Cptr, int M, int Nd, int K)
{
    extern __shared__ __half dyns[];
    __half* Asm = dyns;
    __half* Bsm = dyns + STAGES*TS_STAGE;

    const int tid  = threadIdx.x;
    const int bm   = blockIdx.y * 128;
    const int bn   = blockIdx.x * 128;
    const int wid  = tid >> 5, lane = tid & 31;
    const int wm   = (wid & 1) * 64;
    const int wn   = (wid >> 1) * 32;

    float acc[4][4][4];
#pragma unroll
    for (int mi = 0; mi < 4; mi++)
#pragma unroll
        for (int ni = 0; ni < 4; ni++)
#pragma unroll
            for (int q = 0; q < 4; q++) acc[mi][ni][q] = 0.f;

    const int lr = tid >> 2;
    const int lc = (tid & 3) * 8;
    const int nk = K >> 5;

    auto load_stage = [&](int slot, int kt) {
        __half* As = Asm + slot*TS_STAGE;
        __half* Bs = Bsm + slot*TS_STAGE;
        int k0 = kt << 5;
#pragma unroll
        for (int r = 0; r < 2; r++) {
            int row = lr + 64*r;
            cp_async16(smem_u32(&As[row*40 + lc]), A  + (size_t)(bm+row)*K + k0 + lc);
            cp_async16(smem_u32(&Bs[row*40 + lc]), Wt + (size_t)(bn+row)*K + k0 + lc);
        }
    };

#pragma unroll
    for (int s = 0; s < STAGES-1; s++) {
        if (s < nk) load_stage(s, s);
        asm volatile("cp.async.commit_group;");
    }

    for (int kt = 0; kt < nk; kt++) {
        asm volatile("cp.async.wait_group %0;" :: "n"(STAGES-2));
        __syncthreads();

        int pre = kt + STAGES - 1;
        if (pre < nk) load_stage(pre % STAGES, pre);
        asm volatile("cp.async.commit_group;");

        const __half* As = Asm + (kt % STAGES)*TS_STAGE;
        const __half* Bs = Bsm + (kt % STAGES)*TS_STAGE;

#pragma unroll
        for (int kk = 0; kk < 2; kk++) {
            uint32_t a[4][4], b[4][2];
#pragma unroll
            for (int mi = 0; mi < 4; mi++) {
                int row = wm + mi*16 + (lane & 15);
                int col = kk*16 + ((lane >> 4) << 3);
                LDSM4(a[mi][0], a[mi][1], a[mi][2], a[mi][3],
                      smem_u32(&As[row*40 + col]));
            }
#pragma unroll
            for (int bi = 0; bi < 2; bi++) {
                int n   = wn + bi*16 + ((lane >> 4) << 3) + (lane & 7);
                int col = kk*16 + ((lane >> 3) & 1) * 8;
                uint32_t t0, t1, t2, t3;
                LDSM4(t0, t1, t2, t3, smem_u32(&Bs[n*40 + col]));
                b[bi*2+0][0] = t0; b[bi*2+0][1] = t1;
                b[bi*2+1][0] = t2; b[bi*2+1][1] = t3;
            }
#pragma unroll
            for (int mi = 0; mi < 4; mi++)
#pragma unroll
                for (int ni = 0; ni < 4; ni++)
                    MMA16816(acc[mi][ni], a[mi], b[ni]);
        }
    }

    const int er = lane >> 2, ec = (lane & 3) * 2;

    if (EPI == 0 || EPI == 1) {
        __syncthreads();
        __half* stg = Asm;
#pragma unroll
        for (int mi = 0; mi < 4; mi++) {
#pragma unroll
            for (int ni = 0; ni < 4; ni++) {
                int col = wn + ni*8 + ec;
                float b0 = bias[bn + col], b1 = bias[bn + col + 1];
#pragma unroll
                for (int hh = 0; hh < 2; hh++) {
                    int row = wm + mi*16 + er + hh*8;
                    float v0 = acc[mi][ni][hh*2+0] + b0;
                    float v1 = acc[mi][ni][hh*2+1] + b1;
                    if (EPI == 1) {
                        v0 = gelu_tanh(v0);
                        v1 = gelu_tanh(v1);
                    }
                    *(__half2*)&stg[row*STG_STRIDE + col] = __floats2half2_rn(v0, v1);
                }
            }
        }
        __syncthreads();
#pragma unroll
        for (int i = 0; i < 8; i++) {
            int idx = tid + i*256;
            int row = idx >> 4;
            int u   = idx & 15;
            uint4 v = *(const uint4*)&stg[row*STG_STRIDE + u*8];
            *(uint4*)((__half*)Cptr + (size_t)(bm + row) * Nd + bn + u*8) = v;
        }
    } else if (EPI == 4) {
        // proj: out[spatial] = acc + bias + x[spatial]  (window -> spatial scatter)
#pragma unroll
        for (int mi = 0; mi < 4; mi++) {
#pragma unroll
            for (int hh = 0; hh < 2; hh++) {
                int rp  = bm + wm + mi*16 + er + hh*8;
                int win = rp / Nn49, n = rp % Nn49;
                int b   = win >> 6,  wi = win & 63;
                int sh  = (wi >> 3)*WIN + n/WIN;
                int sw  = (wi & 7)*WIN + n%WIN;
                int hs  = sh + SHIFT; if (hs >= Hh)   hs -= Hh;
                int ws  = sw + SHIFT; if (ws >= Wwid) ws -= Wwid;
                size_t srow = ((size_t)b*Hh + hs)*Wwid + ws;
#pragma unroll
                for (int ni = 0; ni < 4; ni++) {
                    int col = bn + wn + ni*8 + ec;
                    const float* xr = resid + srow * Nd + col;
                    float2 f;
                    f.x = acc[mi][ni][hh*2+0] + bias[col] + xr[0];
                    f.y = acc[mi][ni][hh*2+1] + bias[col+1] + xr[1];
                    *(float2*)((float*)Cptr + srow * Nd + col) = f;
                }
            }
        }
    } else {
        // EPI 3: fp32 + bias + row-direct residual
#pragma unroll
        for (int mi = 0; mi < 4; mi++) {
#pragma unroll
            for (int ni = 0; ni < 4; ni++) {
                int col = bn + wn + ni*8 + ec;
                float b0 = bias[col], b1 = bias[col+1];
#pragma unroll
                for (int hh = 0; hh < 2; hh++) {
                    size_t row = (size_t)(bm + wm + mi*16 + er + hh*8);
                    const float* rr = resid + row * Nd + col;
                    float2 f;
                    f.x = acc[mi][ni][hh*2+0] + b0 + rr[0];
                    f.y = acc[mi][ni][hh*2+1] + b1 + rr[1];
                    *(float2*)((float*)Cptr + row * Nd + col) = f;
                }
            }
        }
    }
}

// ---------------------------------------------------------------------------
// Tensor-core window attention. Zero-fill limited to the only regions whose
// garbage can propagate: vt cols 48-71 (col 48 re-written by the transpose
// after the barrier) and ps cols 56-71. All other garbage is replaced (not
// accumulated) by the masked-softmax epilogue.
// ---------------------------------------------------------------------------
__global__ void __launch_bounds__(128) attn_kernel(const float* __restrict__ lscale)
{
    const int win = blockIdx.x;
    const int h   = blockIdx.y;
    const int wm  = win & 63;
    const int tid = threadIdx.x;
    const int warp = tid >> 5, lane = tid & 31;

    __shared__ __half qs[64*40];
    __shared__ __half ks[64*40];
    __shared__ __half vt[32*72];
    __shared__ __half ps[64*72];

    {
        uint4 z = make_uint4(0,0,0,0);
        for (int i = tid; i < 96 + 128; i += 128) {
            if (i < 96) {                      // vt[d][48..71], 3 uint4 per d
                int d = i / 3, c = (i % 3) * 8 + 48;
                *(uint4*)(vt + d*72 + c) = z;
            } else {                           // ps[r][56..71], 2 uint4 per row
                int r = (i - 96) >> 1, c = ((i - 96) & 1) * 8 + 56;
                *(uint4*)(ps + r*72 + c) = z;
            }
        }
    }
    __syncthreads();

    const __half* base = g_qkv + (size_t)(win*Nn49) * (3*Cc) + h*HD;
    for (int idx = tid; idx < Nn49*4; idx += 128) {
        int row = idx >> 2;
        int c   = (idx & 3) * 8;
        const __half* rb = base + (size_t)row * (3*Cc) + c;
        uint4 qv = *(const uint4*)(rb);
        uint4 kv = *(const uint4*)(rb + Cc);
        uint4 vv = *(const uint4*)(rb + 2*Cc);
        *(uint4*)(qs + row*40 + c) = qv;
        *(uint4*)(ks + row*40 + c) = kv;
        __half hb[8]; *(uint4*)hb = vv;
#pragma unroll
        for (int m = 0; m < 8; m++) vt[(c+m)*72 + row] = hb[m];
    }
    __syncthreads();

    {
        float scale_h = __expf(fminf(lscale[h], 4.6051701859880914f));
        int r = -1; bool isq = false;
        if (tid < Nn49) { r = tid; isq = true; }
        else if (tid >= 64 && tid < 64 + Nn49) { r = tid - 64; }
        if (r >= 0) {
            __half* row = (isq ? qs : ks) + r*40;
            float ss = 0.f;
#pragma unroll
            for (int d = 0; d < HD; d += 2) {
                float2 f = __half22float2(*(__half2*)(row + d));
                ss += f.x*f.x + f.y*f.y;
            }
            float inv = 1.0f / fmaxf(sqrtf(ss), 1e-12f);
            if (isq) inv *= scale_h;
#pragma unroll
            for (int d = 0; d < HD; d += 2) {
                __half2* p = (__half2*)(row + d);
                float2 f = __half22float2(*p);
                *p = __floats2half2_rn(f.x*inv, f.y*inv);
            }
        }
    }
    __syncthreads();

    float s[7][4];
#pragma unroll
    for (int t = 0; t < 7; t++)
#pragma unroll
        for (int c = 0; c < 4; c++) s[t][c] = 0.f;

#pragma unroll
    for (int kk = 0; kk < 2; kk++) {
        uint32_t a[4];
        {
            int row = warp*16 + (lane & 15);
            int col = kk*16 + ((lane >> 4) << 3);
            LDSM4(a[0], a[1], a[2], a[3], smem_u32(qs + row*40 + col));
        }
        uint32_t b[8][2];
#pragma unroll
        for (int bi = 0; bi < 4; bi++) {
            int n   = bi*16 + ((lane >> 4) << 3) + (lane & 7);
            int col = kk*16 + ((lane >> 3) & 1) * 8;
            uint32_t t0, t1, t2, t3;
            LDSM4(t0, t1, t2, t3, smem_u32(ks + n*40 + col));
            b[bi*2+0][0] = t0; b[bi*2+0][1] = t1;
            b[bi*2+1][0] = t2; b[bi*2+1][1] = t3;
        }
#pragma unroll
        for (int t = 0; t < 7; t++)
            MMA16816(s[t], a, b[t]);
    }

    {
        const float* bias = g_bias + ((size_t)wm*HEADS + h) * (Nn49*Nn49);
        int r0 = lane >> 2;
        int i0 = warp*16 + r0;
        int i1 = i0 + 8;
        int jb = (lane & 3) * 2;
#pragma unroll
        for (int t = 0; t < 7; t++) {
#pragma unroll
            for (int c = 0; c < 4; c++) {
                int i = (c >= 2) ? i1 : i0;
                int j = t*8 + jb + (c & 1);
                s[t][c] = (i < Nn49 && j < Nn49) ? s[t][c] + bias[i*Nn49 + j]
                                                 : -1e30f;
            }
        }
        float mx0 = -1e30f, mx1 = -1e30f;
#pragma unroll
        for (int t = 0; t < 7; t++) {
            mx0 = fmaxf(mx0, fmaxf(s[t][0], s[t][1]));
            mx1 = fmaxf(mx1, fmaxf(s[t][2], s[t][3]));
        }
#pragma unroll
        for (int off = 1; off <= 2; off <<= 1) {
            mx0 = fmaxf(mx0, __shfl_xor_sync(0xffffffffu, mx0, off));
            mx1 = fmaxf(mx1, __shfl_xor_sync(0xffffffffu, mx1, off));
        }
        float sm0 = 0.f, sm1 = 0.f;
#pragma unroll
        for (int t = 0; t < 7; t++) {
            s[t][0] = __expf(s[t][0] - mx0); sm0 += s[t][0];
            s[t][1] = __expf(s[t][1] - mx0); sm0 += s[t][1];
            s[t][2] = __expf(s[t][2] - mx1); sm1 += s[t][2];
            s[t][3] = __expf(s[t][3] - mx1); sm1 += s[t][3];
        }
#pragma unroll
        for (int off = 1; off <= 2; off <<= 1) {
            sm0 += __shfl_xor_sync(0xffffffffu, sm0, off);
            sm1 += __shfl_xor_sync(0xffffffffu, sm1, off);
        }
        float inv0 = 1.0f / sm0, inv1 = 1.0f / sm1;
#pragma unroll
        for (int t = 0; t < 7; t++) {
            int j0 = t*8 + jb;
            *(__half2*)(ps + (i0 & 63)*72 + j0) = __floats2half2_rn(s[t][0]*inv0, s[t][1]*inv0);
            *(__half2*)(ps + (i1 & 63)*72 + j0) = __floats2half2_rn(s[t][2]*inv1, s[t][3]*inv1);
        }
    }
    __syncwarp();

    float o[4][4];
#pragma unroll
    for (int t = 0; t < 4; t++)
#pragma unroll
        for (int c = 0; c < 4; c++) o[t][c] = 0.f;

#pragma unroll
    for (int kk = 0; kk < 4; kk++) {
        uint32_t a[4];
        {
            int row = warp*16 + (lane & 15);
            int col = kk*16 + ((lane >> 4) << 3);
            LDSM4(a[0], a[1], a[2], a[3], smem_u32(ps + row*72 + col));
        }
        uint32_t b[4][2];
#pragma unroll
        for (int bi = 0; bi < 2; bi++) {
            int n   = bi*16 + ((lane >> 4) << 3) + (lane & 7);
            int col = kk*16 + ((lane >> 3) & 1) * 8;
            uint32_t t0, t1, t2, t3;
            LDSM4(t0, t1, t2, t3, smem_u32(vt + n*72 + col));
            b[bi*2+0][0] = t0; b[bi*2+0][1] = t1;
            b[bi*2+1][0] = t2; b[bi*2+1][1] = t3;
        }
#pragma unroll
        for (int t = 0; t < 4; t++)
            MMA16816(o[t], a, b[t]);
    }

    {
        int r0 = lane >> 2;
        int i0 = warp*16 + r0;
        int i1 = i0 + 8;
        int d0 = (lane & 3) * 2;
#pragma unroll
        for (int t = 0; t < 4; t++) {
            int d = t*8 + d0;
            if (i0 < Nn49)
                *(__half2*)(g_o + (size_t)(win*Nn49 + i0)*Cc + h*HD + d) =
                    __floats2half2_rn(o[t][0], o[t][1]);
            if (i1 < Nn49)
                *(__half2*)(g_o + (size_t)(win*Nn49 + i1)*Cc + h*HD + d) =
                    __floats2half2_rn(o[t][2], o[t][3]);
        }
    }
}

// ---------------------------------------------------------------------------
// LN2 on g_x2 -> g_xm (fp16). WARP-PER-TOKEN, 8 tokens/block.
// ---------------------------------------------------------------------------
__global__ void __launch_bounds__(256) ln2_kernel(
    const float* __restrict__ g, const float* __restrict__ bb)
{
    const int warp = threadIdx.x >> 5, lane = threadIdx.x & 31;
    const int t = blockIdx.x * 8 + warp;
    const float4* row = (const float4*)(g_x2 + (size_t)t * Cc);

    float4 v[3];
#pragma unroll
    for (int i = 0; i < 3; i++) v[i] = row[lane + 32*i];

    float s = 0.f, s2 = 0.f;
#pragma unroll
    for (int i = 0; i < 3; i++) {
        s  += v[i].x + v[i].y + v[i].z + v[i].w;
        s2 += v[i].x*v[i].x + v[i].y*v[i].y + v[i].z*v[i].z + v[i].w*v[i].w;
    }
#pragma unroll
    for (int off = 16; off; off >>= 1) {
        s  += __shfl_xor_sync(0xffffffffu, s,  off);
        s2 += __shfl_xor_sync(0xffffffffu, s2, off);
    }
    float mu  = s * (1.f/384.f);
    float var = s2 * (1.f/384.f) - mu*mu;
    float inv = rsqrtf(var + 1e-5f);

    uint2* dst = (uint2*)(g_xm + (size_t)t * Cc);
    const float4* gg = (const float4*)g;
    const float4* bv4 = (const float4*)bb;
#pragma unroll
    for (int i = 0; i < 3; i++) {
        float4 gv = gg[lane + 32*i];
        float4 bv = bv4[lane + 32*i];
        __half2 h0 = __floats2half2_rn((v[i].x - mu)*inv*gv.x + bv.x,
                                       (v[i].y - mu)*inv*gv.y + bv.y);
        __half2 h1 = __floats2half2_rn((v[i].z - mu)*inv*gv.z + bv.z,
                                       (v[i].w - mu)*inv*gv.w + bv.w);
        uint2 u; u.x = *(uint32_t*)&h0; u.y = *(uint32_t*)&h1;
        dst[lane + 32*i] = u;
    }
}

// ---------------------------------------------------------------------------
extern "C" void kernel_launch(void* const* d_in, const int* in_sizes, int n_in,
                              void* d_out, int out_size)
{
    const float* x       = (const float*)d_in[0];
    const float* mask    = (const float*)d_in[1];
    const float* n1g     = (const float*)d_in[2];
    const float* n1b     = (const float*)d_in[3];
    const float* qkv_w   = (const float*)d_in[4];
    const float* qkv_b   = (const float*)d_in[5];
    const float* proj_w  = (const float*)d_in[6];
    const float* proj_b  = (const float*)d_in[7];
    const float* cpb_w1  = (const float*)d_in[8];
    const float* cpb_b1  = (const float*)d_in[9];
    const float* cpb_w2  = (const float*)d_in[10];
    const float* lscale  = (const float*)d_in[11];
    const float* n2g     = (const float*)d_in[12];
    const float* n2b     = (const float*)d_in[13];
    const float* mlp_w1  = (const float*)d_in[14];
    const float* mlp_b1  = (const float*)d_in[15];
    const float* mlp_w2  = (const float*)d_in[16];
    const float* mlp_b2  = (const float*)d_in[17];
    float* out = (float*)d_out;

    __half *a=nullptr, *qkv=nullptr, *o=nullptr, *xm=nullptr, *hidden=nullptr;
    __half *wqkv=nullptr, *wproj=nullptr, *wm1=nullptr, *wm2=nullptr;
    float *x2=nullptr;
    cudaGetSymbolAddress((void**)&a,       g_a);
    cudaGetSymbolAddress((void**)&qkv,     g_qkv);
    cudaGetSymbolAddress((void**)&o,       g_o);
    cudaGetSymbolAddress((void**)&x2,      g_x2);
    cudaGetSymbolAddress((void**)&xm,      g_xm);
    cudaGetSymbolAddress((void**)&hidden,  g_hidden);
    cudaGetSymbolAddress((void**)&wqkv,    g_wqkv);
    cudaGetSymbolAddress((void**)&wproj,   g_wproj);
    cudaGetSymbolAddress((void**)&wm1,     g_wm1);
    cudaGetSymbolAddress((void**)&wm2,     g_wm2);

    cudaFuncSetAttribute(hgemm<0>, cudaFuncAttributeMaxDynamicSharedMemorySize, GEMM_SMEM);
    cudaFuncSetAttribute(hgemm<1>, cudaFuncAttributeMaxDynamicSharedMemorySize, GEMM_SMEM);
    cudaFuncSetAttribute(hgemm<3>, cudaFuncAttributeMaxDynamicSharedMemorySize, GEMM_SMEM);
    cudaFuncSetAttribute(hgemm<4>, cudaFuncAttributeMaxDynamicSharedMemorySize, GEMM_SMEM);

    // 1: weights fp32->fp16 + CPB table (fused grid)
    f2h_cpb<<<F2H_BLOCKS + 169, 256>>>(qkv_w, proj_w, mlp_w1, mlp_w2,
                                       cpb_w1, cpb_b1, cpb_w2);
    // 2: LN1 (warp-per-token) + bias table (fused grid; cpb done in k1)
    ln1_bias<<<LN1_BLOCKS + NW*HEADS, 256>>>(x, n1g, n1b, mask);
    // 3: QKV GEMM -> fp16
    hgemm<0><<<dim3(9, TOK/128), 256, GEMM_SMEM>>>(a, wqkv, qkv_b, nullptr, qkv, TOK, 3*Cc, Cc);
    // 4: tensor-core window attention  (profiled launch slot)
    attn_kernel<<<dim3(NWIN, HEADS), 128>>>(lscale);
    // 5: proj GEMM + x residual + spatial scatter -> g_x2 (fp32)
    hgemm<4><<<dim3(3, TOK/128), 256, GEMM_SMEM>>>(o, wproj, proj_b, x, x2, TOK, Cc, Cc);
    // 6: LN2 (warp-per-token) -> g_xm (fp16)
    ln2_kernel<<<TOK/8, 256>>>(n2g, n2b);
    // 7: MLP1 + GELU -> fp16
    hgemm<1><<<dim3(6, TOK/128), 256, GEMM_SMEM>>>(xm, wm1, mlp_b1, nullptr, hidden, TOK, HIDDEN, Cc);
    // 8: MLP2 + x2 residual -> d_out (fp32)
    hgemm<3><<<dim3(3, TOK/128), 256, GEMM_SMEM>>>(hidden, wm2, mlp_b2, x2, out, TOK, Cc, HIDDEN);
}

// round 14
// speedup vs baseline: 1.1175x; 1.0059x over previous
#include <cuda_runtime.h>
#include <cuda_fp16.h>
#include <cstdint>
#include <math.h>

// ---------------------------------------------------------------------------
// SwinV2 block: B=32, H=W=56, C=384, HEADS=12, WIN=7, SHIFT=3
// ---------------------------------------------------------------------------
#define Bb      32
#define Hh      56
#define Wwid    56
#define Cc      384
#define HEADS   12
#define HD      32
#define WIN     7
#define SHIFT   3
#define Nn49    49
#define NW      64
#define NWIN    (Bb*NW)       // 2048
#define TOK     (NWIN*Nn49)   // 100352
#define HIDDEN  768

// scratch (static device globals)
__device__ __half g_a      [(size_t)TOK * Cc];
__device__ __half g_qkv    [(size_t)TOK * 3 * Cc];
__device__ __half g_o      [(size_t)TOK * Cc];
__device__ float  g_x2     [(size_t)TOK * Cc];      // x + attn residual (spatial)
__device__ __half g_xm     [(size_t)TOK * Cc];
__device__ __half g_hidden [(size_t)TOK * HIDDEN];
__device__ float  g_tab    [169 * HEADS];
__device__ float  g_bias   [(size_t)NW * HEADS * Nn49 * Nn49];
// fp16 weights
__device__ __half g_wqkv [3*Cc*Cc];
__device__ __half g_wproj[Cc*Cc];
__device__ __half g_wm1  [HIDDEN*Cc];
__device__ __half g_wm2  [Cc*HIDDEN];

#define SZ_QKV (3*Cc*Cc)
#define SZ_PRJ (Cc*Cc)
#define SZ_M1  (HIDDEN*Cc)
#define SZ_M2  (Cc*HIDDEN)
#define SZ_ALL (SZ_QKV+SZ_PRJ+SZ_M1+SZ_M2)
#define F2H_BLOCKS ((SZ_ALL + 255)/256)          // 4608
#define LN1_BLOCKS (TOK/8)                        // 12544

// ---------------------------------------------------------------------------
__device__ __forceinline__ uint32_t smem_u32(const void* p) {
    return (uint32_t)__cvta_generic_to_shared(p);
}
__device__ __forceinline__ void cp_async16(uint32_t dst, const void* src) {
    asm volatile("cp.async.cg.shared.global [%0], [%1], 16;" :: "r"(dst), "l"(src));
}

#define LDSM4(r0,r1,r2,r3,addr) \
    asm volatile("ldmatrix.sync.aligned.m8n8.x4.shared.b16 {%0,%1,%2,%3}, [%4];" \
        : "=r"(r0),"=r"(r1),"=r"(r2),"=r"(r3) : "r"(addr))

#define LDSM4T(r0,r1,r2,r3,addr) \
    asm volatile("ldmatrix.sync.aligned.m8n8.x4.trans.shared.b16 {%0,%1,%2,%3}, [%4];" \
        : "=r"(r0),"=r"(r1),"=r"(r2),"=r"(r3) : "r"(addr))

#define MMA16816(c, a, b) \
    asm volatile("mma.sync.aligned.m16n8k16.row.col.f32.f16.f16.f32 " \
        "{%0,%1,%2,%3},{%4,%5,%6,%7},{%8,%9},{%0,%1,%2,%3};" \
        : "+f"(c[0]),"+f"(c[1]),"+f"(c[2]),"+f"(c[3]) \
        : "r"(a[0]),"r"(a[1]),"r"(a[2]),"r"(a[3]),"r"(b[0]),"r"(b[1]))

__device__ __forceinline__ float gelu_tanh(float v) {
    float u = 0.7978845608028654f * (v + 0.044715f * v * v * v);
    float th;
    asm("tanh.approx.f32 %0, %1;" : "=f"(th) : "f"(u));
    return 0.5f * v * (1.0f + th);
}

// ---------------------------------------------------------------------------
// kernel 1: weight conversion fp32->fp16 + CPB table (extra blocks)
// ---------------------------------------------------------------------------
__device__ __forceinline__ float relcoord(int d) {
    float v = 8.0f * (float)d / 6.0f;
    return copysignf(log2f(fabsf(v) + 1.0f) * (1.0f / 3.0f), v);
}

__global__ void __launch_bounds__(256) f2h_cpb(
    const float* __restrict__ w_qkv, const float* __restrict__ w_prj,
    const float* __restrict__ w_m1,  const float* __restrict__ w_m2,
    const float* __restrict__ cw1, const float* __restrict__ cb1,
    const float* __restrict__ cw2)
{
    if (blockIdx.x < F2H_BLOCKS) {
        int i = blockIdx.x * 256 + threadIdx.x;
        if (i < SZ_QKV) {
            g_wqkv[i] = __float2half(w_qkv[i]);
        } else if (i < SZ_QKV + SZ_PRJ) {
            g_wproj[i - SZ_QKV] = __float2half(w_prj[i - SZ_QKV]);
        } else if (i < SZ_QKV + SZ_PRJ + SZ_M1) {
            g_wm1[i - SZ_QKV - SZ_PRJ] = __float2half(w_m1[i - SZ_QKV - SZ_PRJ]);
        } else if (i < SZ_ALL) {
            g_wm2[i - SZ_QKV - SZ_PRJ - SZ_M1] = __float2half(w_m2[i - SZ_QKV - SZ_PRJ - SZ_M1]);
        }
    } else {
        int p  = blockIdx.x - F2H_BLOCKS;
        float r0 = relcoord(p / 13 - 6);
        float r1 = relcoord(p % 13 - 6);
        float acc[HEADS];
#pragma unroll
        for (int h = 0; h < HEADS; h++) acc[h] = 0.f;
        for (int j = threadIdx.x; j < 512; j += 256) {
            float hv = fmaxf(r0 * cw1[j*2] + r1 * cw1[j*2+1] + cb1[j], 0.f);
#pragma unroll
            for (int h = 0; h < HEADS; h++) acc[h] += hv * cw2[h*512 + j];
        }
        __shared__ float red[256];
        for (int h = 0; h < HEADS; h++) {
            red[threadIdx.x] = acc[h];
            __syncthreads();
            for (int s = 128; s > 0; s >>= 1) {
                if (threadIdx.x < s) red[threadIdx.x] += red[threadIdx.x + s];
                __syncthreads();
            }
            if (threadIdx.x == 0) g_tab[p*HEADS + h] = red[0];
            __syncthreads();
        }
    }
}

// ---------------------------------------------------------------------------
// kernel 2: LN1 (warp-per-token) + bias table (extra blocks)
// ---------------------------------------------------------------------------
__global__ void __launch_bounds__(256) ln1_bias(
    const float* __restrict__ x, const float* __restrict__ g,
    const float* __restrict__ bb, const float* __restrict__ mask)
{
    if (blockIdx.x < LN1_BLOCKS) {
        const int warp = threadIdx.x >> 5, lane = threadIdx.x & 31;
        const int t   = blockIdx.x * 8 + warp;
        const int win = t / Nn49, n = t % Nn49;
        const int b   = win >> 6, wi = win & 63;
        const int hh  = ((wi >> 3)*WIN + n/WIN + SHIFT) % Hh;
        const int ww  = ((wi & 7)*WIN + n%WIN + SHIFT) % Wwid;
        const float4* row = (const float4*)(x + (((size_t)b*Hh + hh)*Wwid + ww) * Cc);

        float4 v[3];
#pragma unroll
        for (int i = 0; i < 3; i++) v[i] = row[lane + 32*i];

        float s = 0.f, s2 = 0.f;
#pragma unroll
        for (int i = 0; i < 3; i++) {
            s  += v[i].x + v[i].y + v[i].z + v[i].w;
            s2 += v[i].x*v[i].x + v[i].y*v[i].y + v[i].z*v[i].z + v[i].w*v[i].w;
        }
#pragma unroll
        for (int off = 16; off; off >>= 1) {
            s  += __shfl_xor_sync(0xffffffffu, s,  off);
            s2 += __shfl_xor_sync(0xffffffffu, s2, off);
        }
        float mu  = s * (1.f/384.f);
        float var = s2 * (1.f/384.f) - mu*mu;
        float inv = rsqrtf(var + 1e-5f);

        uint2* dst = (uint2*)(g_a + (size_t)t * Cc);
        const float4* gg = (const float4*)g;
        const float4* bv4 = (const float4*)bb;
#pragma unroll
        for (int i = 0; i < 3; i++) {
            float4 gv = gg[lane + 32*i];
            float4 bv = bv4[lane + 32*i];
            __half2 h0 = __floats2half2_rn((v[i].x - mu)*inv*gv.x + bv.x,
                                           (v[i].y - mu)*inv*gv.y + bv.y);
            __half2 h1 = __floats2half2_rn((v[i].z - mu)*inv*gv.z + bv.z,
                                           (v[i].w - mu)*inv*gv.w + bv.w);
            uint2 u; u.x = *(uint32_t*)&h0; u.y = *(uint32_t*)&h1;
            dst[lane + 32*i] = u;
        }
    } else {
        int idx = blockIdx.x - LN1_BLOCKS;
        int wm = idx & 63, h = idx >> 6;
        float* dst = g_bias + ((size_t)wm*HEADS + h) * (Nn49*Nn49);
        const float* msk = mask + (size_t)wm * (Nn49*Nn49);
        for (int e = threadIdx.x; e < Nn49*Nn49; e += 256) {
            int i = e / Nn49, j = e % Nn49;
            int di = (i/WIN - j/WIN + 6)*13 + (i%WIN - j%WIN + 6);
            float t = g_tab[di*HEADS + h];
            dst[e] = 16.f / (1.f + __expf(-t)) + msk[e];
        }
    }
}

// ---------------------------------------------------------------------------
// fp16 HMMA GEMM: BM=128, BN=128, BK=32, 3-stage cp.async, 1 barrier/iter,
// 8 warps (2x4), warp tile 64x32.
// EPI: 0 fp16+bias; 1 fp16+bias+GELU(tanh); 3 fp32+bias+resid;
//      4 fp32+bias + x-residual with window->spatial scatter
// ---------------------------------------------------------------------------
#define STAGES    3
#define TS_STAGE  (128*40)
#define GEMM_SMEM (STAGES*2*TS_STAGE*2)          // 61440 bytes
#define STG_STRIDE 136

template<int EPI>
__global__ void __launch_bounds__(256, 2) hgemm(
    const __half* __restrict__ A, const __half* __restrict__ Wt,
    const float* __restrict__ bias, const float* __restrict__ resid,
    void* __restrict__ Cptr, int M, int Nd, int K)
{
    extern __shared__ __half dyns[];
    __half* Asm = dyns;
    __half* Bsm = dyns + STAGES*TS_STAGE;

    const int tid  = threadIdx.x;
    const int bm   = blockIdx.y * 128;
    const int bn   = blockIdx.x * 128;
    const int wid  = tid >> 5, lane = tid & 31;
    const int wm   = (wid & 1) * 64;
    const int wn   = (wid >> 1) * 32;

    float acc[4][4][4];
#pragma unroll
    for (int mi = 0; mi < 4; mi++)
#pragma unroll
        for (int ni = 0; ni < 4; ni++)
#pragma unroll
            for (int q = 0; q < 4; q++) acc[mi][ni][q] = 0.f;

    const int lr = tid >> 2;
    const int lc = (tid & 3) * 8;
    const int nk = K >> 5;

    auto load_stage = [&](int slot, int kt) {
        __half* As = Asm + slot*TS_STAGE;
        __half* Bs = Bsm + slot*TS_STAGE;
        int k0 = kt << 5;
#pragma unroll
        for (int r = 0; r < 2; r++) {
            int row = lr + 64*r;
            cp_async16(smem_u32(&As[row*40 + lc]), A  + (size_t)(bm+row)*K + k0 + lc);
            cp_async16(smem_u32(&Bs[row*40 + lc]), Wt + (size_t)(bn+row)*K + k0 + lc);
        }
    };

#pragma unroll
    for (int s = 0; s < STAGES-1; s++) {
        if (s < nk) load_stage(s, s);
        asm volatile("cp.async.commit_group;");
    }

    for (int kt = 0; kt < nk; kt++) {
        asm volatile("cp.async.wait_group %0;" :: "n"(STAGES-2));
        __syncthreads();

        int pre = kt + STAGES - 1;
        if (pre < nk) load_stage(pre % STAGES, pre);
        asm volatile("cp.async.commit_group;");

        const __half* As = Asm + (kt % STAGES)*TS_STAGE;
        const __half* Bs = Bsm + (kt % STAGES)*TS_STAGE;

#pragma unroll
        for (int kk = 0; kk < 2; kk++) {
            uint32_t a[4][4], b[4][2];
#pragma unroll
            for (int mi = 0; mi < 4; mi++) {
                int row = wm + mi*16 + (lane & 15);
                int col = kk*16 + ((lane >> 4) << 3);
                LDSM4(a[mi][0], a[mi][1], a[mi][2], a[mi][3],
                      smem_u32(&As[row*40 + col]));
            }
#pragma unroll
            for (int bi = 0; bi < 2; bi++) {
                int n   = wn + bi*16 + ((lane >> 4) << 3) + (lane & 7);
                int col = kk*16 + ((lane >> 3) & 1) * 8;
                uint32_t t0, t1, t2, t3;
                LDSM4(t0, t1, t2, t3, smem_u32(&Bs[n*40 + col]));
                b[bi*2+0][0] = t0; b[bi*2+0][1] = t1;
                b[bi*2+1][0] = t2; b[bi*2+1][1] = t3;
            }
#pragma unroll
            for (int mi = 0; mi < 4; mi++)
#pragma unroll
                for (int ni = 0; ni < 4; ni++)
                    MMA16816(acc[mi][ni], a[mi], b[ni]);
        }
    }

    const int er = lane >> 2, ec = (lane & 3) * 2;

    if (EPI == 0 || EPI == 1) {
        __syncthreads();
        __half* stg = Asm;
#pragma unroll
        for (int mi = 0; mi < 4; mi++) {
#pragma unroll
            for (int ni = 0; ni < 4; ni++) {
                int col = wn + ni*8 + ec;
                float b0 = bias[bn + col], b1 = bias[bn + col + 1];
#pragma unroll
                for (int hh = 0; hh < 2; hh++) {
                    int row = wm + mi*16 + er + hh*8;
                    float v0 = acc[mi][ni][hh*2+0] + b0;
                    float v1 = acc[mi][ni][hh*2+1] + b1;
                    if (EPI == 1) {
                        v0 = gelu_tanh(v0);
                        v1 = gelu_tanh(v1);
                    }
                    *(__half2*)&stg[row*STG_STRIDE + col] = __floats2half2_rn(v0, v1);
                }
            }
        }
        __syncthreads();
#pragma unroll
        for (int i = 0; i < 8; i++) {
            int idx = tid + i*256;
            int row = idx >> 4;
            int u   = idx & 15;
            uint4 v = *(const uint4*)&stg[row*STG_STRIDE + u*8];
            *(uint4*)((__half*)Cptr + (size_t)(bm + row) * Nd + bn + u*8) = v;
        }
    } else if (EPI == 4) {
#pragma unroll
        for (int mi = 0; mi < 4; mi++) {
#pragma unroll
            for (int hh = 0; hh < 2; hh++) {
                int rp  = bm + wm + mi*16 + er + hh*8;
                int win = rp / Nn49, n = rp % Nn49;
                int b   = win >> 6,  wi = win & 63;
                int sh  = (wi >> 3)*WIN + n/WIN;
                int sw  = (wi & 7)*WIN + n%WIN;
                int hs  = sh + SHIFT; if (hs >= Hh)   hs -= Hh;
                int ws  = sw + SHIFT; if (ws >= Wwid) ws -= Wwid;
                size_t srow = ((size_t)b*Hh + hs)*Wwid + ws;
#pragma unroll
                for (int ni = 0; ni < 4; ni++) {
                    int col = bn + wn + ni*8 + ec;
                    const float* xr = resid + srow * Nd + col;
                    float2 f;
                    f.x = acc[mi][ni][hh*2+0] + bias[col] + xr[0];
                    f.y = acc[mi][ni][hh*2+1] + bias[col+1] + xr[1];
                    *(float2*)((float*)Cptr + srow * Nd + col) = f;
                }
            }
        }
    } else {
#pragma unroll
        for (int mi = 0; mi < 4; mi++) {
#pragma unroll
            for (int ni = 0; ni < 4; ni++) {
                int col = bn + wn + ni*8 + ec;
                float b0 = bias[col], b1 = bias[col+1];
#pragma unroll
                for (int hh = 0; hh < 2; hh++) {
                    size_t row = (size_t)(bm + wm + mi*16 + er + hh*8);
                    const float* rr = resid + row * Nd + col;
                    float2 f;
                    f.x = acc[mi][ni][hh*2+0] + b0 + rr[0];
                    f.y = acc[mi][ni][hh*2+1] + b1 + rr[1];
                    *(float2*)((float*)Cptr + row * Nd + col) = f;
                }
            }
        }
    }
}

// ---------------------------------------------------------------------------
// Tensor-core window attention. V kept in natural [j][d] layout; PV B-fragments
// loaded via ldmatrix.trans — no scalar transpose. Zero-fill: vs rows 49-63
// (finite-garbage guard for p=0 cols) and ps cols 56-71 only.
// ---------------------------------------------------------------------------
__global__ void __launch_bounds__(128) attn_kernel(const float* __restrict__ lscale)
{
    const int win = blockIdx.x;
    const int h   = blockIdx.y;
    const int wm  = win & 63;
    const int tid = threadIdx.x;
    const int warp = tid >> 5, lane = tid & 31;

    __shared__ __half qs[64*40];
    __shared__ __half ks[64*40];
    __shared__ __half vs[64*40];   // natural [j][d]
    __shared__ __half ps[64*72];

    {
        uint4 z = make_uint4(0,0,0,0);
        // vs rows 49..63, cols 0..31: 15*4 = 60 uint4 ; ps cols 56..71: 128 uint4
        for (int i = tid; i < 188; i += 128) {
            if (i < 60) {
                int r = 49 + (i >> 2), c = (i & 3) * 8;
                *(uint4*)(vs + r*40 + c) = z;
            } else {
                int k = i - 60;
                int r = k >> 1, c = (k & 1) * 8 + 56;
                *(uint4*)(ps + r*72 + c) = z;
            }
        }
    }
    __syncthreads();

    const __half* base = g_qkv + (size_t)(win*Nn49) * (3*Cc) + h*HD;
    for (int idx = tid; idx < Nn49*4; idx += 128) {
        int row = idx >> 2;
        int c   = (idx & 3) * 8;
        const __half* rb = base + (size_t)row * (3*Cc) + c;
        *(uint4*)(qs + row*40 + c) = *(const uint4*)(rb);
        *(uint4*)(ks + row*40 + c) = *(const uint4*)(rb + Cc);
        *(uint4*)(vs + row*40 + c) = *(const uint4*)(rb + 2*Cc);
    }
    __syncthreads();

    {
        float scale_h = __expf(fminf(lscale[h], 4.6051701859880914f));
        int r = -1; bool isq = false;
        if (tid < Nn49) { r = tid; isq = true; }
        else if (tid >= 64 && tid < 64 + Nn49) { r = tid - 64; }
        if (r >= 0) {
            __half* row = (isq ? qs : ks) + r*40;
            float ss = 0.f;
#pragma unroll
            for (int d = 0; d < HD; d += 2) {
                float2 f = __half22float2(*(__half2*)(row + d));
                ss += f.x*f.x + f.y*f.y;
            }
            float inv = 1.0f / fmaxf(sqrtf(ss), 1e-12f);
            if (isq) inv *= scale_h;
#pragma unroll
            for (int d = 0; d < HD; d += 2) {
                __half2* p = (__half2*)(row + d);
                float2 f = __half22float2(*p);
                *p = __floats2half2_rn(f.x*inv, f.y*inv);
            }
        }
    }
    __syncthreads();

    float s[7][4];
#pragma unroll
    for (int t = 0; t < 7; t++)
#pragma unroll
        for (int c = 0; c < 4; c++) s[t][c] = 0.f;

#pragma unroll
    for (int kk = 0; kk < 2; kk++) {
        uint32_t a[4];
        {
            int row = warp*16 + (lane & 15);
            int col = kk*16 + ((lane >> 4) << 3);
            LDSM4(a[0], a[1], a[2], a[3], smem_u32(qs + row*40 + col));
        }
        uint32_t b[8][2];
#pragma unroll
        for (int bi = 0; bi < 4; bi++) {
            int n   = bi*16 + ((lane >> 4) << 3) + (lane & 7);
            int col = kk*16 + ((lane >> 3) & 1) * 8;
            uint32_t t0, t1, t2, t3;
            LDSM4(t0, t1, t2, t3, smem_u32(ks + n*40 + col));
            b[bi*2+0][0] = t0; b[bi*2+0][1] = t1;
            b[bi*2+1][0] = t2; b[bi*2+1][1] = t3;
        }
#pragma unroll
        for (int t = 0; t < 7; t++)
            MMA16816(s[t], a, b[t]);
    }

    {
        const float* bias = g_bias + ((size_t)wm*HEADS + h) * (Nn49*Nn49);
        int r0 = lane >> 2;
        int i0 = warp*16 + r0;
        int i1 = i0 + 8;
        int jb = (lane & 3) * 2;
#pragma unroll
        for (int t = 0; t < 7; t++) {
#pragma unroll
            for (int c = 0; c < 4; c++) {
                int i = (c >= 2) ? i1 : i0;
                int j = t*8 + jb + (c & 1);
                s[t][c] = (i < Nn49 && j < Nn49) ? s[t][c] + bias[i*Nn49 + j]
                                                 : -1e30f;
            }
        }
        float mx0 = -1e30f, mx1 = -1e30f;
#pragma unroll
        for (int t = 0; t < 7; t++) {
            mx0 = fmaxf(mx0, fmaxf(s[t][0], s[t][1]));
            mx1 = fmaxf(mx1, fmaxf(s[t][2], s[t][3]));
        }
#pragma unroll
        for (int off = 1; off <= 2; off <<= 1) {
            mx0 = fmaxf(mx0, __shfl_xor_sync(0xffffffffu, mx0, off));
            mx1 = fmaxf(mx1, __shfl_xor_sync(0xffffffffu, mx1, off));
        }
        float sm0 = 0.f, sm1 = 0.f;
#pragma unroll
        for (int t = 0; t < 7; t++) {
            s[t][0] = __expf(s[t][0] - mx0); sm0 += s[t][0];
            s[t][1] = __expf(s[t][1] - mx0); sm0 += s[t][1];
            s[t][2] = __expf(s[t][2] - mx1); sm1 += s[t][2];
            s[t][3] = __expf(s[t][3] - mx1); sm1 += s[t][3];
        }
#pragma unroll
        for (int off = 1; off <= 2; off <<= 1) {
            sm0 += __shfl_xor_sync(0xffffffffu, sm0, off);
            sm1 += __shfl_xor_sync(0xffffffffu, sm1, off);
        }
        float inv0 = 1.0f / sm0, inv1 = 1.0f / sm1;
#pragma unroll
        for (int t = 0; t < 7; t++) {
            int j0 = t*8 + jb;
            *(__half2*)(ps + (i0 & 63)*72 + j0) = __floats2half2_rn(s[t][0]*inv0, s[t][1]*inv0);
            *(__half2*)(ps + (i1 & 63)*72 + j0) = __floats2half2_rn(s[t][2]*inv1, s[t][3]*inv1);
        }
    }
    __syncwarp();

    float o[4][4];
#pragma unroll
    for (int t = 0; t < 4; t++)
#pragma unroll
        for (int c = 0; c < 4; c++) o[t][c] = 0.f;

#pragma unroll
    for (int kk = 0; kk < 4; kk++) {
        uint32_t a[4];
        {
            int row = warp*16 + (lane & 15);
            int col = kk*16 + ((lane >> 4) << 3);
            LDSM4(a[0], a[1], a[2], a[3], smem_u32(ps + row*72 + col));
        }
        // B fragments via trans ldmatrix on natural-layout vs[j][d].
        // x4 tiles: t0=(k0,n0) t1=(k0+8,n0) t2=(k0,n0+8) t3=(k0+8,n0+8)
        uint32_t b[4][2];
#pragma unroll
        for (int g = 0; g < 2; g++) {
            int tt   = lane >> 3;                          // tile id 0..3
            int krow = kk*16 + (tt & 1)*8 + (lane & 7);    // j row
            int ncol = g*16 + (tt >> 1)*8;                 // d col
            uint32_t t0, t1, t2, t3;
            LDSM4T(t0, t1, t2, t3, smem_u32(vs + krow*40 + ncol));
            b[g*2+0][0] = t0; b[g*2+0][1] = t1;
            b[g*2+1][0] = t2; b[g*2+1][1] = t3;
        }
#pragma unroll
        for (int t = 0; t < 4; t++)
            MMA16816(o[t], a, b[t]);
    }

    {
        int r0 = lane >> 2;
        int i0 = warp*16 + r0;
        int i1 = i0 + 8;
        int d0 = (lane & 3) * 2;
#pragma unroll
        for (int t = 0; t < 4; t++) {
            int d = t*8 + d0;
            if (i0 < Nn49)
                *(__half2*)(g_o + (size_t)(win*Nn49 + i0)*Cc + h*HD + d) =
                    __floats2half2_rn(o[t][0], o[t][1]);
            if (i1 < Nn49)
                *(__half2*)(g_o + (size_t)(win*Nn49 + i1)*Cc + h*HD + d) =
                    __floats2half2_rn(o[t][2], o[t][3]);
        }
    }
}

// ---------------------------------------------------------------------------
// LN2 on g_x2 -> g_xm (fp16). WARP-PER-TOKEN, 8 tokens/block.
// ---------------------------------------------------------------------------
__global__ void __launch_bounds__(256) ln2_kernel(
    const float* __restrict__ g, const float* __restrict__ bb)
{
    const int warp = threadIdx.x >> 5, lane = threadIdx.x & 31;
    const int t = blockIdx.x * 8 + warp;
    const float4* row = (const float4*)(g_x2 + (size_t)t * Cc);

    float4 v[3];
#pragma unroll
    for (int i = 0; i < 3; i++) v[i] = row[lane + 32*i];

    float s = 0.f, s2 = 0.f;
#pragma unroll
    for (int i = 0; i < 3; i++) {
        s  += v[i].x + v[i].y + v[i].z + v[i].w;
        s2 += v[i].x*v[i].x + v[i].y*v[i].y + v[i].z*v[i].z + v[i].w*v[i].w;
    }
#pragma unroll
    for (int off = 16; off; off >>= 1) {
        s  += __shfl_xor_sync(0xffffffffu, s,  off);
        s2 += __shfl_xor_sync(0xffffffffu, s2, off);
    }
    float mu  = s * (1.f/384.f);
    float var = s2 * (1.f/384.f) - mu*mu;
    float inv = rsqrtf(var + 1e-5f);

    uint2* dst = (uint2*)(g_xm + (size_t)t * Cc);
    const float4* gg = (const float4*)g;
    const float4* bv4 = (const float4*)bb;
#pragma unroll
    for (int i = 0; i < 3; i++) {
        float4 gv = gg[lane + 32*i];
        float4 bv = bv4[lane + 32*i];
        __half2 h0 = __floats2half2_rn((v[i].x - mu)*inv*gv.x + bv.x,
                                       (v[i].y - mu)*inv*gv.y + bv.y);
        __half2 h1 = __floats2half2_rn((v[i].z - mu)*inv*gv.z + bv.z,
                                       (v[i].w - mu)*inv*gv.w + bv.w);
        uint2 u; u.x = *(uint32_t*)&h0; u.y = *(uint32_t*)&h1;
        dst[lane + 32*i] = u;
    }
}

// ---------------------------------------------------------------------------
extern "C" void kernel_launch(void* const* d_in, const int* in_sizes, int n_in,
                              void* d_out, int out_size)
{
    const float* x       = (const float*)d_in[0];
    const float* mask    = (const float*)d_in[1];
    const float* n1g     = (const float*)d_in[2];
    const float* n1b     = (const float*)d_in[3];
    const float* qkv_w   = (const float*)d_in[4];
    const float* qkv_b   = (const float*)d_in[5];
    const float* proj_w  = (const float*)d_in[6];
    const float* proj_b  = (const float*)d_in[7];
    const float* cpb_w1  = (const float*)d_in[8];
    const float* cpb_b1  = (const float*)d_in[9];
    const float* cpb_w2  = (const float*)d_in[10];
    const float* lscale  = (const float*)d_in[11];
    const float* n2g     = (const float*)d_in[12];
    const float* n2b     = (const float*)d_in[13];
    const float* mlp_w1  = (const float*)d_in[14];
    const float* mlp_b1  = (const float*)d_in[15];
    const float* mlp_w2  = (const float*)d_in[16];
    const float* mlp_b2  = (const float*)d_in[17];
    float* out = (float*)d_out;

    __half *a=nullptr, *qkv=nullptr, *o=nullptr, *xm=nullptr, *hidden=nullptr;
    __half *wqkv=nullptr, *wproj=nullptr, *wm1=nullptr, *wm2=nullptr;
    float *x2=nullptr;
    cudaGetSymbolAddress((void**)&a,       g_a);
    cudaGetSymbolAddress((void**)&qkv,     g_qkv);
    cudaGetSymbolAddress((void**)&o,       g_o);
    cudaGetSymbolAddress((void**)&x2,      g_x2);
    cudaGetSymbolAddress((void**)&xm,      g_xm);
    cudaGetSymbolAddress((void**)&hidden,  g_hidden);
    cudaGetSymbolAddress((void**)&wqkv,    g_wqkv);
    cudaGetSymbolAddress((void**)&wproj,   g_wproj);
    cudaGetSymbolAddress((void**)&wm1,     g_wm1);
    cudaGetSymbolAddress((void**)&wm2,     g_wm2);

    cudaFuncSetAttribute(hgemm<0>, cudaFuncAttributeMaxDynamicSharedMemorySize, GEMM_SMEM);
    cudaFuncSetAttribute(hgemm<1>, cudaFuncAttributeMaxDynamicSharedMemorySize, GEMM_SMEM);
    cudaFuncSetAttribute(hgemm<3>, cudaFuncAttributeMaxDynamicSharedMemorySize, GEMM_SMEM);
    cudaFuncSetAttribute(hgemm<4>, cudaFuncAttributeMaxDynamicSharedMemorySize, GEMM_SMEM);

    // 1: weights fp32->fp16 + CPB table (fused grid)
    f2h_cpb<<<F2H_BLOCKS + 169, 256>>>(qkv_w, proj_w, mlp_w1, mlp_w2,
                                       cpb_w1, cpb_b1, cpb_w2);
    // 2: LN1 (warp-per-token) + bias table (fused grid)
    ln1_bias<<<LN1_BLOCKS + NW*HEADS, 256>>>(x, n1g, n1b, mask);
    // 3: QKV GEMM -> fp16
    hgemm<0><<<dim3(9, TOK/128), 256, GEMM_SMEM>>>(a, wqkv, qkv_b, nullptr, qkv, TOK, 3*Cc, Cc);
    // 4: tensor-core window attention (profiled launch slot)
    attn_kernel<<<dim3(NWIN, HEADS), 128>>>(lscale);
    // 5: proj GEMM + x residual + spatial scatter -> g_x2 (fp32)
    hgemm<4><<<dim3(3, TOK/128), 256, GEMM_SMEM>>>(o, wproj, proj_b, x, x2, TOK, Cc, Cc);
    // 6: LN2 (warp-per-token) -> g_xm (fp16)
    ln2_kernel<<<TOK/8, 256>>>(n2g, n2b);
    // 7: MLP1 + GELU -> fp16
    hgemm<1><<<dim3(6, TOK/128), 256, GEMM_SMEM>>>(xm, wm1, mlp_b1, nullptr, hidden, TOK, HIDDEN, Cc);
    // 8: MLP2 + x2 residual -> d_out (fp32)
    hgemm<3><<<dim3(3, TOK/128), 256, GEMM_SMEM>>>(hidden, wm2, mlp_b2, x2, out, TOK, Cc, HIDDEN);
}

// round 15
// speedup vs baseline: 1.1457x; 1.0252x over previous
#include <cuda_runtime.h>
#include <cuda_fp16.h>
#include <cstdint>
#include <math.h>

// ---------------------------------------------------------------------------
// SwinV2 block: B=32, H=W=56, C=384, HEADS=12, WIN=7, SHIFT=3
// ---------------------------------------------------------------------------
#define Bb      32
#define Hh      56
#define Wwid    56
#define Cc      384
#define HEADS   12
#define HD      32
#define WIN     7
#define SHIFT   3
#define Nn49    49
#define NW      64
#define NWIN    (Bb*NW)       // 2048
#define TOK     (NWIN*Nn49)   // 100352
#define HIDDEN  768

// scratch (static device globals)
__device__ __half g_a      [(size_t)TOK * Cc];
__device__ __half g_qkv    [(size_t)TOK * 3 * Cc];
__device__ __half g_o      [(size_t)TOK * Cc];
__device__ float  g_x2     [(size_t)TOK * Cc];      // x + attn residual (spatial)
__device__ __half g_xm     [(size_t)TOK * Cc];
__device__ __half g_hidden [(size_t)TOK * HIDDEN];
__device__ float  g_tab    [169 * HEADS];
__device__ float  g_bias   [(size_t)NW * HEADS * Nn49 * Nn49];
// fp16 weights
__device__ __half g_wqkv [3*Cc*Cc];
__device__ __half g_wproj[Cc*Cc];
__device__ __half g_wm1  [HIDDEN*Cc];
__device__ __half g_wm2  [Cc*HIDDEN];

#define SZ_QKV (3*Cc*Cc)
#define SZ_PRJ (Cc*Cc)
#define SZ_M1  (HIDDEN*Cc)
#define SZ_M2  (Cc*HIDDEN)
#define SZ_ALL (SZ_QKV+SZ_PRJ+SZ_M1+SZ_M2)
#define F2H_BLOCKS ((SZ_ALL + 255)/256)          // 4608
#define LN1_BLOCKS (TOK/8)                        // 12544

// ---------------------------------------------------------------------------
__device__ __forceinline__ uint32_t smem_u32(const void* p) {
    return (uint32_t)__cvta_generic_to_shared(p);
}
__device__ __forceinline__ void cp_async16(uint32_t dst, const void* src) {
    asm volatile("cp.async.cg.shared.global [%0], [%1], 16;" :: "r"(dst), "l"(src));
}

#define LDSM4(r0,r1,r2,r3,addr) \
    asm volatile("ldmatrix.sync.aligned.m8n8.x4.shared.b16 {%0,%1,%2,%3}, [%4];" \
        : "=r"(r0),"=r"(r1),"=r"(r2),"=r"(r3) : "r"(addr))

#define LDSM4T(r0,r1,r2,r3,addr) \
    asm volatile("ldmatrix.sync.aligned.m8n8.x4.trans.shared.b16 {%0,%1,%2,%3}, [%4];" \
        : "=r"(r0),"=r"(r1),"=r"(r2),"=r"(r3) : "r"(addr))

#define MMA16816(c, a, b) \
    asm volatile("mma.sync.aligned.m16n8k16.row.col.f32.f16.f16.f32 " \
        "{%0,%1,%2,%3},{%4,%5,%6,%7},{%8,%9},{%0,%1,%2,%3};" \
        : "+f"(c[0]),"+f"(c[1]),"+f"(c[2]),"+f"(c[3]) \
        : "r"(a[0]),"r"(a[1]),"r"(a[2]),"r"(a[3]),"r"(b[0]),"r"(b[1]))

__device__ __forceinline__ float gelu_tanh(float v) {
    float u = 0.7978845608028654f * (v + 0.044715f * v * v * v);
    float th;
    asm("tanh.approx.f32 %0, %1;" : "=f"(th) : "f"(u));
    return 0.5f * v * (1.0f + th);
}

// ---------------------------------------------------------------------------
// kernel 1: weight conversion fp32->fp16 + CPB table (extra blocks)
// ---------------------------------------------------------------------------
__device__ __forceinline__ float relcoord(int d) {
    float v = 8.0f * (float)d / 6.0f;
    return copysignf(log2f(fabsf(v) + 1.0f) * (1.0f / 3.0f), v);
}

__global__ void __launch_bounds__(256) f2h_cpb(
    const float* __restrict__ w_qkv, const float* __restrict__ w_prj,
    const float* __restrict__ w_m1,  const float* __restrict__ w_m2,
    const float* __restrict__ cw1, const float* __restrict__ cb1,
    const float* __restrict__ cw2)
{
    if (blockIdx.x < F2H_BLOCKS) {
        int i = blockIdx.x * 256 + threadIdx.x;
        if (i < SZ_QKV) {
            g_wqkv[i] = __float2half(w_qkv[i]);
        } else if (i < SZ_QKV + SZ_PRJ) {
            g_wproj[i - SZ_QKV] = __float2half(w_prj[i - SZ_QKV]);
        } else if (i < SZ_QKV + SZ_PRJ + SZ_M1) {
            g_wm1[i - SZ_QKV - SZ_PRJ] = __float2half(w_m1[i - SZ_QKV - SZ_PRJ]);
        } else if (i < SZ_ALL) {
            g_wm2[i - SZ_QKV - SZ_PRJ - SZ_M1] = __float2half(w_m2[i - SZ_QKV - SZ_PRJ - SZ_M1]);
        }
    } else {
        int p  = blockIdx.x - F2H_BLOCKS;
        float r0 = relcoord(p / 13 - 6);
        float r1 = relcoord(p % 13 - 6);
        float acc[HEADS];
#pragma unroll
        for (int h = 0; h < HEADS; h++) acc[h] = 0.f;
        for (int j = threadIdx.x; j < 512; j += 256) {
            float hv = fmaxf(r0 * cw1[j*2] + r1 * cw1[j*2+1] + cb1[j], 0.f);
#pragma unroll
            for (int h = 0; h < HEADS; h++) acc[h] += hv * cw2[h*512 + j];
        }
        __shared__ float red[256];
        for (int h = 0; h < HEADS; h++) {
            red[threadIdx.x] = acc[h];
            __syncthreads();
            for (int s = 128; s > 0; s >>= 1) {
                if (threadIdx.x < s) red[threadIdx.x] += red[threadIdx.x + s];
                __syncthreads();
            }
            if (threadIdx.x == 0) g_tab[p*HEADS + h] = red[0];
            __syncthreads();
        }
    }
}

// ---------------------------------------------------------------------------
// kernel 2: LN1 (warp-per-token) + bias table (extra blocks)
// ---------------------------------------------------------------------------
__global__ void __launch_bounds__(256) ln1_bias(
    const float* __restrict__ x, const float* __restrict__ g,
    const float* __restrict__ bb, const float* __restrict__ mask)
{
    if (blockIdx.x < LN1_BLOCKS) {
        const int warp = threadIdx.x >> 5, lane = threadIdx.x & 31;
        const int t   = blockIdx.x * 8 + warp;
        const int win = t / Nn49, n = t % Nn49;
        const int b   = win >> 6, wi = win & 63;
        const int hh  = ((wi >> 3)*WIN + n/WIN + SHIFT) % Hh;
        const int ww  = ((wi & 7)*WIN + n%WIN + SHIFT) % Wwid;
        const float4* row = (const float4*)(x + (((size_t)b*Hh + hh)*Wwid + ww) * Cc);

        float4 v[3];
#pragma unroll
        for (int i = 0; i < 3; i++) v[i] = row[lane + 32*i];

        float s = 0.f, s2 = 0.f;
#pragma unroll
        for (int i = 0; i < 3; i++) {
            s  += v[i].x + v[i].y + v[i].z + v[i].w;
            s2 += v[i].x*v[i].x + v[i].y*v[i].y + v[i].z*v[i].z + v[i].w*v[i].w;
        }
#pragma unroll
        for (int off = 16; off; off >>= 1) {
            s  += __shfl_xor_sync(0xffffffffu, s,  off);
            s2 += __shfl_xor_sync(0xffffffffu, s2, off);
        }
        float mu  = s * (1.f/384.f);
        float var = s2 * (1.f/384.f) - mu*mu;
        float inv = rsqrtf(var + 1e-5f);

        uint2* dst = (uint2*)(g_a + (size_t)t * Cc);
        const float4* gg = (const float4*)g;
        const float4* bv4 = (const float4*)bb;
#pragma unroll
        for (int i = 0; i < 3; i++) {
            float4 gv = gg[lane + 32*i];
            float4 bv = bv4[lane + 32*i];
            __half2 h0 = __floats2half2_rn((v[i].x - mu)*inv*gv.x + bv.x,
                                           (v[i].y - mu)*inv*gv.y + bv.y);
            __half2 h1 = __floats2half2_rn((v[i].z - mu)*inv*gv.z + bv.z,
                                           (v[i].w - mu)*inv*gv.w + bv.w);
            uint2 u; u.x = *(uint32_t*)&h0; u.y = *(uint32_t*)&h1;
            dst[lane + 32*i] = u;
        }
    } else {
        int idx = blockIdx.x - LN1_BLOCKS;
        int wm = idx & 63, h = idx >> 6;
        float* dst = g_bias + ((size_t)wm*HEADS + h) * (Nn49*Nn49);
        const float* msk = mask + (size_t)wm * (Nn49*Nn49);
        for (int e = threadIdx.x; e < Nn49*Nn49; e += 256) {
            int i = e / Nn49, j = e % Nn49;
            int di = (i/WIN - j/WIN + 6)*13 + (i%WIN - j%WIN + 6);
            float t = g_tab[di*HEADS + h];
            dst[e] = 16.f / (1.f + __expf(-t)) + msk[e];
        }
    }
}

// ---------------------------------------------------------------------------
// fp16 HMMA GEMM: BM=128, BN=128, BK=32, 3-stage cp.async, 1 barrier/iter,
// 8 warps (2x4), warp tile 64x32.
// EPI: 0 fp16+bias; 1 fp16+bias+GELU(tanh); 3 fp32+bias+resid;
//      4 fp32+bias + x-residual with window->spatial scatter
// ---------------------------------------------------------------------------
#define STAGES    3
#define TS_STAGE  (128*40)
#define GEMM_SMEM (STAGES*2*TS_STAGE*2)          // 61440 bytes
#define STG_STRIDE 136

template<int EPI>
__global__ void __launch_bounds__(256, 2) hgemm(
    const __half* __restrict__ A, const __half* __restrict__ Wt,
    const float* __restrict__ bias, const float* __restrict__ resid,
    void* __restrict__ Cptr, int M, int Nd, int K)
{
    extern __shared__ __half dyns[];
    __half* Asm = dyns;
    __half* Bsm = dyns + STAGES*TS_STAGE;

    const int tid  = threadIdx.x;
    const int bm   = blockIdx.y * 128;
    const int bn   = blockIdx.x * 128;
    const int wid  = tid >> 5, lane = tid & 31;
    const int wm   = (wid & 1) * 64;
    const int wn   = (wid >> 1) * 32;

    float acc[4][4][4];
#pragma unroll
    for (int mi = 0; mi < 4; mi++)
#pragma unroll
        for (int ni = 0; ni < 4; ni++)
#pragma unroll
            for (int q = 0; q < 4; q++) acc[mi][ni][q] = 0.f;

    const int lr = tid >> 2;
    const int lc = (tid & 3) * 8;
    const int nk = K >> 5;

    auto load_stage = [&](int slot, int kt) {
        __half* As = Asm + slot*TS_STAGE;
        __half* Bs = Bsm + slot*TS_STAGE;
        int k0 = kt << 5;
#pragma unroll
        for (int r = 0; r < 2; r++) {
            int row = lr + 64*r;
            cp_async16(smem_u32(&As[row*40 + lc]), A  + (size_t)(bm+row)*K + k0 + lc);
            cp_async16(smem_u32(&Bs[row*40 + lc]), Wt + (size_t)(bn+row)*K + k0 + lc);
        }
    };

#pragma unroll
    for (int s = 0; s < STAGES-1; s++) {
        if (s < nk) load_stage(s, s);
        asm volatile("cp.async.commit_group;");
    }

    for (int kt = 0; kt < nk; kt++) {
        asm volatile("cp.async.wait_group %0;" :: "n"(STAGES-2));
        __syncthreads();

        int pre = kt + STAGES - 1;
        if (pre < nk) load_stage(pre % STAGES, pre);
        asm volatile("cp.async.commit_group;");

        const __half* As = Asm + (kt % STAGES)*TS_STAGE;
        const __half* Bs = Bsm + (kt % STAGES)*TS_STAGE;

#pragma unroll
        for (int kk = 0; kk < 2; kk++) {
            uint32_t a[4][4], b[4][2];
#pragma unroll
            for (int mi = 0; mi < 4; mi++) {
                int row = wm + mi*16 + (lane & 15);
                int col = kk*16 + ((lane >> 4) << 3);
                LDSM4(a[mi][0], a[mi][1], a[mi][2], a[mi][3],
                      smem_u32(&As[row*40 + col]));
            }
#pragma unroll
            for (int bi = 0; bi < 2; bi++) {
                int n   = wn + bi*16 + ((lane >> 4) << 3) + (lane & 7);
                int col = kk*16 + ((lane >> 3) & 1) * 8;
                uint32_t t0, t1, t2, t3;
                LDSM4(t0, t1, t2, t3, smem_u32(&Bs[n*40 + col]));
                b[bi*2+0][0] = t0; b[bi*2+0][1] = t1;
                b[bi*2+1][0] = t2; b[bi*2+1][1] = t3;
            }
#pragma unroll
            for (int mi = 0; mi < 4; mi++)
#pragma unroll
                for (int ni = 0; ni < 4; ni++)
                    MMA16816(acc[mi][ni], a[mi], b[ni]);
        }
    }

    const int er = lane >> 2, ec = (lane & 3) * 2;

    if (EPI == 0 || EPI == 1) {
        __syncthreads();
        __half* stg = Asm;
#pragma unroll
        for (int mi = 0; mi < 4; mi++) {
#pragma unroll
            for (int ni = 0; ni < 4; ni++) {
                int col = wn + ni*8 + ec;
                float b0 = bias[bn + col], b1 = bias[bn + col + 1];
#pragma unroll
                for (int hh = 0; hh < 2; hh++) {
                    int row = wm + mi*16 + er + hh*8;
                    float v0 = acc[mi][ni][hh*2+0] + b0;
                    float v1 = acc[mi][ni][hh*2+1] + b1;
                    if (EPI == 1) {
                        v0 = gelu_tanh(v0);
                        v1 = gelu_tanh(v1);
                    }
                    *(__half2*)&stg[row*STG_STRIDE + col] = __floats2half2_rn(v0, v1);
                }
            }
        }
        __syncthreads();
#pragma unroll
        for (int i = 0; i < 8; i++) {
            int idx = tid + i*256;
            int row = idx >> 4;
            int u   = idx & 15;
            uint4 v = *(const uint4*)&stg[row*STG_STRIDE + u*8];
            *(uint4*)((__half*)Cptr + (size_t)(bm + row) * Nd + bn + u*8) = v;
        }
    } else if (EPI == 4) {
#pragma unroll
        for (int mi = 0; mi < 4; mi++) {
#pragma unroll
            for (int hh = 0; hh < 2; hh++) {
                int rp  = bm + wm + mi*16 + er + hh*8;
                int win = rp / Nn49, n = rp % Nn49;
                int b   = win >> 6,  wi = win & 63;
                int sh  = (wi >> 3)*WIN + n/WIN;
                int sw  = (wi & 7)*WIN + n%WIN;
                int hs  = sh + SHIFT; if (hs >= Hh)   hs -= Hh;
                int ws  = sw + SHIFT; if (ws >= Wwid) ws -= Wwid;
                size_t srow = ((size_t)b*Hh + hs)*Wwid + ws;
#pragma unroll
                for (int ni = 0; ni < 4; ni++) {
                    int col = bn + wn + ni*8 + ec;
                    const float* xr = resid + srow * Nd + col;
                    float2 f;
                    f.x = acc[mi][ni][hh*2+0] + bias[col] + xr[0];
                    f.y = acc[mi][ni][hh*2+1] + bias[col+1] + xr[1];
                    *(float2*)((float*)Cptr + srow * Nd + col) = f;
                }
            }
        }
    } else {
#pragma unroll
        for (int mi = 0; mi < 4; mi++) {
#pragma unroll
            for (int ni = 0; ni < 4; ni++) {
                int col = bn + wn + ni*8 + ec;
                float b0 = bias[col], b1 = bias[col+1];
#pragma unroll
                for (int hh = 0; hh < 2; hh++) {
                    size_t row = (size_t)(bm + wm + mi*16 + er + hh*8);
                    const float* rr = resid + row * Nd + col;
                    float2 f;
                    f.x = acc[mi][ni][hh*2+0] + b0 + rr[0];
                    f.y = acc[mi][ni][hh*2+1] + b1 + rr[1];
                    *(float2*)((float*)Cptr + row * Nd + col) = f;
                }
            }
        }
    }
}

// ---------------------------------------------------------------------------
// Tensor-core window attention. smem 15.4KB: ps aliases the qs+ks region
// (dead after the S-MMA; a block barrier separates the phases).
// __launch_bounds__(128, 10) lifts occupancy to 10 blocks/SM.
// ---------------------------------------------------------------------------
#define SM_QS 0            // 64*40 halves
#define SM_KS (64*40)      // 64*40 halves
#define SM_VS (2*64*40)    // 64*40 halves
#define SM_PS 0            // 64*72 = 4608 halves, overlays qs+ks (5120)
#define ATTN_SMEM (3*64*40)

__global__ void __launch_bounds__(128, 10) attn_kernel(const float* __restrict__ lscale)
{
    const int win = blockIdx.x;
    const int h   = blockIdx.y;
    const int wm  = win & 63;
    const int tid = threadIdx.x;
    const int warp = tid >> 5, lane = tid & 31;

    __shared__ __half sbuf[ATTN_SMEM];
    __half* qs = sbuf + SM_QS;
    __half* ks = sbuf + SM_KS;
    __half* vs = sbuf + SM_VS;
    __half* ps = sbuf + SM_PS;

    // zero vs rows 49..63 (cols 0..31): 60 uint4
    {
        uint4 z = make_uint4(0,0,0,0);
        if (tid < 60) {
            int r = 49 + (tid >> 2), c = (tid & 3) * 8;
            *(uint4*)(vs + r*40 + c) = z;
        }
    }

    const __half* base = g_qkv + (size_t)(win*Nn49) * (3*Cc) + h*HD;
    for (int idx = tid; idx < Nn49*4; idx += 128) {
        int row = idx >> 2;
        int c   = (idx & 3) * 8;
        const __half* rb = base + (size_t)row * (3*Cc) + c;
        *(uint4*)(qs + row*40 + c) = *(const uint4*)(rb);
        *(uint4*)(ks + row*40 + c) = *(const uint4*)(rb + Cc);
        *(uint4*)(vs + row*40 + c) = *(const uint4*)(rb + 2*Cc);
    }
    __syncthreads();

    {
        float scale_h = __expf(fminf(lscale[h], 4.6051701859880914f));
        int r = -1; bool isq = false;
        if (tid < Nn49) { r = tid; isq = true; }
        else if (tid >= 64 && tid < 64 + Nn49) { r = tid - 64; }
        if (r >= 0) {
            __half* row = (isq ? qs : ks) + r*40;
            float ss = 0.f;
#pragma unroll
            for (int d = 0; d < HD; d += 2) {
                float2 f = __half22float2(*(__half2*)(row + d));
                ss += f.x*f.x + f.y*f.y;
            }
            float inv = 1.0f / fmaxf(sqrtf(ss), 1e-12f);
            if (isq) inv *= scale_h;
#pragma unroll
            for (int d = 0; d < HD; d += 2) {
                __half2* p = (__half2*)(row + d);
                float2 f = __half22float2(*p);
                *p = __floats2half2_rn(f.x*inv, f.y*inv);
            }
        }
    }
    __syncthreads();

    float s[7][4];
#pragma unroll
    for (int t = 0; t < 7; t++)
#pragma unroll
        for (int c = 0; c < 4; c++) s[t][c] = 0.f;

#pragma unroll
    for (int kk = 0; kk < 2; kk++) {
        uint32_t a[4];
        {
            int row = warp*16 + (lane & 15);
            int col = kk*16 + ((lane >> 4) << 3);
            LDSM4(a[0], a[1], a[2], a[3], smem_u32(qs + row*40 + col));
        }
        uint32_t b[8][2];
#pragma unroll
        for (int bi = 0; bi < 4; bi++) {
            int n   = bi*16 + ((lane >> 4) << 3) + (lane & 7);
            int col = kk*16 + ((lane >> 3) & 1) * 8;
            uint32_t t0, t1, t2, t3;
            LDSM4(t0, t1, t2, t3, smem_u32(ks + n*40 + col));
            b[bi*2+0][0] = t0; b[bi*2+0][1] = t1;
            b[bi*2+1][0] = t2; b[bi*2+1][1] = t3;
        }
#pragma unroll
        for (int t = 0; t < 7; t++)
            MMA16816(s[t], a, b[t]);
    }

    // qs/ks fully consumed (fragments in registers) -> ps may overwrite them
    __syncthreads();

    {
        const float* bias = g_bias + ((size_t)wm*HEADS + h) * (Nn49*Nn49);
        int r0 = lane >> 2;
        int i0 = warp*16 + r0;
        int i1 = i0 + 8;
        int jb = (lane & 3) * 2;

        // zero own band's ps cols 56..71 (2 uint4 per row, 16 rows, 32 lanes)
        {
            uint4 z = make_uint4(0,0,0,0);
            int r = warp*16 + (lane >> 1);
            int c = (lane & 1) * 8 + 56;
            *(uint4*)(ps + r*72 + c) = z;
        }

#pragma unroll
        for (int t = 0; t < 7; t++) {
#pragma unroll
            for (int c = 0; c < 4; c++) {
                int i = (c >= 2) ? i1 : i0;
                int j = t*8 + jb + (c & 1);
                s[t][c] = (i < Nn49 && j < Nn49) ? s[t][c] + bias[i*Nn49 + j]
                                                 : -1e30f;
            }
        }
        float mx0 = -1e30f, mx1 = -1e30f;
#pragma unroll
        for (int t = 0; t < 7; t++) {
            mx0 = fmaxf(mx0, fmaxf(s[t][0], s[t][1]));
            mx1 = fmaxf(mx1, fmaxf(s[t][2], s[t][3]));
        }
#pragma unroll
        for (int off = 1; off <= 2; off <<= 1) {
            mx0 = fmaxf(mx0, __shfl_xor_sync(0xffffffffu, mx0, off));
            mx1 = fmaxf(mx1, __shfl_xor_sync(0xffffffffu, mx1, off));
        }
        float sm0 = 0.f, sm1 = 0.f;
#pragma unroll
        for (int t = 0; t < 7; t++) {
            s[t][0] = __expf(s[t][0] - mx0); sm0 += s[t][0];
            s[t][1] = __expf(s[t][1] - mx0); sm0 += s[t][1];
            s[t][2] = __expf(s[t][2] - mx1); sm1 += s[t][2];
            s[t][3] = __expf(s[t][3] - mx1); sm1 += s[t][3];
        }
#pragma unroll
        for (int off = 1; off <= 2; off <<= 1) {
            sm0 += __shfl_xor_sync(0xffffffffu, sm0, off);
            sm1 += __shfl_xor_sync(0xffffffffu, sm1, off);
        }
        float inv0 = 1.0f / sm0, inv1 = 1.0f / sm1;
#pragma unroll
        for (int t = 0; t < 7; t++) {
            int j0 = t*8 + jb;
            *(__half2*)(ps + (i0 & 63)*72 + j0) = __floats2half2_rn(s[t][0]*inv0, s[t][1]*inv0);
            *(__half2*)(ps + (i1 & 63)*72 + j0) = __floats2half2_rn(s[t][2]*inv1, s[t][3]*inv1);
        }
    }
    __syncwarp();   // ps rows are warp-private; PV reads only own band

    float o[4][4];
#pragma unroll
    for (int t = 0; t < 4; t++)
#pragma unroll
        for (int c = 0; c < 4; c++) o[t][c] = 0.f;

#pragma unroll
    for (int kk = 0; kk < 4; kk++) {
        uint32_t a[4];
        {
            int row = warp*16 + (lane & 15);
            int col = kk*16 + ((lane >> 4) << 3);
            LDSM4(a[0], a[1], a[2], a[3], smem_u32(ps + row*72 + col));
        }
        uint32_t b[4][2];
#pragma unroll
        for (int g = 0; g < 2; g++) {
            int tt   = lane >> 3;
            int krow = kk*16 + (tt & 1)*8 + (lane & 7);
            int ncol = g*16 + (tt >> 1)*8;
            uint32_t t0, t1, t2, t3;
            LDSM4T(t0, t1, t2, t3, smem_u32(vs + krow*40 + ncol));
            b[g*2+0][0] = t0; b[g*2+0][1] = t1;
            b[g*2+1][0] = t2; b[g*2+1][1] = t3;
        }
#pragma unroll
        for (int t = 0; t < 4; t++)
            MMA16816(o[t], a, b[t]);
    }

    {
        int r0 = lane >> 2;
        int i0 = warp*16 + r0;
        int i1 = i0 + 8;
        int d0 = (lane & 3) * 2;
#pragma unroll
        for (int t = 0; t < 4; t++) {
            int d = t*8 + d0;
            if (i0 < Nn49)
                *(__half2*)(g_o + (size_t)(win*Nn49 + i0)*Cc + h*HD + d) =
                    __floats2half2_rn(o[t][0], o[t][1]);
            if (i1 < Nn49)
                *(__half2*)(g_o + (size_t)(win*Nn49 + i1)*Cc + h*HD + d) =
                    __floats2half2_rn(o[t][2], o[t][3]);
        }
    }
}

// ---------------------------------------------------------------------------
// LN2 on g_x2 -> g_xm (fp16). WARP-PER-TOKEN, 8 tokens/block.
// ---------------------------------------------------------------------------
__global__ void __launch_bounds__(256) ln2_kernel(
    const float* __restrict__ g, const float* __restrict__ bb)
{
    const int warp = threadIdx.x >> 5, lane = threadIdx.x & 31;
    const int t = blockIdx.x * 8 + warp;
    const float4* row = (const float4*)(g_x2 + (size_t)t * Cc);

    float4 v[3];
#pragma unroll
    for (int i = 0; i < 3; i++) v[i] = row[lane + 32*i];

    float s = 0.f, s2 = 0.f;
#pragma unroll
    for (int i = 0; i < 3; i++) {
        s  += v[i].x + v[i].y + v[i].z + v[i].w;
        s2 += v[i].x*v[i].x + v[i].y*v[i].y + v[i].z*v[i].z + v[i].w*v[i].w;
    }
#pragma unroll
    for (int off = 16; off; off >>= 1) {
        s  += __shfl_xor_sync(0xffffffffu, s,  off);
        s2 += __shfl_xor_sync(0xffffffffu, s2, off);
    }
    float mu  = s * (1.f/384.f);
    float var = s2 * (1.f/384.f) - mu*mu;
    float inv = rsqrtf(var + 1e-5f);

    uint2* dst = (uint2*)(g_xm + (size_t)t * Cc);
    const float4* gg = (const float4*)g;
    const float4* bv4 = (const float4*)bb;
#pragma unroll
    for (int i = 0; i < 3; i++) {
        float4 gv = gg[lane + 32*i];
        float4 bv = bv4[lane + 32*i];
        __half2 h0 = __floats2half2_rn((v[i].x - mu)*inv*gv.x + bv.x,
                                       (v[i].y - mu)*inv*gv.y + bv.y);
        __half2 h1 = __floats2half2_rn((v[i].z - mu)*inv*gv.z + bv.z,
                                       (v[i].w - mu)*inv*gv.w + bv.w);
        uint2 u; u.x = *(uint32_t*)&h0; u.y = *(uint32_t*)&h1;
        dst[lane + 32*i] = u;
    }
}

// ---------------------------------------------------------------------------
extern "C" void kernel_launch(void* const* d_in, const int* in_sizes, int n_in,
                              void* d_out, int out_size)
{
    const float* x       = (const float*)d_in[0];
    const float* mask    = (const float*)d_in[1];
    const float* n1g     = (const float*)d_in[2];
    const float* n1b     = (const float*)d_in[3];
    const float* qkv_w   = (const float*)d_in[4];
    const float* qkv_b   = (const float*)d_in[5];
    const float* proj_w  = (const float*)d_in[6];
    const float* proj_b  = (const float*)d_in[7];
    const float* cpb_w1  = (const float*)d_in[8];
    const float* cpb_b1  = (const float*)d_in[9];
    const float* cpb_w2  = (const float*)d_in[10];
    const float* lscale  = (const float*)d_in[11];
    const float* n2g     = (const float*)d_in[12];
    const float* n2b     = (const float*)d_in[13];
    const float* mlp_w1  = (const float*)d_in[14];
    const float* mlp_b1  = (const float*)d_in[15];
    const float* mlp_w2  = (const float*)d_in[16];
    const float* mlp_b2  = (const float*)d_in[17];
    float* out = (float*)d_out;

    __half *a=nullptr, *qkv=nullptr, *o=nullptr, *xm=nullptr, *hidden=nullptr;
    __half *wqkv=nullptr, *wproj=nullptr, *wm1=nullptr, *wm2=nullptr;
    float *x2=nullptr;
    cudaGetSymbolAddress((void**)&a,       g_a);
    cudaGetSymbolAddress((void**)&qkv,     g_qkv);
    cudaGetSymbolAddress((void**)&o,       g_o);
    cudaGetSymbolAddress((void**)&x2,      g_x2);
    cudaGetSymbolAddress((void**)&xm,      g_xm);
    cudaGetSymbolAddress((void**)&hidden,  g_hidden);
    cudaGetSymbolAddress((void**)&wqkv,    g_wqkv);
    cudaGetSymbolAddress((void**)&wproj,   g_wproj);
    cudaGetSymbolAddress((void**)&wm1,     g_wm1);
    cudaGetSymbolAddress((void**)&wm2,     g_wm2);

    cudaFuncSetAttribute(hgemm<0>, cudaFuncAttributeMaxDynamicSharedMemorySize, GEMM_SMEM);
    cudaFuncSetAttribute(hgemm<1>, cudaFuncAttributeMaxDynamicSharedMemorySize, GEMM_SMEM);
    cudaFuncSetAttribute(hgemm<3>, cudaFuncAttributeMaxDynamicSharedMemorySize, GEMM_SMEM);
    cudaFuncSetAttribute(hgemm<4>, cudaFuncAttributeMaxDynamicSharedMemorySize, GEMM_SMEM);

    // 1: weights fp32->fp16 + CPB table (fused grid)
    f2h_cpb<<<F2H_BLOCKS + 169, 256>>>(qkv_w, proj_w, mlp_w1, mlp_w2,
                                       cpb_w1, cpb_b1, cpb_w2);
    // 2: LN1 (warp-per-token) + bias table (fused grid)
    ln1_bias<<<LN1_BLOCKS + NW*HEADS, 256>>>(x, n1g, n1b, mask);
    // 3: QKV GEMM -> fp16
    hgemm<0><<<dim3(9, TOK/128), 256, GEMM_SMEM>>>(a, wqkv, qkv_b, nullptr, qkv, TOK, 3*Cc, Cc);
    // 4: tensor-core window attention (profiled launch slot)
    attn_kernel<<<dim3(NWIN, HEADS), 128>>>(lscale);
    // 5: proj GEMM + x residual + spatial scatter -> g_x2 (fp32)
    hgemm<4><<<dim3(3, TOK/128), 256, GEMM_SMEM>>>(o, wproj, proj_b, x, x2, TOK, Cc, Cc);
    // 6: LN2 (warp-per-token) -> g_xm (fp16)
    ln2_kernel<<<TOK/8, 256>>>(n2g, n2b);
    // 7: MLP1 + GELU -> fp16
    hgemm<1><<<dim3(6, TOK/128), 256, GEMM_SMEM>>>(xm, wm1, mlp_b1, nullptr, hidden, TOK, HIDDEN, Cc);
    // 8: MLP2 + x2 residual -> d_out (fp32)
    hgemm<3><<<dim3(3, TOK/128), 256, GEMM_SMEM>>>(hidden, wm2, mlp_b2, x2, out, TOK, Cc, HIDDEN);
}

// round 16
// speedup vs baseline: 1.1644x; 1.0163x over previous
#include <cuda_runtime.h>
#include <cuda_fp16.h>
#include <cstdint>
#include <math.h>

// ---------------------------------------------------------------------------
// SwinV2 block: B=32, H=W=56, C=384, HEADS=12, WIN=7, SHIFT=3
// ---------------------------------------------------------------------------
#define Bb      32
#define Hh      56
#define Wwid    56
#define Cc      384
#define HEADS   12
#define HD      32
#define WIN     7
#define SHIFT   3
#define Nn49    49
#define NW      64
#define NWIN    (Bb*NW)       // 2048
#define TOK     (NWIN*Nn49)   // 100352
#define HIDDEN  768
#define BSTRIDE 56            // fp16 bias row stride (even -> half2 aligned)

// scratch (static device globals)
__device__ __half g_a      [(size_t)TOK * Cc];
__device__ __half g_qkv    [(size_t)TOK * 3 * Cc];
__device__ __half g_o      [(size_t)TOK * Cc];
__device__ float  g_x2     [(size_t)TOK * Cc];
__device__ __half g_xm     [(size_t)TOK * Cc];
__device__ __half g_hidden [(size_t)TOK * HIDDEN];
__device__ float  g_tab    [169 * HEADS];
__device__ __half g_biash  [(size_t)NW * HEADS * Nn49 * BSTRIDE + 4096];
// fp16 weights
__device__ __half g_wqkv [3*Cc*Cc];
__device__ __half g_wproj[Cc*Cc];
__device__ __half g_wm1  [HIDDEN*Cc];
__device__ __half g_wm2  [Cc*HIDDEN];

#define SZ_QKV (3*Cc*Cc)
#define SZ_PRJ (Cc*Cc)
#define SZ_M1  (HIDDEN*Cc)
#define SZ_M2  (Cc*HIDDEN)
#define SZ_ALL (SZ_QKV+SZ_PRJ+SZ_M1+SZ_M2)
#define F2H_BLOCKS ((SZ_ALL + 255)/256)          // 4608
#define LN1_BLOCKS (TOK/8)                        // 12544

// ---------------------------------------------------------------------------
__device__ __forceinline__ uint32_t smem_u32(const void* p) {
    return (uint32_t)__cvta_generic_to_shared(p);
}
__device__ __forceinline__ void cp_async16(uint32_t dst, const void* src) {
    asm volatile("cp.async.cg.shared.global [%0], [%1], 16;" :: "r"(dst), "l"(src));
}

#define LDSM4(r0,r1,r2,r3,addr) \
    asm volatile("ldmatrix.sync.aligned.m8n8.x4.shared.b16 {%0,%1,%2,%3}, [%4];" \
        : "=r"(r0),"=r"(r1),"=r"(r2),"=r"(r3) : "r"(addr))

#define LDSM4T(r0,r1,r2,r3,addr) \
    asm volatile("ldmatrix.sync.aligned.m8n8.x4.trans.shared.b16 {%0,%1,%2,%3}, [%4];" \
        : "=r"(r0),"=r"(r1),"=r"(r2),"=r"(r3) : "r"(addr))

#define MMA16816(c, a, b) \
    asm volatile("mma.sync.aligned.m16n8k16.row.col.f32.f16.f16.f32 " \
        "{%0,%1,%2,%3},{%4,%5,%6,%7},{%8,%9},{%0,%1,%2,%3};" \
        : "+f"(c[0]),"+f"(c[1]),"+f"(c[2]),"+f"(c[3]) \
        : "r"(a[0]),"r"(a[1]),"r"(a[2]),"r"(a[3]),"r"(b[0]),"r"(b[1]))

__device__ __forceinline__ float gelu_tanh(float v) {
    float u = 0.7978845608028654f * (v + 0.044715f * v * v * v);
    float th;
    asm("tanh.approx.f32 %0, %1;" : "=f"(th) : "f"(u));
    return 0.5f * v * (1.0f + th);
}

// ---------------------------------------------------------------------------
// kernel 1: weight conversion fp32->fp16 + CPB table (extra blocks)
// ---------------------------------------------------------------------------
__device__ __forceinline__ float relcoord(int d) {
    float v = 8.0f * (float)d / 6.0f;
    return copysignf(log2f(fabsf(v) + 1.0f) * (1.0f / 3.0f), v);
}

__global__ void __launch_bounds__(256) f2h_cpb(
    const float* __restrict__ w_qkv, const float* __restrict__ w_prj,
    const float* __restrict__ w_m1,  const float* __restrict__ w_m2,
    const float* __restrict__ cw1, const float* __restrict__ cb1,
    const float* __restrict__ cw2)
{
    if (blockIdx.x < F2H_BLOCKS) {
        int i = blockIdx.x * 256 + threadIdx.x;
        if (i < SZ_QKV) {
            g_wqkv[i] = __float2half(w_qkv[i]);
        } else if (i < SZ_QKV + SZ_PRJ) {
            g_wproj[i - SZ_QKV] = __float2half(w_prj[i - SZ_QKV]);
        } else if (i < SZ_QKV + SZ_PRJ + SZ_M1) {
            g_wm1[i - SZ_QKV - SZ_PRJ] = __float2half(w_m1[i - SZ_QKV - SZ_PRJ]);
        } else if (i < SZ_ALL) {
            g_wm2[i - SZ_QKV - SZ_PRJ - SZ_M1] = __float2half(w_m2[i - SZ_QKV - SZ_PRJ - SZ_M1]);
        }
    } else {
        int p  = blockIdx.x - F2H_BLOCKS;
        float r0 = relcoord(p / 13 - 6);
        float r1 = relcoord(p % 13 - 6);
        float acc[HEADS];
#pragma unroll
        for (int h = 0; h < HEADS; h++) acc[h] = 0.f;
        for (int j = threadIdx.x; j < 512; j += 256) {
            float hv = fmaxf(r0 * cw1[j*2] + r1 * cw1[j*2+1] + cb1[j], 0.f);
#pragma unroll
            for (int h = 0; h < HEADS; h++) acc[h] += hv * cw2[h*512 + j];
        }
        __shared__ float red[256];
        for (int h = 0; h < HEADS; h++) {
            red[threadIdx.x] = acc[h];
            __syncthreads();
            for (int s = 128; s > 0; s >>= 1) {
                if (threadIdx.x < s) red[threadIdx.x] += red[threadIdx.x + s];
                __syncthreads();
            }
            if (threadIdx.x == 0) g_tab[p*HEADS + h] = red[0];
            __syncthreads();
        }
    }
}

// ---------------------------------------------------------------------------
// kernel 2: LN1 (warp-per-token) + fp16 bias table (extra blocks)
// ---------------------------------------------------------------------------
__global__ void __launch_bounds__(256) ln1_bias(
    const float* __restrict__ x, const float* __restrict__ g,
    const float* __restrict__ bb, const float* __restrict__ mask)
{
    if (blockIdx.x < LN1_BLOCKS) {
        const int warp = threadIdx.x >> 5, lane = threadIdx.x & 31;
        const int t   = blockIdx.x * 8 + warp;
        const int win = t / Nn49, n = t % Nn49;
        const int b   = win >> 6, wi = win & 63;
        const int hh  = ((wi >> 3)*WIN + n/WIN + SHIFT) % Hh;
        const int ww  = ((wi & 7)*WIN + n%WIN + SHIFT) % Wwid;
        const float4* row = (const float4*)(x + (((size_t)b*Hh + hh)*Wwid + ww) * Cc);

        float4 v[3];
#pragma unroll
        for (int i = 0; i < 3; i++) v[i] = row[lane + 32*i];

        float s = 0.f, s2 = 0.f;
#pragma unroll
        for (int i = 0; i < 3; i++) {
            s  += v[i].x + v[i].y + v[i].z + v[i].w;
            s2 += v[i].x*v[i].x + v[i].y*v[i].y + v[i].z*v[i].z + v[i].w*v[i].w;
        }
#pragma unroll
        for (int off = 16; off; off >>= 1) {
            s  += __shfl_xor_sync(0xffffffffu, s,  off);
            s2 += __shfl_xor_sync(0xffffffffu, s2, off);
        }
        float mu  = s * (1.f/384.f);
        float var = s2 * (1.f/384.f) - mu*mu;
        float inv = rsqrtf(var + 1e-5f);

        uint2* dst = (uint2*)(g_a + (size_t)t * Cc);
        const float4* gg = (const float4*)g;
        const float4* bv4 = (const float4*)bb;
#pragma unroll
        for (int i = 0; i < 3; i++) {
            float4 gv = gg[lane + 32*i];
            float4 bv = bv4[lane + 32*i];
            __half2 h0 = __floats2half2_rn((v[i].x - mu)*inv*gv.x + bv.x,
                                           (v[i].y - mu)*inv*gv.y + bv.y);
            __half2 h1 = __floats2half2_rn((v[i].z - mu)*inv*gv.z + bv.z,
                                           (v[i].w - mu)*inv*gv.w + bv.w);
            uint2 u; u.x = *(uint32_t*)&h0; u.y = *(uint32_t*)&h1;
            dst[lane + 32*i] = u;
        }
    } else {
        int idx = blockIdx.x - LN1_BLOCKS;
        int wm = idx & 63, h = idx >> 6;
        __half* dst = g_biash + ((size_t)wm*HEADS + h) * (Nn49*BSTRIDE);
        const float* msk = mask + (size_t)wm * (Nn49*Nn49);
        for (int e = threadIdx.x; e < Nn49*Nn49; e += 256) {
            int i = e / Nn49, j = e % Nn49;
            int di = (i/WIN - j/WIN + 6)*13 + (i%WIN - j%WIN + 6);
            float t = g_tab[di*HEADS + h];
            dst[i*BSTRIDE + j] = __float2half(16.f / (1.f + __expf(-t)) + msk[e]);
        }
    }
}

// ---------------------------------------------------------------------------
// fp16 HMMA GEMM: BM=128, BN=128, BK=32, 3-stage cp.async, 1 barrier/iter,
// 8 warps (2x4), warp tile 64x32.
// EPI: 0 fp16+bias; 1 fp16+bias+GELU(tanh); 3 fp32+bias+resid;
//      4 fp32+bias + x-residual with window->spatial scatter
// ---------------------------------------------------------------------------
#define STAGES    3
#define TS_STAGE  (128*40)
#define GEMM_SMEM (STAGES*2*TS_STAGE*2)          // 61440 bytes
#define STG_STRIDE 136

template<int EPI>
__global__ void __launch_bounds__(256, 2) hgemm(
    const __half* __restrict__ A, const __half* __restrict__ Wt,
    const float* __restrict__ bias, const float* __restrict__ resid,
    void* __restrict__ Cptr, int M, int Nd, int K)
{
    extern __shared__ __half dyns[];
    __half* Asm = dyns;
    __half* Bsm = dyns + STAGES*TS_STAGE;

    const int tid  = threadIdx.x;
    const int bm   = blockIdx.y * 128;
    const int bn   = blockIdx.x * 128;
    const int wid  = tid >> 5, lane = tid & 31;
    const int wm   = (wid & 1) * 64;
    const int wn   = (wid >> 1) * 32;

    float acc[4][4][4];
#pragma unroll
    for (int mi = 0; mi < 4; mi++)
#pragma unroll
        for (int ni = 0; ni < 4; ni++)
#pragma unroll
            for (int q = 0; q < 4; q++) acc[mi][ni][q] = 0.f;

    const int lr = tid >> 2;
    const int lc = (tid & 3) * 8;
    const int nk = K >> 5;

    auto load_stage = [&](int slot, int kt) {
        __half* As = Asm + slot*TS_STAGE;
        __half* Bs = Bsm + slot*TS_STAGE;
        int k0 = kt << 5;
#pragma unroll
        for (int r = 0; r < 2; r++) {
            int row = lr + 64*r;
            cp_async16(smem_u32(&As[row*40 + lc]), A  + (size_t)(bm+row)*K + k0 + lc);
            cp_async16(smem_u32(&Bs[row*40 + lc]), Wt + (size_t)(bn+row)*K + k0 + lc);
        }
    };

#pragma unroll
    for (int s = 0; s < STAGES-1; s++) {
        if (s < nk) load_stage(s, s);
        asm volatile("cp.async.commit_group;");
    }

    for (int kt = 0; kt < nk; kt++) {
        asm volatile("cp.async.wait_group %0;" :: "n"(STAGES-2));
        __syncthreads();

        int pre = kt + STAGES - 1;
        if (pre < nk) load_stage(pre % STAGES, pre);
        asm volatile("cp.async.commit_group;");

        const __half* As = Asm + (kt % STAGES)*TS_STAGE;
        const __half* Bs = Bsm + (kt % STAGES)*TS_STAGE;

#pragma unroll
        for (int kk = 0; kk < 2; kk++) {
            uint32_t a[4][4], b[4][2];
#pragma unroll
            for (int mi = 0; mi < 4; mi++) {
                int row = wm + mi*16 + (lane & 15);
                int col = kk*16 + ((lane >> 4) << 3);
                LDSM4(a[mi][0], a[mi][1], a[mi][2], a[mi][3],
                      smem_u32(&As[row*40 + col]));
            }
#pragma unroll
            for (int bi = 0; bi < 2; bi++) {
                int n   = wn + bi*16 + ((lane >> 4) << 3) + (lane & 7);
                int col = kk*16 + ((lane >> 3) & 1) * 8;
                uint32_t t0, t1, t2, t3;
                LDSM4(t0, t1, t2, t3, smem_u32(&Bs[n*40 + col]));
                b[bi*2+0][0] = t0; b[bi*2+0][1] = t1;
                b[bi*2+1][0] = t2; b[bi*2+1][1] = t3;
            }
#pragma unroll
            for (int mi = 0; mi < 4; mi++)
#pragma unroll
                for (int ni = 0; ni < 4; ni++)
                    MMA16816(acc[mi][ni], a[mi], b[ni]);
        }
    }

    const int er = lane >> 2, ec = (lane & 3) * 2;

    if (EPI == 0 || EPI == 1) {
        __syncthreads();
        __half* stg = Asm;
#pragma unroll
        for (int mi = 0; mi < 4; mi++) {
#pragma unroll
            for (int ni = 0; ni < 4; ni++) {
                int col = wn + ni*8 + ec;
                float b0 = bias[bn + col], b1 = bias[bn + col + 1];
#pragma unroll
                for (int hh = 0; hh < 2; hh++) {
                    int row = wm + mi*16 + er + hh*8;
                    float v0 = acc[mi][ni][hh*2+0] + b0;
                    float v1 = acc[mi][ni][hh*2+1] + b1;
                    if (EPI == 1) {
                        v0 = gelu_tanh(v0);
                        v1 = gelu_tanh(v1);
                    }
                    *(__half2*)&stg[row*STG_STRIDE + col] = __floats2half2_rn(v0, v1);
                }
            }
        }
        __syncthreads();
#pragma unroll
        for (int i = 0; i < 8; i++) {
            int idx = tid + i*256;
            int row = idx >> 4;
            int u   = idx & 15;
            uint4 v = *(const uint4*)&stg[row*STG_STRIDE + u*8];
            *(uint4*)((__half*)Cptr + (size_t)(bm + row) * Nd + bn + u*8) = v;
        }
    } else if (EPI == 4) {
#pragma unroll
        for (int mi = 0; mi < 4; mi++) {
#pragma unroll
            for (int hh = 0; hh < 2; hh++) {
                int rp  = bm + wm + mi*16 + er + hh*8;
                int win = rp / Nn49, n = rp % Nn49;
                int b   = win >> 6,  wi = win & 63;
                int sh  = (wi >> 3)*WIN + n/WIN;
                int sw  = (wi & 7)*WIN + n%WIN;
                int hs  = sh + SHIFT; if (hs >= Hh)   hs -= Hh;
                int ws  = sw + SHIFT; if (ws >= Wwid) ws -= Wwid;
                size_t srow = ((size_t)b*Hh + hs)*Wwid + ws;
#pragma unroll
                for (int ni = 0; ni < 4; ni++) {
                    int col = bn + wn + ni*8 + ec;
                    const float* xr = resid + srow * Nd + col;
                    float2 f;
                    f.x = acc[mi][ni][hh*2+0] + bias[col] + xr[0];
                    f.y = acc[mi][ni][hh*2+1] + bias[col+1] + xr[1];
                    *(float2*)((float*)Cptr + srow * Nd + col) = f;
                }
            }
        }
    } else {
#pragma unroll
        for (int mi = 0; mi < 4; mi++) {
#pragma unroll
            for (int ni = 0; ni < 4; ni++) {
                int col = bn + wn + ni*8 + ec;
                float b0 = bias[col], b1 = bias[col+1];
#pragma unroll
                for (int hh = 0; hh < 2; hh++) {
                    size_t row = (size_t)(bm + wm + mi*16 + er + hh*8);
                    const float* rr = resid + row * Nd + col;
                    float2 f;
                    f.x = acc[mi][ni][hh*2+0] + b0 + rr[0];
                    f.y = acc[mi][ni][hh*2+1] + b1 + rr[1];
                    *(float2*)((float*)Cptr + row * Nd + col) = f;
                }
            }
        }
    }
}

// ---------------------------------------------------------------------------
// Tensor-core window attention. smem 15.4KB (ps aliases qs+ks), occ 10 blocks,
// fp16 bias table with half2 loads.
// ---------------------------------------------------------------------------
#define SM_QS 0
#define SM_KS (64*40)
#define SM_VS (2*64*40)
#define SM_PS 0
#define ATTN_SMEM (3*64*40)

__global__ void __launch_bounds__(128, 10) attn_kernel(const float* __restrict__ lscale)
{
    const int win = blockIdx.x;
    const int h   = blockIdx.y;
    const int wm  = win & 63;
    const int tid = threadIdx.x;
    const int warp = tid >> 5, lane = tid & 31;

    __shared__ __half sbuf[ATTN_SMEM];
    __half* qs = sbuf + SM_QS;
    __half* ks = sbuf + SM_KS;
    __half* vs = sbuf + SM_VS;
    __half* ps = sbuf + SM_PS;

    {
        uint4 z = make_uint4(0,0,0,0);
        if (tid < 60) {
            int r = 49 + (tid >> 2), c = (tid & 3) * 8;
            *(uint4*)(vs + r*40 + c) = z;
        }
    }

    const __half* base = g_qkv + (size_t)(win*Nn49) * (3*Cc) + h*HD;
    for (int idx = tid; idx < Nn49*4; idx += 128) {
        int row = idx >> 2;
        int c   = (idx & 3) * 8;
        const __half* rb = base + (size_t)row * (3*Cc) + c;
        *(uint4*)(qs + row*40 + c) = *(const uint4*)(rb);
        *(uint4*)(ks + row*40 + c) = *(const uint4*)(rb + Cc);
        *(uint4*)(vs + row*40 + c) = *(const uint4*)(rb + 2*Cc);
    }
    __syncthreads();

    {
        float scale_h = __expf(fminf(lscale[h], 4.6051701859880914f));
        int r = -1; bool isq = false;
        if (tid < Nn49) { r = tid; isq = true; }
        else if (tid >= 64 && tid < 64 + Nn49) { r = tid - 64; }
        if (r >= 0) {
            __half* row = (isq ? qs : ks) + r*40;
            float ss = 0.f;
#pragma unroll
            for (int d = 0; d < HD; d += 2) {
                float2 f = __half22float2(*(__half2*)(row + d));
                ss += f.x*f.x + f.y*f.y;
            }
            float inv = 1.0f / fmaxf(sqrtf(ss), 1e-12f);
            if (isq) inv *= scale_h;
#pragma unroll
            for (int d = 0; d < HD; d += 2) {
                __half2* p = (__half2*)(row + d);
                float2 f = __half22float2(*p);
                *p = __floats2half2_rn(f.x*inv, f.y*inv);
            }
        }
    }
    __syncthreads();

    float s[7][4];
#pragma unroll
    for (int t = 0; t < 7; t++)
#pragma unroll
        for (int c = 0; c < 4; c++) s[t][c] = 0.f;

#pragma unroll
    for (int kk = 0; kk < 2; kk++) {
        uint32_t a[4];
        {
            int row = warp*16 + (lane & 15);
            int col = kk*16 + ((lane >> 4) << 3);
            LDSM4(a[0], a[1], a[2], a[3], smem_u32(qs + row*40 + col));
        }
        uint32_t b[8][2];
#pragma unroll
        for (int bi = 0; bi < 4; bi++) {
            int n   = bi*16 + ((lane >> 4) << 3) + (lane & 7);
            int col = kk*16 + ((lane >> 3) & 1) * 8;
            uint32_t t0, t1, t2, t3;
            LDSM4(t0, t1, t2, t3, smem_u32(ks + n*40 + col));
            b[bi*2+0][0] = t0; b[bi*2+0][1] = t1;
            b[bi*2+1][0] = t2; b[bi*2+1][1] = t3;
        }
#pragma unroll
        for (int t = 0; t < 7; t++)
            MMA16816(s[t], a, b[t]);
    }

    // qs/ks consumed -> ps may overwrite them
    __syncthreads();

    {
        const __half* bias = g_biash + ((size_t)wm*HEADS + h) * (Nn49*BSTRIDE);
        int r0 = lane >> 2;
        int i0 = warp*16 + r0;
        int i1 = i0 + 8;
        int jb = (lane & 3) * 2;

        // zero own band's ps cols 56..71
        {
            uint4 z = make_uint4(0,0,0,0);
            int r = warp*16 + (lane >> 1);
            int c = (lane & 1) * 8 + 56;
            *(uint4*)(ps + r*72 + c) = z;
        }

        const bool v0 = (i0 < Nn49);
        const bool v1 = (i1 < Nn49);
#pragma unroll
        for (int t = 0; t < 7; t++) {
            int j0 = t*8 + jb;
            float2 b0 = __half22float2(*(const __half2*)(bias + i0*BSTRIDE + j0));
            float2 b1 = __half22float2(*(const __half2*)(bias + i1*BSTRIDE + j0));
            s[t][0] = (v0 && j0     < Nn49) ? s[t][0] + b0.x : -1e30f;
            s[t][1] = (v0 && j0 + 1 < Nn49) ? s[t][1] + b0.y : -1e30f;
            s[t][2] = (v1 && j0     < Nn49) ? s[t][2] + b1.x : -1e30f;
            s[t][3] = (v1 && j0 + 1 < Nn49) ? s[t][3] + b1.y : -1e30f;
        }
        float mx0 = -1e30f, mx1 = -1e30f;
#pragma unroll
        for (int t = 0; t < 7; t++) {
            mx0 = fmaxf(mx0, fmaxf(s[t][0], s[t][1]));
            mx1 = fmaxf(mx1, fmaxf(s[t][2], s[t][3]));
        }
#pragma unroll
        for (int off = 1; off <= 2; off <<= 1) {
            mx0 = fmaxf(mx0, __shfl_xor_sync(0xffffffffu, mx0, off));
            mx1 = fmaxf(mx1, __shfl_xor_sync(0xffffffffu, mx1, off));
        }
        float sm0 = 0.f, sm1 = 0.f;
#pragma unroll
        for (int t = 0; t < 7; t++) {
            s[t][0] = __expf(s[t][0] - mx0); sm0 += s[t][0];
            s[t][1] = __expf(s[t][1] - mx0); sm0 += s[t][1];
            s[t][2] = __expf(s[t][2] - mx1); sm1 += s[t][2];
            s[t][3] = __expf(s[t][3] - mx1); sm1 += s[t][3];
        }
#pragma unroll
        for (int off = 1; off <= 2; off <<= 1) {
            sm0 += __shfl_xor_sync(0xffffffffu, sm0, off);
            sm1 += __shfl_xor_sync(0xffffffffu, sm1, off);
        }
        float inv0 = 1.0f / sm0, inv1 = 1.0f / sm1;
#pragma unroll
        for (int t = 0; t < 7; t++) {
            int j0 = t*8 + jb;
            *(__half2*)(ps + (i0 & 63)*72 + j0) = __floats2half2_rn(s[t][0]*inv0, s[t][1]*inv0);
            *(__half2*)(ps + (i1 & 63)*72 + j0) = __floats2half2_rn(s[t][2]*inv1, s[t][3]*inv1);
        }
    }
    __syncwarp();

    float o[4][4];
#pragma unroll
    for (int t = 0; t < 4; t++)
#pragma unroll
        for (int c = 0; c < 4; c++) o[t][c] = 0.f;

#pragma unroll
    for (int kk = 0; kk < 4; kk++) {
        uint32_t a[4];
        {
            int row = warp*16 + (lane & 15);
            int col = kk*16 + ((lane >> 4) << 3);
            LDSM4(a[0], a[1], a[2], a[3], smem_u32(ps + row*72 + col));
        }
        uint32_t b[4][2];
#pragma unroll
        for (int g = 0; g < 2; g++) {
            int tt   = lane >> 3;
            int krow = kk*16 + (tt & 1)*8 + (lane & 7);
            int ncol = g*16 + (tt >> 1)*8;
            uint32_t t0, t1, t2, t3;
            LDSM4T(t0, t1, t2, t3, smem_u32(vs + krow*40 + ncol));
            b[g*2+0][0] = t0; b[g*2+0][1] = t1;
            b[g*2+1][0] = t2; b[g*2+1][1] = t3;
        }
#pragma unroll
        for (int t = 0; t < 4; t++)
            MMA16816(o[t], a, b[t]);
    }

    {
        int r0 = lane >> 2;
        int i0 = warp*16 + r0;
        int i1 = i0 + 8;
        int d0 = (lane & 3) * 2;
#pragma unroll
        for (int t = 0; t < 4; t++) {
            int d = t*8 + d0;
            if (i0 < Nn49)
                *(__half2*)(g_o + (size_t)(win*Nn49 + i0)*Cc + h*HD + d) =
                    __floats2half2_rn(o[t][0], o[t][1]);
            if (i1 < Nn49)
                *(__half2*)(g_o + (size_t)(win*Nn49 + i1)*Cc + h*HD + d) =
                    __floats2half2_rn(o[t][2], o[t][3]);
        }
    }
}

// ---------------------------------------------------------------------------
// LN2 on g_x2 -> g_xm (fp16). WARP-PER-TOKEN, 8 tokens/block.
// ---------------------------------------------------------------------------
__global__ void __launch_bounds__(256) ln2_kernel(
    const float* __restrict__ g, const float* __restrict__ bb)
{
    const int warp = threadIdx.x >> 5, lane = threadIdx.x & 31;
    const int t = blockIdx.x * 8 + warp;
    const float4* row = (const float4*)(g_x2 + (size_t)t * Cc);

    float4 v[3];
#pragma unroll
    for (int i = 0; i < 3; i++) v[i] = row[lane + 32*i];

    float s = 0.f, s2 = 0.f;
#pragma unroll
    for (int i = 0; i < 3; i++) {
        s  += v[i].x + v[i].y + v[i].z + v[i].w;
        s2 += v[i].x*v[i].x + v[i].y*v[i].y + v[i].z*v[i].z + v[i].w*v[i].w;
    }
#pragma unroll
    for (int off = 16; off; off >>= 1) {
        s  += __shfl_xor_sync(0xffffffffu, s,  off);
        s2 += __shfl_xor_sync(0xffffffffu, s2, off);
    }
    float mu  = s * (1.f/384.f);
    float var = s2 * (1.f/384.f) - mu*mu;
    float inv = rsqrtf(var + 1e-5f);

    uint2* dst = (uint2*)(g_xm + (size_t)t * Cc);
    const float4* gg = (const float4*)g;
    const float4* bv4 = (const float4*)bb;
#pragma unroll
    for (int i = 0; i < 3; i++) {
        float4 gv = gg[lane + 32*i];
        float4 bv = bv4[lane + 32*i];
        __half2 h0 = __floats2half2_rn((v[i].x - mu)*inv*gv.x + bv.x,
                                       (v[i].y - mu)*inv*gv.y + bv.y);
        __half2 h1 = __floats2half2_rn((v[i].z - mu)*inv*gv.z + bv.z,
                                       (v[i].w - mu)*inv*gv.w + bv.w);
        uint2 u; u.x = *(uint32_t*)&h0; u.y = *(uint32_t*)&h1;
        dst[lane + 32*i] = u;
    }
}

// ---------------------------------------------------------------------------
extern "C" void kernel_launch(void* const* d_in, const int* in_sizes, int n_in,
                              void* d_out, int out_size)
{
    const float* x       = (const float*)d_in[0];
    const float* mask    = (const float*)d_in[1];
    const float* n1g     = (const float*)d_in[2];
    const float* n1b     = (const float*)d_in[3];
    const float* qkv_w   = (const float*)d_in[4];
    const float* qkv_b   = (const float*)d_in[5];
    const float* proj_w  = (const float*)d_in[6];
    const float* proj_b  = (const float*)d_in[7];
    const float* cpb_w1  = (const float*)d_in[8];
    const float* cpb_b1  = (const float*)d_in[9];
    const float* cpb_w2  = (const float*)d_in[10];
    const float* lscale  = (const float*)d_in[11];
    const float* n2g     = (const float*)d_in[12];
    const float* n2b     = (const float*)d_in[13];
    const float* mlp_w1  = (const float*)d_in[14];
    const float* mlp_b1  = (const float*)d_in[15];
    const float* mlp_w2  = (const float*)d_in[16];
    const float* mlp_b2  = (const float*)d_in[17];
    float* out = (float*)d_out;

    __half *a=nullptr, *qkv=nullptr, *o=nullptr, *xm=nullptr, *hidden=nullptr;
    __half *wqkv=nullptr, *wproj=nullptr, *wm1=nullptr, *wm2=nullptr;
    float *x2=nullptr;
    cudaGetSymbolAddress((void**)&a,       g_a);
    cudaGetSymbolAddress((void**)&qkv,     g_qkv);
    cudaGetSymbolAddress((void**)&o,       g_o);
    cudaGetSymbolAddress((void**)&x2,      g_x2);
    cudaGetSymbolAddress((void**)&xm,      g_xm);
    cudaGetSymbolAddress((void**)&hidden,  g_hidden);
    cudaGetSymbolAddress((void**)&wqkv,    g_wqkv);
    cudaGetSymbolAddress((void**)&wproj,   g_wproj);
    cudaGetSymbolAddress((void**)&wm1,     g_wm1);
    cudaGetSymbolAddress((void**)&wm2,     g_wm2);

    cudaFuncSetAttribute(hgemm<0>, cudaFuncAttributeMaxDynamicSharedMemorySize, GEMM_SMEM);
    cudaFuncSetAttribute(hgemm<1>, cudaFuncAttributeMaxDynamicSharedMemorySize, GEMM_SMEM);
    cudaFuncSetAttribute(hgemm<3>, cudaFuncAttributeMaxDynamicSharedMemorySize, GEMM_SMEM);
    cudaFuncSetAttribute(hgemm<4>, cudaFuncAttributeMaxDynamicSharedMemorySize, GEMM_SMEM);

    // 1: weights fp32->fp16 + CPB table (fused grid)
    f2h_cpb<<<F2H_BLOCKS + 169, 256>>>(qkv_w, proj_w, mlp_w1, mlp_w2,
                                       cpb_w1, cpb_b1, cpb_w2);
    // 2: LN1 (warp-per-token) + fp16 bias table (fused grid)
    ln1_bias<<<LN1_BLOCKS + NW*HEADS, 256>>>(x, n1g, n1b, mask);
    // 3: QKV GEMM -> fp16
    hgemm<0><<<dim3(9, TOK/128), 256, GEMM_SMEM>>>(a, wqkv, qkv_b, nullptr, qkv, TOK, 3*Cc, Cc);
    // 4: tensor-core window attention (profiled launch slot)
    attn_kernel<<<dim3(NWIN, HEADS), 128>>>(lscale);
    // 5: proj GEMM + x residual + spatial scatter -> g_x2 (fp32)
    hgemm<4><<<dim3(3, TOK/128), 256, GEMM_SMEM>>>(o, wproj, proj_b, x, x2, TOK, Cc, Cc);
    // 6: LN2 (warp-per-token) -> g_xm (fp16)
    ln2_kernel<<<TOK/8, 256>>>(n2g, n2b);
    // 7: MLP1 + GELU -> fp16
    hgemm<1><<<dim3(6, TOK/128), 256, GEMM_SMEM>>>(xm, wm1, mlp_b1, nullptr, hidden, TOK, HIDDEN, Cc);
    // 8: MLP2 + x2 residual -> d_out (fp32)
    hgemm<3><<<dim3(3, TOK/128), 256, GEMM_SMEM>>>(hidden, wm2, mlp_b2, x2, out, TOK, Cc, HIDDEN);
}

// round 17
// speedup vs baseline: 1.1681x; 1.0032x over previous
#include <cuda_runtime.h>
#include <cuda_fp16.h>
#include <cstdint>
#include <math.h>

// ---------------------------------------------------------------------------
// SwinV2 block: B=32, H=W=56, C=384, HEADS=12, WIN=7, SHIFT=3
// ---------------------------------------------------------------------------
#define Bb      32
#define Hh      56
#define Wwid    56
#define Cc      384
#define HEADS   12
#define HD      32
#define WIN     7
#define SHIFT   3
#define Nn49    49
#define NW      64
#define NWIN    (Bb*NW)       // 2048
#define TOK     (NWIN*Nn49)   // 100352
#define HIDDEN  768
#define BSTRIDE 56            // fp16 bias row stride (even -> half2 aligned)

// scratch (static device globals)
__device__ __half g_a      [(size_t)TOK * Cc];
__device__ __half g_qkv    [(size_t)TOK * 3 * Cc];
__device__ __half g_o      [(size_t)TOK * Cc];
__device__ float  g_x2     [(size_t)TOK * Cc];
__device__ __half g_xm     [(size_t)TOK * Cc];
__device__ __half g_hidden [(size_t)TOK * HIDDEN];
__device__ float  g_tab    [169 * HEADS];
__device__ __half g_biash  [(size_t)NW * HEADS * Nn49 * BSTRIDE + 4096];
// fp16 weights
__device__ __half g_wqkv [3*Cc*Cc];
__device__ __half g_wproj[Cc*Cc];
__device__ __half g_wm1  [HIDDEN*Cc];
__device__ __half g_wm2  [Cc*HIDDEN];

#define SZ_QKV (3*Cc*Cc)
#define SZ_PRJ (Cc*Cc)
#define SZ_M1  (HIDDEN*Cc)
#define SZ_M2  (Cc*HIDDEN)
#define SZ_ALL (SZ_QKV+SZ_PRJ+SZ_M1+SZ_M2)
#define F2H_BLOCKS ((SZ_ALL + 255)/256)          // 4608
#define LN1_BLOCKS (TOK/8)                        // 12544

// ---------------------------------------------------------------------------
__device__ __forceinline__ uint32_t smem_u32(const void* p) {
    return (uint32_t)__cvta_generic_to_shared(p);
}
__device__ __forceinline__ void cp_async16(uint32_t dst, const void* src) {
    asm volatile("cp.async.cg.shared.global [%0], [%1], 16;" :: "r"(dst), "l"(src));
}

#define LDSM4(r0,r1,r2,r3,addr) \
    asm volatile("ldmatrix.sync.aligned.m8n8.x4.shared.b16 {%0,%1,%2,%3}, [%4];" \
        : "=r"(r0),"=r"(r1),"=r"(r2),"=r"(r3) : "r"(addr))

#define LDSM4T(r0,r1,r2,r3,addr) \
    asm volatile("ldmatrix.sync.aligned.m8n8.x4.trans.shared.b16 {%0,%1,%2,%3}, [%4];" \
        : "=r"(r0),"=r"(r1),"=r"(r2),"=r"(r3) : "r"(addr))

#define MMA16816(c, a, b) \
    asm volatile("mma.sync.aligned.m16n8k16.row.col.f32.f16.f16.f32 " \
        "{%0,%1,%2,%3},{%4,%5,%6,%7},{%8,%9},{%0,%1,%2,%3};" \
        : "+f"(c[0]),"+f"(c[1]),"+f"(c[2]),"+f"(c[3]) \
        : "r"(a[0]),"r"(a[1]),"r"(a[2]),"r"(a[3]),"r"(b[0]),"r"(b[1]))

__device__ __forceinline__ float gelu_tanh(float v) {
    float u = 0.7978845608028654f * (v + 0.044715f * v * v * v);
    float th;
    asm("tanh.approx.f32 %0, %1;" : "=f"(th) : "f"(u));
    return 0.5f * v * (1.0f + th);
}

// ---------------------------------------------------------------------------
// kernel 1: weight conversion fp32->fp16 + CPB table (extra blocks)
// ---------------------------------------------------------------------------
__device__ __forceinline__ float relcoord(int d) {
    float v = 8.0f * (float)d / 6.0f;
    return copysignf(log2f(fabsf(v) + 1.0f) * (1.0f / 3.0f), v);
}

__global__ void __launch_bounds__(256) f2h_cpb(
    const float* __restrict__ w_qkv, const float* __restrict__ w_prj,
    const float* __restrict__ w_m1,  const float* __restrict__ w_m2,
    const float* __restrict__ cw1, const float* __restrict__ cb1,
    const float* __restrict__ cw2)
{
    if (blockIdx.x < F2H_BLOCKS) {
        int i = blockIdx.x * 256 + threadIdx.x;
        if (i < SZ_QKV) {
            g_wqkv[i] = __float2half(w_qkv[i]);
        } else if (i < SZ_QKV + SZ_PRJ) {
            g_wproj[i - SZ_QKV] = __float2half(w_prj[i - SZ_QKV]);
        } else if (i < SZ_QKV + SZ_PRJ + SZ_M1) {
            g_wm1[i - SZ_QKV - SZ_PRJ] = __float2half(w_m1[i - SZ_QKV - SZ_PRJ]);
        } else if (i < SZ_ALL) {
            g_wm2[i - SZ_QKV - SZ_PRJ - SZ_M1] = __float2half(w_m2[i - SZ_QKV - SZ_PRJ - SZ_M1]);
        }
    } else {
        int p  = blockIdx.x - F2H_BLOCKS;
        float r0 = relcoord(p / 13 - 6);
        float r1 = relcoord(p % 13 - 6);
        float acc[HEADS];
#pragma unroll
        for (int h = 0; h < HEADS; h++) acc[h] = 0.f;
        for (int j = threadIdx.x; j < 512; j += 256) {
            float hv = fmaxf(r0 * cw1[j*2] + r1 * cw1[j*2+1] + cb1[j], 0.f);
#pragma unroll
            for (int h = 0; h < HEADS; h++) acc[h] += hv * cw2[h*512 + j];
        }
        __shared__ float red[256];
        for (int h = 0; h < HEADS; h++) {
            red[threadIdx.x] = acc[h];
            __syncthreads();
            for (int s = 128; s > 0; s >>= 1) {
                if (threadIdx.x < s) red[threadIdx.x] += red[threadIdx.x + s];
                __syncthreads();
            }
            if (threadIdx.x == 0) g_tab[p*HEADS + h] = red[0];
            __syncthreads();
        }
    }
}

// ---------------------------------------------------------------------------
// kernel 2: LN1 (warp-per-token) + fp16 bias table (extra blocks)
// ---------------------------------------------------------------------------
__global__ void __launch_bounds__(256) ln1_bias(
    const float* __restrict__ x, const float* __restrict__ g,
    const float* __restrict__ bb, const float* __restrict__ mask)
{
    if (blockIdx.x < LN1_BLOCKS) {
        const int warp = threadIdx.x >> 5, lane = threadIdx.x & 31;
        const int t   = blockIdx.x * 8 + warp;
        const int win = t / Nn49, n = t % Nn49;
        const int b   = win >> 6, wi = win & 63;
        const int hh  = ((wi >> 3)*WIN + n/WIN + SHIFT) % Hh;
        const int ww  = ((wi & 7)*WIN + n%WIN + SHIFT) % Wwid;
        const float4* row = (const float4*)(x + (((size_t)b*Hh + hh)*Wwid + ww) * Cc);

        float4 v[3];
#pragma unroll
        for (int i = 0; i < 3; i++) v[i] = row[lane + 32*i];

        float s = 0.f, s2 = 0.f;
#pragma unroll
        for (int i = 0; i < 3; i++) {
            s  += v[i].x + v[i].y + v[i].z + v[i].w;
            s2 += v[i].x*v[i].x + v[i].y*v[i].y + v[i].z*v[i].z + v[i].w*v[i].w;
        }
#pragma unroll
        for (int off = 16; off; off >>= 1) {
            s  += __shfl_xor_sync(0xffffffffu, s,  off);
            s2 += __shfl_xor_sync(0xffffffffu, s2, off);
        }
        float mu  = s * (1.f/384.f);
        float var = s2 * (1.f/384.f) - mu*mu;
        float inv = rsqrtf(var + 1e-5f);

        uint2* dst = (uint2*)(g_a + (size_t)t * Cc);
        const float4* gg = (const float4*)g;
        const float4* bv4 = (const float4*)bb;
#pragma unroll
        for (int i = 0; i < 3; i++) {
            float4 gv = gg[lane + 32*i];
            float4 bv = bv4[lane + 32*i];
            __half2 h0 = __floats2half2_rn((v[i].x - mu)*inv*gv.x + bv.x,
                                           (v[i].y - mu)*inv*gv.y + bv.y);
            __half2 h1 = __floats2half2_rn((v[i].z - mu)*inv*gv.z + bv.z,
                                           (v[i].w - mu)*inv*gv.w + bv.w);
            uint2 u; u.x = *(uint32_t*)&h0; u.y = *(uint32_t*)&h1;
            dst[lane + 32*i] = u;
        }
    } else {
        int idx = blockIdx.x - LN1_BLOCKS;
        int wm = idx & 63, h = idx >> 6;
        __half* dst = g_biash + ((size_t)wm*HEADS + h) * (Nn49*BSTRIDE);
        const float* msk = mask + (size_t)wm * (Nn49*Nn49);
        for (int e = threadIdx.x; e < Nn49*Nn49; e += 256) {
            int i = e / Nn49, j = e % Nn49;
            int di = (i/WIN - j/WIN + 6)*13 + (i%WIN - j%WIN + 6);
            float t = g_tab[di*HEADS + h];
            dst[i*BSTRIDE + j] = __float2half(16.f / (1.f + __expf(-t)) + msk[e]);
        }
    }
}

// ---------------------------------------------------------------------------
// fp16 HMMA GEMM: BM=128, BN=128, BK=32, 3-stage cp.async, 1 barrier/iter,
// 8 warps (2x4), warp tile 64x32.
// EPI: 0 fp16+bias; 1 fp16+bias+GELU(tanh); 3 fp32+bias+resid;
//      4 fp32+bias + x-residual with window->spatial scatter
// ---------------------------------------------------------------------------
#define STAGES    3
#define TS_STAGE  (128*40)
#define GEMM_SMEM (STAGES*2*TS_STAGE*2)          // 61440 bytes
#define STG_STRIDE 136

template<int EPI>
__global__ void __launch_bounds__(256, 2) hgemm(
    const __half* __restrict__ A, const __half* __restrict__ Wt,
    const float* __restrict__ bias, const float* __restrict__ resid,
    void* __restrict__ Cptr, int M, int Nd, int K)
{
    extern __shared__ __half dyns[];
    __half* Asm = dyns;
    __half* Bsm = dyns + STAGES*TS_STAGE;

    const int tid  = threadIdx.x;
    const int bm   = blockIdx.y * 128;
    const int bn   = blockIdx.x * 128;
    const int wid  = tid >> 5, lane = tid & 31;
    const int wm   = (wid & 1) * 64;
    const int wn   = (wid >> 1) * 32;

    float acc[4][4][4];
#pragma unroll
    for (int mi = 0; mi < 4; mi++)
#pragma unroll
        for (int ni = 0; ni < 4; ni++)
#pragma unroll
            for (int q = 0; q < 4; q++) acc[mi][ni][q] = 0.f;

    const int lr = tid >> 2;
    const int lc = (tid & 3) * 8;
    const int nk = K >> 5;

    auto load_stage = [&](int slot, int kt) {
        __half* As = Asm + slot*TS_STAGE;
        __half* Bs = Bsm + slot*TS_STAGE;
        int k0 = kt << 5;
#pragma unroll
        for (int r = 0; r < 2; r++) {
            int row = lr + 64*r;
            cp_async16(smem_u32(&As[row*40 + lc]), A  + (size_t)(bm+row)*K + k0 + lc);
            cp_async16(smem_u32(&Bs[row*40 + lc]), Wt + (size_t)(bn+row)*K + k0 + lc);
        }
    };

#pragma unroll
    for (int s = 0; s < STAGES-1; s++) {
        if (s < nk) load_stage(s, s);
        asm volatile("cp.async.commit_group;");
    }

    for (int kt = 0; kt < nk; kt++) {
        asm volatile("cp.async.wait_group %0;" :: "n"(STAGES-2));
        __syncthreads();

        int pre = kt + STAGES - 1;
        if (pre < nk) load_stage(pre % STAGES, pre);
        asm volatile("cp.async.commit_group;");

        const __half* As = Asm + (kt % STAGES)*TS_STAGE;
        const __half* Bs = Bsm + (kt % STAGES)*TS_STAGE;

#pragma unroll
        for (int kk = 0; kk < 2; kk++) {
            uint32_t a[4][4], b[4][2];
#pragma unroll
            for (int mi = 0; mi < 4; mi++) {
                int row = wm + mi*16 + (lane & 15);
                int col = kk*16 + ((lane >> 4) << 3);
                LDSM4(a[mi][0], a[mi][1], a[mi][2], a[mi][3],
                      smem_u32(&As[row*40 + col]));
            }
#pragma unroll
            for (int bi = 0; bi < 2; bi++) {
                int n   = wn + bi*16 + ((lane >> 4) << 3) + (lane & 7);
                int col = kk*16 + ((lane >> 3) & 1) * 8;
                uint32_t t0, t1, t2, t3;
                LDSM4(t0, t1, t2, t3, smem_u32(&Bs[n*40 + col]));
                b[bi*2+0][0] = t0; b[bi*2+0][1] = t1;
                b[bi*2+1][0] = t2; b[bi*2+1][1] = t3;
            }
#pragma unroll
            for (int mi = 0; mi < 4; mi++)
#pragma unroll
                for (int ni = 0; ni < 4; ni++)
                    MMA16816(acc[mi][ni], a[mi], b[ni]);
        }
    }

    const int er = lane >> 2, ec = (lane & 3) * 2;

    if (EPI == 0 || EPI == 1) {
        __syncthreads();
        __half* stg = Asm;
#pragma unroll
        for (int mi = 0; mi < 4; mi++) {
#pragma unroll
            for (int ni = 0; ni < 4; ni++) {
                int col = wn + ni*8 + ec;
                float b0 = bias[bn + col], b1 = bias[bn + col + 1];
#pragma unroll
                for (int hh = 0; hh < 2; hh++) {
                    int row = wm + mi*16 + er + hh*8;
                    float v0 = acc[mi][ni][hh*2+0] + b0;
                    float v1 = acc[mi][ni][hh*2+1] + b1;
                    if (EPI == 1) {
                        v0 = gelu_tanh(v0);
                        v1 = gelu_tanh(v1);
                    }
                    *(__half2*)&stg[row*STG_STRIDE + col] = __floats2half2_rn(v0, v1);
                }
            }
        }
        __syncthreads();
#pragma unroll
        for (int i = 0; i < 8; i++) {
            int idx = tid + i*256;
            int row = idx >> 4;
            int u   = idx & 15;
            uint4 v = *(const uint4*)&stg[row*STG_STRIDE + u*8];
            *(uint4*)((__half*)Cptr + (size_t)(bm + row) * Nd + bn + u*8) = v;
        }
    } else if (EPI == 4) {
#pragma unroll
        for (int mi = 0; mi < 4; mi++) {
#pragma unroll
            for (int hh = 0; hh < 2; hh++) {
                int rp  = bm + wm + mi*16 + er + hh*8;
                int win = rp / Nn49, n = rp % Nn49;
                int b   = win >> 6,  wi = win & 63;
                int sh  = (wi >> 3)*WIN + n/WIN;
                int sw  = (wi & 7)*WIN + n%WIN;
                int hs  = sh + SHIFT; if (hs >= Hh)   hs -= Hh;
                int ws  = sw + SHIFT; if (ws >= Wwid) ws -= Wwid;
                size_t srow = ((size_t)b*Hh + hs)*Wwid + ws;
#pragma unroll
                for (int ni = 0; ni < 4; ni++) {
                    int col = bn + wn + ni*8 + ec;
                    const float* xr = resid + srow * Nd + col;
                    float2 f;
                    f.x = acc[mi][ni][hh*2+0] + bias[col] + xr[0];
                    f.y = acc[mi][ni][hh*2+1] + bias[col+1] + xr[1];
                    *(float2*)((float*)Cptr + srow * Nd + col) = f;
                }
            }
        }
    } else {
#pragma unroll
        for (int mi = 0; mi < 4; mi++) {
#pragma unroll
            for (int ni = 0; ni < 4; ni++) {
                int col = bn + wn + ni*8 + ec;
                float b0 = bias[col], b1 = bias[col+1];
#pragma unroll
                for (int hh = 0; hh < 2; hh++) {
                    size_t row = (size_t)(bm + wm + mi*16 + er + hh*8);
                    const float* rr = resid + row * Nd + col;
                    float2 f;
                    f.x = acc[mi][ni][hh*2+0] + b0 + rr[0];
                    f.y = acc[mi][ni][hh*2+1] + b1 + rr[1];
                    *(float2*)((float*)Cptr + row * Nd + col) = f;
                }
            }
        }
    }
}

// ---------------------------------------------------------------------------
// Tensor-core window attention, TWO HEADS PER BLOCK (256 thr, 8 warps).
// Warps 0-3 -> head 2p, warps 4-7 -> head 2p+1; per-head smem bank
// [qs|ks|vs] with ps aliasing qs+ks (dead after S-MMA). 30.7KB smem.
// ---------------------------------------------------------------------------
#define HEAD_SM (3*64*40)    // halves per head bank

__global__ void __launch_bounds__(256, 5) attn_kernel(const float* __restrict__ lscale)
{
    const int win = blockIdx.x;
    const int hp  = blockIdx.y;           // head pair 0..5
    const int wm  = win & 63;
    const int tid = threadIdx.x;
    const int warp = tid >> 5, lane = tid & 31;
    const int wg    = warp >> 2;          // head within pair (0/1)
    const int warpl = warp & 3;
    const int h     = hp*2 + wg;

    __shared__ __half sbuf[2*HEAD_SM];
    __half* qs = sbuf + wg*HEAD_SM;
    __half* ks = qs + 64*40;
    __half* vs = ks + 64*40;
    __half* ps = qs;                       // alias qs+ks after S-MMA

    // zero vs rows 49..63 cols 0..31, both heads: 2*60 uint4
    if (tid < 120) {
        uint4 z = make_uint4(0,0,0,0);
        int hh = tid / 60, i = tid % 60;
        int r = 49 + (i >> 2), c = (i & 3) * 8;
        *(uint4*)(sbuf + hh*HEAD_SM + 2*64*40 + r*40 + c) = z;
    }

    // load q,k,v: 128B-contiguous per row across the head pair
    {
        const __half* base = g_qkv + (size_t)(win*Nn49) * (3*Cc) + hp*2*HD;
        for (int idx = tid; idx < Nn49*8; idx += 256) {
            int row = idx >> 3;
            int c8  = idx & 7;          // 0..7: head hh, chunk c
            int hh  = c8 >> 2;
            int c   = (c8 & 3) * 8;
            const __half* rb = base + (size_t)row * (3*Cc) + hh*HD + c;
            __half* bank = sbuf + hh*HEAD_SM;
            *(uint4*)(bank + row*40 + c)            = *(const uint4*)(rb);
            *(uint4*)(bank + 64*40 + row*40 + c)    = *(const uint4*)(rb + Cc);
            *(uint4*)(bank + 2*64*40 + row*40 + c)  = *(const uint4*)(rb + 2*Cc);
        }
    }
    __syncthreads();

    // normalize q (fold scale) and k rows; threads 0-127 head0, 128-255 head1
    {
        int hh = tid >> 7;
        int t7 = tid & 127;
        float scale_h = __expf(fminf(lscale[hp*2 + hh], 4.6051701859880914f));
        int r = -1; bool isq = false;
        if (t7 < Nn49) { r = t7; isq = true; }
        else if (t7 >= 64 && t7 < 64 + Nn49) { r = t7 - 64; }
        if (r >= 0) {
            __half* row = sbuf + hh*HEAD_SM + (isq ? 0 : 64*40) + r*40;
            float ss = 0.f;
#pragma unroll
            for (int d = 0; d < HD; d += 2) {
                float2 f = __half22float2(*(__half2*)(row + d));
                ss += f.x*f.x + f.y*f.y;
            }
            float inv = 1.0f / fmaxf(sqrtf(ss), 1e-12f);
            if (isq) inv *= scale_h;
#pragma unroll
            for (int d = 0; d < HD; d += 2) {
                __half2* p = (__half2*)(row + d);
                float2 f = __half22float2(*p);
                *p = __floats2half2_rn(f.x*inv, f.y*inv);
            }
        }
    }
    __syncthreads();

    float s[7][4];
#pragma unroll
    for (int t = 0; t < 7; t++)
#pragma unroll
        for (int c = 0; c < 4; c++) s[t][c] = 0.f;

#pragma unroll
    for (int kk = 0; kk < 2; kk++) {
        uint32_t a[4];
        {
            int row = warpl*16 + (lane & 15);
            int col = kk*16 + ((lane >> 4) << 3);
            LDSM4(a[0], a[1], a[2], a[3], smem_u32(qs + row*40 + col));
        }
        uint32_t b[8][2];
#pragma unroll
        for (int bi = 0; bi < 4; bi++) {
            int n   = bi*16 + ((lane >> 4) << 3) + (lane & 7);
            int col = kk*16 + ((lane >> 3) & 1) * 8;
            uint32_t t0, t1, t2, t3;
            LDSM4(t0, t1, t2, t3, smem_u32(ks + n*40 + col));
            b[bi*2+0][0] = t0; b[bi*2+0][1] = t1;
            b[bi*2+1][0] = t2; b[bi*2+1][1] = t3;
        }
#pragma unroll
        for (int t = 0; t < 7; t++)
            MMA16816(s[t], a, b[t]);
    }

    // qs/ks consumed -> ps may overwrite them
    __syncthreads();

    {
        const __half* bias = g_biash + ((size_t)wm*HEADS + h) * (Nn49*BSTRIDE);
        int r0 = lane >> 2;
        int i0 = warpl*16 + r0;
        int i1 = i0 + 8;
        int jb = (lane & 3) * 2;

        // zero own band's ps cols 56..71
        {
            uint4 z = make_uint4(0,0,0,0);
            int r = warpl*16 + (lane >> 1);
            int c = (lane & 1) * 8 + 56;
            *(uint4*)(ps + r*72 + c) = z;
        }

        const bool v0 = (i0 < Nn49);
        const bool v1 = (i1 < Nn49);
#pragma unroll
        for (int t = 0; t < 7; t++) {
            int j0 = t*8 + jb;
            float2 b0 = __half22float2(*(const __half2*)(bias + i0*BSTRIDE + j0));
            float2 b1 = __half22float2(*(const __half2*)(bias + i1*BSTRIDE + j0));
            s[t][0] = (v0 && j0     < Nn49) ? s[t][0] + b0.x : -1e30f;
            s[t][1] = (v0 && j0 + 1 < Nn49) ? s[t][1] + b0.y : -1e30f;
            s[t][2] = (v1 && j0     < Nn49) ? s[t][2] + b1.x : -1e30f;
            s[t][3] = (v1 && j0 + 1 < Nn49) ? s[t][3] + b1.y : -1e30f;
        }
        float mx0 = -1e30f, mx1 = -1e30f;
#pragma unroll
        for (int t = 0; t < 7; t++) {
            mx0 = fmaxf(mx0, fmaxf(s[t][0], s[t][1]));
            mx1 = fmaxf(mx1, fmaxf(s[t][2], s[t][3]));
        }
#pragma unroll
        for (int off = 1; off <= 2; off <<= 1) {
            mx0 = fmaxf(mx0, __shfl_xor_sync(0xffffffffu, mx0, off));
            mx1 = fmaxf(mx1, __shfl_xor_sync(0xffffffffu, mx1, off));
        }
        float sm0 = 0.f, sm1 = 0.f;
#pragma unroll
        for (int t = 0; t < 7; t++) {
            s[t][0] = __expf(s[t][0] - mx0); sm0 += s[t][0];
            s[t][1] = __expf(s[t][1] - mx0); sm0 += s[t][1];
            s[t][2] = __expf(s[t][2] - mx1); sm1 += s[t][2];
            s[t][3] = __expf(s[t][3] - mx1); sm1 += s[t][3];
        }
#pragma unroll
        for (int off = 1; off <= 2; off <<= 1) {
            sm0 += __shfl_xor_sync(0xffffffffu, sm0, off);
            sm1 += __shfl_xor_sync(0xffffffffu, sm1, off);
        }
        float inv0 = 1.0f / sm0, inv1 = 1.0f / sm1;
#pragma unroll
        for (int t = 0; t < 7; t++) {
            int j0 = t*8 + jb;
            *(__half2*)(ps + (i0 & 63)*72 + j0) = __floats2half2_rn(s[t][0]*inv0, s[t][1]*inv0);
            *(__half2*)(ps + (i1 & 63)*72 + j0) = __floats2half2_rn(s[t][2]*inv1, s[t][3]*inv1);
        }
    }
    __syncwarp();   // ps rows are warp-private within the head bank

    float o[4][4];
#pragma unroll
    for (int t = 0; t < 4; t++)
#pragma unroll
        for (int c = 0; c < 4; c++) o[t][c] = 0.f;

#pragma unroll
    for (int kk = 0; kk < 4; kk++) {
        uint32_t a[4];
        {
            int row = warpl*16 + (lane & 15);
            int col = kk*16 + ((lane >> 4) << 3);
            LDSM4(a[0], a[1], a[2], a[3], smem_u32(ps + row*72 + col));
        }
        uint32_t b[4][2];
#pragma unroll
        for (int g = 0; g < 2; g++) {
            int tt   = lane >> 3;
            int krow = kk*16 + (tt & 1)*8 + (lane & 7);
            int ncol = g*16 + (tt >> 1)*8;
            uint32_t t0, t1, t2, t3;
            LDSM4T(t0, t1, t2, t3, smem_u32(vs + krow*40 + ncol));
            b[g*2+0][0] = t0; b[g*2+0][1] = t1;
            b[g*2+1][0] = t2; b[g*2+1][1] = t3;
        }
#pragma unroll
        for (int t = 0; t < 4; t++)
            MMA16816(o[t], a, b[t]);
    }

    {
        int r0 = lane >> 2;
        int i0 = warpl*16 + r0;
        int i1 = i0 + 8;
        int d0 = (lane & 3) * 2;
#pragma unroll
        for (int t = 0; t < 4; t++) {
            int d = t*8 + d0;
            if (i0 < Nn49)
                *(__half2*)(g_o + (size_t)(win*Nn49 + i0)*Cc + h*HD + d) =
                    __floats2half2_rn(o[t][0], o[t][1]);
            if (i1 < Nn49)
                *(__half2*)(g_o + (size_t)(win*Nn49 + i1)*Cc + h*HD + d) =
                    __floats2half2_rn(o[t][2], o[t][3]);
        }
    }
}

// ---------------------------------------------------------------------------
// LN2 on g_x2 -> g_xm (fp16). WARP-PER-TOKEN, 8 tokens/block.
// ---------------------------------------------------------------------------
__global__ void __launch_bounds__(256) ln2_kernel(
    const float* __restrict__ g, const float* __restrict__ bb)
{
    const int warp = threadIdx.x >> 5, lane = threadIdx.x & 31;
    const int t = blockIdx.x * 8 + warp;
    const float4* row = (const float4*)(g_x2 + (size_t)t * Cc);

    float4 v[3];
#pragma unroll
    for (int i = 0; i < 3; i++) v[i] = row[lane + 32*i];

    float s = 0.f, s2 = 0.f;
#pragma unroll
    for (int i = 0; i < 3; i++) {
        s  += v[i].x + v[i].y + v[i].z + v[i].w;
        s2 += v[i].x*v[i].x + v[i].y*v[i].y + v[i].z*v[i].z + v[i].w*v[i].w;
    }
#pragma unroll
    for (int off = 16; off; off >>= 1) {
        s  += __shfl_xor_sync(0xffffffffu, s,  off);
        s2 += __shfl_xor_sync(0xffffffffu, s2, off);
    }
    float mu  = s * (1.f/384.f);
    float var = s2 * (1.f/384.f) - mu*mu;
    float inv = rsqrtf(var + 1e-5f);

    uint2* dst = (uint2*)(g_xm + (size_t)t * Cc);
    const float4* gg = (const float4*)g;
    const float4* bv4 = (const float4*)bb;
#pragma unroll
    for (int i = 0; i < 3; i++) {
        float4 gv = gg[lane + 32*i];
        float4 bv = bv4[lane + 32*i];
        __half2 h0 = __floats2half2_rn((v[i].x - mu)*inv*gv.x + bv.x,
                                       (v[i].y - mu)*inv*gv.y + bv.y);
        __half2 h1 = __floats2half2_rn((v[i].z - mu)*inv*gv.z + bv.z,
                                       (v[i].w - mu)*inv*gv.w + bv.w);
        uint2 u; u.x = *(uint32_t*)&h0; u.y = *(uint32_t*)&h1;
        dst[lane + 32*i] = u;
    }
}

// ---------------------------------------------------------------------------
extern "C" void kernel_launch(void* const* d_in, const int* in_sizes, int n_in,
                              void* d_out, int out_size)
{
    const float* x       = (const float*)d_in[0];
    const float* mask    = (const float*)d_in[1];
    const float* n1g     = (const float*)d_in[2];
    const float* n1b     = (const float*)d_in[3];
    const float* qkv_w   = (const float*)d_in[4];
    const float* qkv_b   = (const float*)d_in[5];
    const float* proj_w  = (const float*)d_in[6];
    const float* proj_b  = (const float*)d_in[7];
    const float* cpb_w1  = (const float*)d_in[8];
    const float* cpb_b1  = (const float*)d_in[9];
    const float* cpb_w2  = (const float*)d_in[10];
    const float* lscale  = (const float*)d_in[11];
    const float* n2g     = (const float*)d_in[12];
    const float* n2b     = (const float*)d_in[13];
    const float* mlp_w1  = (const float*)d_in[14];
    const float* mlp_b1  = (const float*)d_in[15];
    const float* mlp_w2  = (const float*)d_in[16];
    const float* mlp_b2  = (const float*)d_in[17];
    float* out = (float*)d_out;

    __half *a=nullptr, *qkv=nullptr, *o=nullptr, *xm=nullptr, *hidden=nullptr;
    __half *wqkv=nullptr, *wproj=nullptr, *wm1=nullptr, *wm2=nullptr;
    float *x2=nullptr;
    cudaGetSymbolAddress((void**)&a,       g_a);
    cudaGetSymbolAddress((void**)&qkv,     g_qkv);
    cudaGetSymbolAddress((void**)&o,       g_o);
    cudaGetSymbolAddress((void**)&x2,      g_x2);
    cudaGetSymbolAddress((void**)&xm,      g_xm);
    cudaGetSymbolAddress((void**)&hidden,  g_hidden);
    cudaGetSymbolAddress((void**)&wqkv,    g_wqkv);
    cudaGetSymbolAddress((void**)&wproj,   g_wproj);
    cudaGetSymbolAddress((void**)&wm1,     g_wm1);
    cudaGetSymbolAddress((void**)&wm2,     g_wm2);

    cudaFuncSetAttribute(hgemm<0>, cudaFuncAttributeMaxDynamicSharedMemorySize, GEMM_SMEM);
    cudaFuncSetAttribute(hgemm<1>, cudaFuncAttributeMaxDynamicSharedMemorySize, GEMM_SMEM);
    cudaFuncSetAttribute(hgemm<3>, cudaFuncAttributeMaxDynamicSharedMemorySize, GEMM_SMEM);
    cudaFuncSetAttribute(hgemm<4>, cudaFuncAttributeMaxDynamicSharedMemorySize, GEMM_SMEM);

    // 1: weights fp32->fp16 + CPB table (fused grid)
    f2h_cpb<<<F2H_BLOCKS + 169, 256>>>(qkv_w, proj_w, mlp_w1, mlp_w2,
                                       cpb_w1, cpb_b1, cpb_w2);
    // 2: LN1 (warp-per-token) + fp16 bias table (fused grid)
    ln1_bias<<<LN1_BLOCKS + NW*HEADS, 256>>>(x, n1g, n1b, mask);
    // 3: QKV GEMM -> fp16
    hgemm<0><<<dim3(9, TOK/128), 256, GEMM_SMEM>>>(a, wqkv, qkv_b, nullptr, qkv, TOK, 3*Cc, Cc);
    // 4: tensor-core window attention, 2 heads/block (profiled launch slot)
    attn_kernel<<<dim3(NWIN, HEADS/2), 256>>>(lscale);
    // 5: proj GEMM + x residual + spatial scatter -> g_x2 (fp32)
    hgemm<4><<<dim3(3, TOK/128), 256, GEMM_SMEM>>>(o, wproj, proj_b, x, x2, TOK, Cc, Cc);
    // 6: LN2 (warp-per-token) -> g_xm (fp16)
    ln2_kernel<<<TOK/8, 256>>>(n2g, n2b);
    // 7: MLP1 + GELU -> fp16
    hgemm<1><<<dim3(6, TOK/128), 256, GEMM_SMEM>>>(xm, wm1, mlp_b1, nullptr, hidden, TOK, HIDDEN, Cc);
    // 8: MLP2 + x2 residual -> d_out (fp32)
    hgemm<3><<<dim3(3, TOK/128), 256, GEMM_SMEM>>>(hidden, wm2, mlp_b2, x2, out, TOK, Cc, HIDDEN);
}